// round 1
// baseline (speedup 1.0000x reference)
#include <cuda_runtime.h>
#include <cuda_bf16.h>
#include <math.h>

#define S_LEN 4096
#define HID 2048
#define NH 8
#define KVH 4
#define HD 256
#define QR 6
#define KR 2
#define VR 2
#define WINDOW 1024
#define SOFTCAP 50.0f
#define SCALING 0.0625f   // 256^-0.5
#define EPS 1e-6f

// ---------------- scratch (device globals; allocation-free) ----------------
__device__ float g_Aq[S_LEN * NH * QR];        // 4096 x 48
__device__ float g_Ak[S_LEN * KVH * KR];       // 4096 x 8
__device__ float g_Av[S_LEN * KVH * VR];       // 4096 x 8
__device__ float g_Bq[S_LEN * QR * HD];        // 4096 x 1536
__device__ float g_Bk[S_LEN * KR * HD];        // 4096 x 512
__device__ float g_Bv[S_LEN * VR * HD];        // 4096 x 512
__device__ float g_q[S_LEN * NH * HD];         // 4096 x 2048 (scaled, rmsnormed)
__device__ float g_k[S_LEN * KVH * HD];        // 4096 x 1024
__device__ float g_v[S_LEN * KVH * HD];        // 4096 x 1024
__device__ float g_attn[S_LEN * NH * HD];      // 4096 x 2048

// ---------------- SGEMM: C[m,n] = sum_k A[m,k] * B[n,k] --------------------
// A: MxK row-major, B: NxK row-major (i.e. C = A @ B^T). 128x128 tile, BK=8.
#define BM 128
#define BN 128
#define BK 8

__global__ __launch_bounds__(256) void sgemm_nt(
    const float* __restrict__ A, const float* __restrict__ B,
    float* __restrict__ C, int M, int N, int K)
{
    __shared__ float As[BK][BM + 4];
    __shared__ float Bs[BK][BN + 4];

    int bx = blockIdx.x;             // n-tile
    int by = blockIdx.y;             // m-tile
    int tid = threadIdx.x;

    int lr = tid >> 1;               // 0..127 (row within tile for loads)
    int lc = (tid & 1) * 4;          // 0 or 4 (k offset)
    int tx = tid & 15;               // 0..15  (n micro)
    int ty = tid >> 4;               // 0..15  (m micro)

    float acc[8][8];
    #pragma unroll
    for (int i = 0; i < 8; i++)
        #pragma unroll
        for (int j = 0; j < 8; j++) acc[i][j] = 0.f;

    const float* Ap = A + (size_t)(by * BM + lr) * K + lc;
    int brow = bx * BN + lr;
    bool bvalid = brow < N;
    const float* Bp = B + (size_t)(bvalid ? brow : 0) * K + lc;

    for (int k0 = 0; k0 < K; k0 += BK) {
        float4 av = *(const float4*)(Ap + k0);
        float4 bv = make_float4(0.f, 0.f, 0.f, 0.f);
        if (bvalid) bv = *(const float4*)(Bp + k0);
        As[lc + 0][lr] = av.x; As[lc + 1][lr] = av.y;
        As[lc + 2][lr] = av.z; As[lc + 3][lr] = av.w;
        Bs[lc + 0][lr] = bv.x; Bs[lc + 1][lr] = bv.y;
        Bs[lc + 2][lr] = bv.z; Bs[lc + 3][lr] = bv.w;
        __syncthreads();

        #pragma unroll
        for (int kk = 0; kk < BK; kk++) {
            float a[8], b[8];
            *(float4*)&a[0] = *(const float4*)&As[kk][ty * 8];
            *(float4*)&a[4] = *(const float4*)&As[kk][ty * 8 + 4];
            *(float4*)&b[0] = *(const float4*)&Bs[kk][tx * 8];
            *(float4*)&b[4] = *(const float4*)&Bs[kk][tx * 8 + 4];
            #pragma unroll
            for (int i = 0; i < 8; i++)
                #pragma unroll
                for (int j = 0; j < 8; j++)
                    acc[i][j] += a[i] * b[j];
        }
        __syncthreads();
    }

    #pragma unroll
    for (int i = 0; i < 8; i++) {
        int m = by * BM + ty * 8 + i;
        float* crow = C + (size_t)m * N;
        #pragma unroll
        for (int j = 0; j < 8; j++) {
            int n = bx * BN + tx * 8 + j;
            if (n < N) crow[n] = acc[i][j];
        }
    }
}

// ---------------- fused RoPE + tensor-product + RMSNorm --------------------
// One block per token s, 256 threads (thread = dim d).
__global__ __launch_bounds__(256) void qkv_kernel(
    const float* __restrict__ Aq, const float* __restrict__ Ak,
    const float* __restrict__ Av, const float* __restrict__ Bq,
    const float* __restrict__ Bk, const float* __restrict__ Bv,
    const float* __restrict__ fcos, const float* __restrict__ fsin,
    const float* __restrict__ qnw, const float* __restrict__ knw,
    const int* __restrict__ idx,
    float* __restrict__ qo, float* __restrict__ ko, float* __restrict__ vo)
{
    int s = blockIdx.x;
    int tid = threadIdx.x;
    int d = tid;
    int warp = tid >> 5, lane = tid & 31;

    __shared__ float sA[64];            // 48 Aq | 8 Ak | 8 Av
    __shared__ float red[8][8];         // [warp][h]
    __shared__ float srstd[8];
    __shared__ float skrstd[4];

    if (tid < 48)       sA[tid] = Aq[s * 48 + tid];
    else if (tid < 56)  sA[tid] = Ak[s * 8 + (tid - 48)];
    else if (tid < 64)  sA[tid] = Av[s * 8 + (tid - 56)];
    __syncthreads();

    float c  = fcos[s * (HD / 2) + (d >> 1)];
    float sn = fsin[s * (HD / 2) + (d >> 1)];
    float seff = (d & 1) ? sn : -sn;

    // ---- q ----
    float bq[QR];
    #pragma unroll
    for (int r = 0; r < QR; r++) {
        float x  = Bq[(size_t)s * (QR * HD) + r * HD + d];
        float xn = Bq[(size_t)s * (QR * HD) + r * HD + (d ^ 1)];
        bq[r] = x * c + xn * seff;
    }
    float qraw[NH];
    #pragma unroll
    for (int h = 0; h < NH; h++) {
        float acc = 0.f;
        #pragma unroll
        for (int r = 0; r < QR; r++) acc += sA[h * QR + r] * bq[r];
        qraw[h] = acc * (1.f / QR);
    }
    #pragma unroll
    for (int h = 0; h < NH; h++) {
        float ss = qraw[h] * qraw[h];
        #pragma unroll
        for (int o = 16; o > 0; o >>= 1) ss += __shfl_xor_sync(0xffffffffu, ss, o);
        if (lane == 0) red[warp][h] = ss;
    }
    __syncthreads();
    if (tid < NH) {
        float t = 0.f;
        #pragma unroll
        for (int w = 0; w < 8; w++) t += red[w][tid];
        srstd[tid] = rsqrtf(t * (1.f / HD) + EPS);
    }
    __syncthreads();
    float qw = (1.f + qnw[d]) * SCALING;
    #pragma unroll
    for (int h = 0; h < NH; h++)
        qo[((size_t)s * NH + h) * HD + d] = qraw[h] * srstd[h] * qw;

    // ---- k ----
    float bk[KR];
    #pragma unroll
    for (int r = 0; r < KR; r++) {
        float x  = Bk[(size_t)s * (KR * HD) + r * HD + d];
        float xn = Bk[(size_t)s * (KR * HD) + r * HD + (d ^ 1)];
        bk[r] = x * c + xn * seff;
    }
    float kraw[KVH];
    #pragma unroll
    for (int kh = 0; kh < KVH; kh++)
        kraw[kh] = (sA[48 + kh * KR + 0] * bk[0] + sA[48 + kh * KR + 1] * bk[1]) * 0.5f;

    __syncthreads();   // red reuse safe
    #pragma unroll
    for (int kh = 0; kh < KVH; kh++) {
        float ss = kraw[kh] * kraw[kh];
        #pragma unroll
        for (int o = 16; o > 0; o >>= 1) ss += __shfl_xor_sync(0xffffffffu, ss, o);
        if (lane == 0) red[warp][kh] = ss;
    }
    __syncthreads();
    if (tid < KVH) {
        float t = 0.f;
        #pragma unroll
        for (int w = 0; w < 8; w++) t += red[w][tid];
        skrstd[tid] = rsqrtf(t * (1.f / HD) + EPS);
    }
    __syncthreads();

    int tpos = idx[s];
    float kw = 1.f + knw[d];
    #pragma unroll
    for (int kh = 0; kh < KVH; kh++)
        ko[((size_t)tpos * KVH + kh) * HD + d] = kraw[kh] * skrstd[kh] * kw;

    // ---- v (no rope, no norm) ----
    float bv0 = Bv[(size_t)s * (VR * HD) + 0 * HD + d];
    float bv1 = Bv[(size_t)s * (VR * HD) + 1 * HD + d];
    #pragma unroll
    for (int kh = 0; kh < KVH; kh++)
        vo[((size_t)tpos * KVH + kh) * HD + d] =
            (sA[56 + kh * VR + 0] * bv0 + sA[56 + kh * VR + 1] * bv1) * 0.5f;
}

// ---------------- sliding-window softcapped attention ----------------------
// Block = (32-query tile, head). 256 threads: 32 groups of 8.
// Group owns one query; each thread owns dims d = g + 8*j, j<32.
#define BQ 32
#define BT 16

__global__ __launch_bounds__(256) void attn_kernel(
    const float* __restrict__ q, const float* __restrict__ k,
    const float* __restrict__ v, const int* __restrict__ idx,
    float* __restrict__ out)
{
    __shared__ float sk[BT][HD];
    __shared__ float sv[BT][HD];
    __shared__ int spos[BQ];
    __shared__ int srange[2];

    int s0 = blockIdx.x * BQ;
    int h = blockIdx.y;
    int kvh = h >> 1;            // rep = H/KVH = 2
    int tid = threadIdx.x;
    int qi = tid >> 3;
    int g = tid & 7;

    if (tid < BQ) spos[tid] = idx[s0 + tid];
    __syncthreads();
    if (tid == 0) {
        int mn = spos[0], mx = spos[0];
        for (int i = 1; i < BQ; i++) { mn = min(mn, spos[i]); mx = max(mx, spos[i]); }
        srange[0] = max(0, mn - (WINDOW - 1));
        srange[1] = mx;
    }
    __syncthreads();
    int kmin = srange[0], kmax = srange[1];
    int qpos = spos[qi];

    float qreg[32];
    const float* qp = q + ((size_t)(s0 + qi) * NH + h) * HD + g;
    #pragma unroll
    for (int j = 0; j < 32; j++) qreg[j] = qp[8 * j];

    float acc[32];
    #pragma unroll
    for (int j = 0; j < 32; j++) acc[j] = 0.f;
    float den = 0.f;

    for (int t0 = kmin; t0 <= kmax; t0 += BT) {
        // cooperative chunk load: BT x 256 floats for k and v (float4)
        for (int l = tid; l < BT * HD / 4; l += 256) {
            int row = l >> 6;
            int c4 = l & 63;
            int t = t0 + row;
            float4 kq = make_float4(0.f, 0.f, 0.f, 0.f);
            float4 vq = make_float4(0.f, 0.f, 0.f, 0.f);
            if (t < S_LEN) {
                kq = *(const float4*)(k + ((size_t)t * KVH + kvh) * HD + c4 * 4);
                vq = *(const float4*)(v + ((size_t)t * KVH + kvh) * HD + c4 * 4);
            }
            *(float4*)&sk[row][c4 * 4] = kq;
            *(float4*)&sv[row][c4 * 4] = vq;
        }
        __syncthreads();

        float ps[BT];
        #pragma unroll
        for (int t = 0; t < BT; t++) ps[t] = 0.f;
        #pragma unroll
        for (int j = 0; j < 32; j++) {
            float qv = qreg[j];
            #pragma unroll
            for (int t = 0; t < BT; t++)
                ps[t] += qv * sk[t][g + 8 * j];
        }
        // reduce partial dots across the 8-thread group
        #pragma unroll
        for (int t = 0; t < BT; t++) {
            float x = ps[t];
            x += __shfl_xor_sync(0xffffffffu, x, 1, 8);
            x += __shfl_xor_sync(0xffffffffu, x, 2, 8);
            x += __shfl_xor_sync(0xffffffffu, x, 4, 8);
            ps[t] = x;
        }
        // softcap + mask + accumulate (no max subtraction needed: |score|<=50)
        #pragma unroll
        for (int t = 0; t < BT; t++) {
            int tt = t0 + t;
            int diff = qpos - tt;
            float p = 0.f;
            if (diff >= 0 && diff < WINDOW) {
                float sc = tanhf(ps[t] * (1.f / SOFTCAP)) * SOFTCAP;
                p = __expf(sc);
            }
            if (p != 0.f) {
                den += p;
                #pragma unroll
                for (int j = 0; j < 32; j++)
                    acc[j] += p * sv[t][g + 8 * j];
            }
        }
        __syncthreads();
    }

    float inv = 1.f / den;
    float* op = out + (size_t)(s0 + qi) * (NH * HD) + h * HD + g;
    #pragma unroll
    for (int j = 0; j < 32; j++) op[8 * j] = acc[j] * inv;
}

// ---------------- launch ----------------------------------------------------
extern "C" void kernel_launch(void* const* d_in, const int* in_sizes, int n_in,
                              void* d_out, int out_size)
{
    const float* x   = (const float*)d_in[0];
    const float* fc  = (const float*)d_in[1];
    const float* fs  = (const float*)d_in[2];
    const float* WAq = (const float*)d_in[3];
    const float* WAk = (const float*)d_in[4];
    const float* WAv = (const float*)d_in[5];
    const float* WBq = (const float*)d_in[6];
    const float* WBk = (const float*)d_in[7];
    const float* WBv = (const float*)d_in[8];
    const float* Wo  = (const float*)d_in[9];
    const float* qnw = (const float*)d_in[10];
    const float* knw = (const float*)d_in[11];
    const int*   idx = (const int*)d_in[16];
    float* out = (float*)d_out;

    float *gAq, *gAk, *gAv, *gBq, *gBk, *gBv, *gq, *gk, *gv, *gattn;
    cudaGetSymbolAddress((void**)&gAq, g_Aq);
    cudaGetSymbolAddress((void**)&gAk, g_Ak);
    cudaGetSymbolAddress((void**)&gAv, g_Av);
    cudaGetSymbolAddress((void**)&gBq, g_Bq);
    cudaGetSymbolAddress((void**)&gBk, g_Bk);
    cudaGetSymbolAddress((void**)&gBv, g_Bv);
    cudaGetSymbolAddress((void**)&gq,  g_q);
    cudaGetSymbolAddress((void**)&gk,  g_k);
    cudaGetSymbolAddress((void**)&gv,  g_v);
    cudaGetSymbolAddress((void**)&gattn, g_attn);

    // caches start at zero (matches zero cache inputs); scatter then overwrites
    cudaMemsetAsync(gk, 0, (size_t)S_LEN * KVH * HD * sizeof(float));
    cudaMemsetAsync(gv, 0, (size_t)S_LEN * KVH * HD * sizeof(float));

    dim3 blk(256);
    // projections: C = x @ W^T
    sgemm_nt<<<dim3(1, 32), blk>>>(x, WAq, gAq, S_LEN, NH * QR, HID);
    sgemm_nt<<<dim3(1, 32), blk>>>(x, WAk, gAk, S_LEN, KVH * KR, HID);
    sgemm_nt<<<dim3(1, 32), blk>>>(x, WAv, gAv, S_LEN, KVH * VR, HID);
    sgemm_nt<<<dim3(12, 32), blk>>>(x, WBq, gBq, S_LEN, QR * HD, HID);
    sgemm_nt<<<dim3(4, 32), blk>>>(x, WBk, gBk, S_LEN, KR * HD, HID);
    sgemm_nt<<<dim3(4, 32), blk>>>(x, WBv, gBv, S_LEN, VR * HD, HID);

    qkv_kernel<<<S_LEN, 256>>>(gAq, gAk, gAv, gBq, gBk, gBv,
                               fc, fs, qnw, knw, idx, gq, gk, gv);

    attn_kernel<<<dim3(S_LEN / BQ, NH), 256>>>(gq, gk, gv, idx, gattn);

    // output projection: out = attn @ Wo^T
    sgemm_nt<<<dim3(16, 32), blk>>>(gattn, Wo, out, S_LEN, HID, HID);
}

// round 3
// speedup vs baseline: 1.7729x; 1.7729x over previous
#include <cuda_runtime.h>
#include <cuda_bf16.h>
#include <math.h>
#include <stdint.h>

#define S_LEN 4096
#define HID 2048
#define NH 8
#define KVH 4
#define HD 256
#define QR 6
#define KR 2
#define VR 2
#define WINDOW 1024
#define SOFTCAP 50.0f
#define SCALING 0.0625f   // 256^-0.5
#define EPS 1e-6f

// ---------------- scratch (device globals; allocation-free) ----------------
__device__ float g_Acat[S_LEN * 128];
__device__ float g_Bq[S_LEN * QR * HD];
__device__ float g_Bk[S_LEN * KR * HD];
__device__ float g_Bv[S_LEN * VR * HD];
__device__ float g_q[S_LEN * NH * HD];
__device__ float g_k[S_LEN * KVH * HD];
__device__ float g_v[S_LEN * KVH * HD];
__device__ float g_attn[S_LEN * NH * HD];

__device__ __nv_bfloat16 g_xhi[S_LEN * HID];
__device__ __nv_bfloat16 g_xlo[S_LEN * HID];
__device__ __nv_bfloat16 g_wbq_hi[QR * HD * HID];
__device__ __nv_bfloat16 g_wbq_lo[QR * HD * HID];
__device__ __nv_bfloat16 g_wbk_hi[KR * HD * HID];
__device__ __nv_bfloat16 g_wbk_lo[KR * HD * HID];
__device__ __nv_bfloat16 g_wbv_hi[VR * HD * HID];
__device__ __nv_bfloat16 g_wbv_lo[VR * HD * HID];
__device__ __nv_bfloat16 g_wo_hi[HID * HID];
__device__ __nv_bfloat16 g_wo_lo[HID * HID];
__device__ __nv_bfloat16 g_wa_hi[128 * HID];
__device__ __nv_bfloat16 g_wa_lo[128 * HID];
__device__ __nv_bfloat16 g_attnhi[S_LEN * HID];
__device__ __nv_bfloat16 g_attnlo[S_LEN * HID];

// ---------------- helpers ----------------
__device__ __forceinline__ uint32_t smem_u32(const void* p) {
    uint32_t a;
    asm("{ .reg .u64 t; cvta.to.shared.u64 t, %1; cvt.u32.u64 %0, t; }" : "=r"(a) : "l"(p));
    return a;
}

#define LDMX4(r0, r1, r2, r3, addr)                                              \
    asm volatile("ldmatrix.sync.aligned.m8n8.x4.shared.b16 {%0,%1,%2,%3}, [%4];" \
                 : "=r"(r0), "=r"(r1), "=r"(r2), "=r"(r3) : "r"(addr))

#define LDMX2(r0, r1, addr)                                                      \
    asm volatile("ldmatrix.sync.aligned.m8n8.x2.shared.b16 {%0,%1}, [%2];"       \
                 : "=r"(r0), "=r"(r1) : "r"(addr))

#define MMA16816(d, a, b)                                                        \
    asm volatile("mma.sync.aligned.m16n8k16.row.col.f32.bf16.bf16.f32 "          \
                 "{%0,%1,%2,%3}, {%4,%5,%6,%7}, {%8,%9}, {%0,%1,%2,%3};"         \
                 : "+f"((d)[0]), "+f"((d)[1]), "+f"((d)[2]), "+f"((d)[3])        \
                 : "r"((a)[0]), "r"((a)[1]), "r"((a)[2]), "r"((a)[3]),           \
                   "r"((b)[0]), "r"((b)[1]))

#define CP_ASYNC16(dst, src)                                                     \
    asm volatile("cp.async.cg.shared.global [%0], [%1], 16;" :: "r"(dst), "l"(src))

// ---------------- bf16x3 GEMM via mma.sync: C = A @ B^T --------------------
// A: MxK (hi/lo bf16), B: NxK (hi/lo bf16), C: MxN fp32.
// CTA tile 128x128, K-chunk 32, 8 warps (warp tile 32x64), double-buffered.
#define CK 32
#define ROW_B 80                     // 64B data + 16B pad (conflict-free ldmatrix)
#define MAT_B (128 * ROW_B)          // 10240 bytes per matrix tile
#define BUF_B (4 * MAT_B)            // Ah | Al | Bh | Bl
#define GEMM_SMEM (2 * BUF_B)        // 81920 bytes

__global__ __launch_bounds__(256, 2)
void mma_gemm(const __nv_bfloat16* __restrict__ Ah, const __nv_bfloat16* __restrict__ Al,
              const __nv_bfloat16* __restrict__ Bh, const __nv_bfloat16* __restrict__ Bl,
              float* __restrict__ C, int M, int N, int K)
{
    extern __shared__ char sm[];
    const uint32_t smb = smem_u32(sm);

    const int tid = threadIdx.x;
    const int wid = tid >> 5;
    const int lane = tid & 31;
    const int wm = wid & 3;          // M band (4 x 32 rows)
    const int wn = wid >> 2;         // N band (2 x 64 cols)
    const int bm = blockIdx.y;
    const int bn = blockIdx.x;

    const __nv_bfloat16* baseAh = Ah + (size_t)(bm * 128) * K;
    const __nv_bfloat16* baseAl = Al + (size_t)(bm * 128) * K;
    const __nv_bfloat16* baseBh = Bh + (size_t)(bn * 128) * K;
    const __nv_bfloat16* baseBl = Bl + (size_t)(bn * 128) * K;

    float acc[2][8][4];
    #pragma unroll
    for (int mi = 0; mi < 2; mi++)
        #pragma unroll
        for (int ni = 0; ni < 8; ni++)
            #pragma unroll
            for (int j = 0; j < 4; j++) acc[mi][ni][j] = 0.f;

    // chunk loader: 4 matrices x 128 rows x 64B, 16B per cp.async
    auto load_chunk = [&](int kb, int b) {
        uint32_t bufb = smb + b * BUF_B;
        #pragma unroll
        for (int it = 0; it < 8; it++) {
            const __nv_bfloat16* base =
                (it < 2) ? baseAh : (it < 4) ? baseAl : (it < 6) ? baseBh : baseBl;
            int idx = ((it & 1) << 8) + tid;         // 0..511
            int r = idx >> 2;
            int c = tid & 3;
            const void* src = base + (size_t)r * K + kb * CK + c * 8;
            uint32_t dst = bufb + (it >> 1) * MAT_B + r * ROW_B + c * 16;
            CP_ASYNC16(dst, src);
        }
        asm volatile("cp.async.commit_group;");
    };

    const int NC = K / CK;
    load_chunk(0, 0);

    for (int i = 0; i < NC; i++) {
        if (i + 1 < NC) {
            load_chunk(i + 1, (i + 1) & 1);
            asm volatile("cp.async.wait_group 1;");
        } else {
            asm volatile("cp.async.wait_group 0;");
        }
        __syncthreads();

        uint32_t sbase = smb + (i & 1) * BUF_B;
        uint32_t aoff_h = sbase + (wm * 32 + (lane & 15)) * ROW_B + (lane >> 4) * 16;
        uint32_t aoff_l = aoff_h + MAT_B;
        uint32_t boff_h = sbase + 2 * MAT_B
                        + (wn * 64 + (lane & 7)) * ROW_B + ((lane >> 3) & 1) * 16;
        uint32_t boff_l = boff_h + MAT_B;

        #pragma unroll
        for (int kk = 0; kk < 2; kk++) {
            uint32_t a_h[2][4], a_l[2][4];
            #pragma unroll
            for (int mi = 0; mi < 2; mi++) {
                LDMX4(a_h[mi][0], a_h[mi][1], a_h[mi][2], a_h[mi][3],
                      aoff_h + mi * 16 * ROW_B + kk * 32);
                LDMX4(a_l[mi][0], a_l[mi][1], a_l[mi][2], a_l[mi][3],
                      aoff_l + mi * 16 * ROW_B + kk * 32);
            }
            #pragma unroll
            for (int ni = 0; ni < 8; ni++) {
                uint32_t bh[2], bl[2];
                LDMX2(bh[0], bh[1], boff_h + ni * 8 * ROW_B + kk * 32);
                LDMX2(bl[0], bl[1], boff_l + ni * 8 * ROW_B + kk * 32);
                #pragma unroll
                for (int mi = 0; mi < 2; mi++) {
                    MMA16816(acc[mi][ni], a_h[mi], bh);
                    MMA16816(acc[mi][ni], a_h[mi], bl);
                    MMA16816(acc[mi][ni], a_l[mi], bh);
                }
            }
        }
        __syncthreads();
    }

    // epilogue: fp32 direct stores
    #pragma unroll
    for (int mi = 0; mi < 2; mi++) {
        int row0 = bm * 128 + wm * 32 + mi * 16 + (lane >> 2);
        #pragma unroll
        for (int ni = 0; ni < 8; ni++) {
            int col = bn * 128 + wn * 64 + ni * 8 + (lane & 3) * 2;
            float2 v0 = make_float2(acc[mi][ni][0], acc[mi][ni][1]);
            float2 v1 = make_float2(acc[mi][ni][2], acc[mi][ni][3]);
            *(float2*)(C + (size_t)row0 * N + col) = v0;
            *(float2*)(C + (size_t)(row0 + 8) * N + col) = v1;
        }
    }
}

// ---------------- fp32 -> bf16 hi/lo split ----------------
__global__ __launch_bounds__(256) void cvt_split(
    const float4* __restrict__ x, __nv_bfloat162* __restrict__ hi,
    __nv_bfloat162* __restrict__ lo, int n4)
{
    int i = blockIdx.x * 256 + threadIdx.x;
    if (i >= n4) return;
    float4 v = x[i];
    __nv_bfloat16 h0 = __float2bfloat16_rn(v.x);
    __nv_bfloat16 h1 = __float2bfloat16_rn(v.y);
    __nv_bfloat16 h2 = __float2bfloat16_rn(v.z);
    __nv_bfloat16 h3 = __float2bfloat16_rn(v.w);
    __nv_bfloat16 l0 = __float2bfloat16_rn(v.x - __bfloat162float(h0));
    __nv_bfloat16 l1 = __float2bfloat16_rn(v.y - __bfloat162float(h1));
    __nv_bfloat16 l2 = __float2bfloat16_rn(v.z - __bfloat162float(h2));
    __nv_bfloat16 l3 = __float2bfloat16_rn(v.w - __bfloat162float(h3));
    hi[2 * i]     = __halves2bfloat162(h0, h1);
    hi[2 * i + 1] = __halves2bfloat162(h2, h3);
    lo[2 * i]     = __halves2bfloat162(l0, l1);
    lo[2 * i + 1] = __halves2bfloat162(l2, l3);
}

__global__ __launch_bounds__(256) void cvt_wa(
    const float* __restrict__ wq, const float* __restrict__ wk,
    const float* __restrict__ wv, __nv_bfloat16* __restrict__ hi,
    __nv_bfloat16* __restrict__ lo)
{
    int i = blockIdx.x * 256 + threadIdx.x;
    if (i >= 128 * HID) return;
    int row = i >> 11, col = i & (HID - 1);
    float val = 0.f;
    if (row < 48)      val = wq[row * HID + col];
    else if (row < 56) val = wk[(row - 48) * HID + col];
    else if (row < 64) val = wv[(row - 56) * HID + col];
    __nv_bfloat16 h = __float2bfloat16_rn(val);
    hi[i] = h;
    lo[i] = __float2bfloat16_rn(val - __bfloat162float(h));
}

// ---------------- fused RoPE + tensor-product + RMSNorm --------------------
__global__ __launch_bounds__(256) void qkv_kernel(
    const float* __restrict__ Acat, const float* __restrict__ Bq,
    const float* __restrict__ Bk, const float* __restrict__ Bv,
    const float* __restrict__ fcos, const float* __restrict__ fsin,
    const float* __restrict__ qnw, const float* __restrict__ knw,
    const int* __restrict__ idx,
    float* __restrict__ qo, float* __restrict__ ko, float* __restrict__ vo)
{
    int s = blockIdx.x;
    int tid = threadIdx.x;
    int d = tid;
    int warp = tid >> 5, lane = tid & 31;

    __shared__ float sA[64];
    __shared__ float red[8][8];
    __shared__ float srstd[8];
    __shared__ float skrstd[4];

    if (tid < 64) sA[tid] = Acat[s * 128 + tid];
    __syncthreads();

    float c  = fcos[s * (HD / 2) + (d >> 1)];
    float sn = fsin[s * (HD / 2) + (d >> 1)];
    float seff = (d & 1) ? sn : -sn;

    float bq[QR];
    #pragma unroll
    for (int r = 0; r < QR; r++) {
        float x  = Bq[(size_t)s * (QR * HD) + r * HD + d];
        float xn = Bq[(size_t)s * (QR * HD) + r * HD + (d ^ 1)];
        bq[r] = x * c + xn * seff;
    }
    float qraw[NH];
    #pragma unroll
    for (int h = 0; h < NH; h++) {
        float a = 0.f;
        #pragma unroll
        for (int r = 0; r < QR; r++) a += sA[h * QR + r] * bq[r];
        qraw[h] = a * (1.f / QR);
    }
    #pragma unroll
    for (int h = 0; h < NH; h++) {
        float ss = qraw[h] * qraw[h];
        #pragma unroll
        for (int o = 16; o > 0; o >>= 1) ss += __shfl_xor_sync(0xffffffffu, ss, o);
        if (lane == 0) red[warp][h] = ss;
    }
    __syncthreads();
    if (tid < NH) {
        float t = 0.f;
        #pragma unroll
        for (int w = 0; w < 8; w++) t += red[w][tid];
        srstd[tid] = rsqrtf(t * (1.f / HD) + EPS);
    }
    __syncthreads();
    float qw = (1.f + qnw[d]) * SCALING;
    #pragma unroll
    for (int h = 0; h < NH; h++)
        qo[((size_t)s * NH + h) * HD + d] = qraw[h] * srstd[h] * qw;

    float bk[KR];
    #pragma unroll
    for (int r = 0; r < KR; r++) {
        float x  = Bk[(size_t)s * (KR * HD) + r * HD + d];
        float xn = Bk[(size_t)s * (KR * HD) + r * HD + (d ^ 1)];
        bk[r] = x * c + xn * seff;
    }
    float kraw[KVH];
    #pragma unroll
    for (int kh = 0; kh < KVH; kh++)
        kraw[kh] = (sA[48 + kh * KR + 0] * bk[0] + sA[48 + kh * KR + 1] * bk[1]) * 0.5f;

    __syncthreads();
    #pragma unroll
    for (int kh = 0; kh < KVH; kh++) {
        float ss = kraw[kh] * kraw[kh];
        #pragma unroll
        for (int o = 16; o > 0; o >>= 1) ss += __shfl_xor_sync(0xffffffffu, ss, o);
        if (lane == 0) red[warp][kh] = ss;
    }
    __syncthreads();
    if (tid < KVH) {
        float t = 0.f;
        #pragma unroll
        for (int w = 0; w < 8; w++) t += red[w][tid];
        skrstd[tid] = rsqrtf(t * (1.f / HD) + EPS);
    }
    __syncthreads();

    int tpos = idx[s];
    float kw = 1.f + knw[d];
    #pragma unroll
    for (int kh = 0; kh < KVH; kh++)
        ko[((size_t)tpos * KVH + kh) * HD + d] = kraw[kh] * skrstd[kh] * kw;

    float bv0 = Bv[(size_t)s * (VR * HD) + 0 * HD + d];
    float bv1 = Bv[(size_t)s * (VR * HD) + 1 * HD + d];
    #pragma unroll
    for (int kh = 0; kh < KVH; kh++)
        vo[((size_t)tpos * KVH + kh) * HD + d] =
            (sA[56 + kh * VR + 0] * bv0 + sA[56 + kh * VR + 1] * bv1) * 0.5f;
}

// ---------------- sliding-window softcapped attention ----------------------
#define BQ 32
#define BT 16

__global__ __launch_bounds__(256) void attn_kernel(
    const float* __restrict__ q, const float* __restrict__ k,
    const float* __restrict__ v, const int* __restrict__ idx,
    float* __restrict__ out)
{
    __shared__ float sk[BT][HD];
    __shared__ float sv[BT][HD];
    __shared__ int spos[BQ];
    __shared__ int srange[2];

    int s0 = blockIdx.x * BQ;
    int h = blockIdx.y;
    int kvh = h >> 1;
    int tid = threadIdx.x;
    int qi = tid >> 3;
    int g = tid & 7;

    if (tid < BQ) spos[tid] = idx[s0 + tid];
    __syncthreads();
    if (tid == 0) {
        int mn = spos[0], mx = spos[0];
        for (int i = 1; i < BQ; i++) { mn = min(mn, spos[i]); mx = max(mx, spos[i]); }
        srange[0] = max(0, mn - (WINDOW - 1));
        srange[1] = mx;
    }
    __syncthreads();
    int kmin = srange[0], kmax = srange[1];
    int qpos = spos[qi];

    float qreg[32];
    const float* qp = q + ((size_t)(s0 + qi) * NH + h) * HD + g;
    #pragma unroll
    for (int j = 0; j < 32; j++) qreg[j] = qp[8 * j];

    float acc[32];
    #pragma unroll
    for (int j = 0; j < 32; j++) acc[j] = 0.f;
    float den = 0.f;

    for (int t0 = kmin; t0 <= kmax; t0 += BT) {
        for (int l = tid; l < BT * HD / 4; l += 256) {
            int row = l >> 6;
            int c4 = l & 63;
            int t = t0 + row;
            float4 kq = make_float4(0.f, 0.f, 0.f, 0.f);
            float4 vq = make_float4(0.f, 0.f, 0.f, 0.f);
            if (t < S_LEN) {
                kq = *(const float4*)(k + ((size_t)t * KVH + kvh) * HD + c4 * 4);
                vq = *(const float4*)(v + ((size_t)t * KVH + kvh) * HD + c4 * 4);
            }
            *(float4*)&sk[row][c4 * 4] = kq;
            *(float4*)&sv[row][c4 * 4] = vq;
        }
        __syncthreads();

        float ps[BT];
        #pragma unroll
        for (int t = 0; t < BT; t++) ps[t] = 0.f;
        #pragma unroll
        for (int j = 0; j < 32; j++) {
            float qv = qreg[j];
            #pragma unroll
            for (int t = 0; t < BT; t++)
                ps[t] += qv * sk[t][g + 8 * j];
        }
        #pragma unroll
        for (int t = 0; t < BT; t++) {
            float x = ps[t];
            x += __shfl_xor_sync(0xffffffffu, x, 1, 8);
            x += __shfl_xor_sync(0xffffffffu, x, 2, 8);
            x += __shfl_xor_sync(0xffffffffu, x, 4, 8);
            ps[t] = x;
        }
        #pragma unroll
        for (int t = 0; t < BT; t++) {
            int tt = t0 + t;
            int diff = qpos - tt;
            float p = 0.f;
            if (diff >= 0 && diff < WINDOW) {
                float sc = tanhf(ps[t] * (1.f / SOFTCAP)) * SOFTCAP;
                p = __expf(sc);
            }
            if (p != 0.f) {
                den += p;
                #pragma unroll
                for (int j = 0; j < 32; j++)
                    acc[j] += p * sv[t][g + 8 * j];
            }
        }
        __syncthreads();
    }

    float inv = 1.f / den;
    float* op = out + (size_t)(s0 + qi) * (NH * HD) + h * HD + g;
    #pragma unroll
    for (int j = 0; j < 32; j++) op[8 * j] = acc[j] * inv;
}

// ---------------- launch ----------------------------------------------------
extern "C" void kernel_launch(void* const* d_in, const int* in_sizes, int n_in,
                              void* d_out, int out_size)
{
    const float* x   = (const float*)d_in[0];
    const float* fc  = (const float*)d_in[1];
    const float* fs  = (const float*)d_in[2];
    const float* WAq = (const float*)d_in[3];
    const float* WAk = (const float*)d_in[4];
    const float* WAv = (const float*)d_in[5];
    const float* WBq = (const float*)d_in[6];
    const float* WBk = (const float*)d_in[7];
    const float* WBv = (const float*)d_in[8];
    const float* Wo  = (const float*)d_in[9];
    const float* qnw = (const float*)d_in[10];
    const float* knw = (const float*)d_in[11];
    const int*   idx = (const int*)d_in[16];
    float* out = (float*)d_out;

    float *gAcat, *gBq, *gBk, *gBv, *gq, *gk, *gv, *gattn;
    __nv_bfloat16 *xhi, *xlo, *wbqh, *wbql, *wbkh, *wbkl, *wbvh, *wbvl;
    __nv_bfloat16 *woh, *wol, *wah, *wal, *ah, *al;
    cudaGetSymbolAddress((void**)&gAcat, g_Acat);
    cudaGetSymbolAddress((void**)&gBq, g_Bq);
    cudaGetSymbolAddress((void**)&gBk, g_Bk);
    cudaGetSymbolAddress((void**)&gBv, g_Bv);
    cudaGetSymbolAddress((void**)&gq,  g_q);
    cudaGetSymbolAddress((void**)&gk,  g_k);
    cudaGetSymbolAddress((void**)&gv,  g_v);
    cudaGetSymbolAddress((void**)&gattn, g_attn);
    cudaGetSymbolAddress((void**)&xhi, g_xhi);
    cudaGetSymbolAddress((void**)&xlo, g_xlo);
    cudaGetSymbolAddress((void**)&wbqh, g_wbq_hi);
    cudaGetSymbolAddress((void**)&wbql, g_wbq_lo);
    cudaGetSymbolAddress((void**)&wbkh, g_wbk_hi);
    cudaGetSymbolAddress((void**)&wbkl, g_wbk_lo);
    cudaGetSymbolAddress((void**)&wbvh, g_wbv_hi);
    cudaGetSymbolAddress((void**)&wbvl, g_wbv_lo);
    cudaGetSymbolAddress((void**)&woh, g_wo_hi);
    cudaGetSymbolAddress((void**)&wol, g_wo_lo);
    cudaGetSymbolAddress((void**)&wah, g_wa_hi);
    cudaGetSymbolAddress((void**)&wal, g_wa_lo);
    cudaGetSymbolAddress((void**)&ah, g_attnhi);
    cudaGetSymbolAddress((void**)&al, g_attnlo);

    cudaFuncSetAttribute(mma_gemm, cudaFuncAttributeMaxDynamicSharedMemorySize, GEMM_SMEM);

    cudaMemsetAsync(gk, 0, (size_t)S_LEN * KVH * HD * sizeof(float));
    cudaMemsetAsync(gv, 0, (size_t)S_LEN * KVH * HD * sizeof(float));

    {
        int n4 = S_LEN * HID / 4;
        cvt_split<<<(n4 + 255) / 256, 256>>>((const float4*)x,
            (__nv_bfloat162*)xhi, (__nv_bfloat162*)xlo, n4);
    }
    {
        int n4 = QR * HD * HID / 4;
        cvt_split<<<(n4 + 255) / 256, 256>>>((const float4*)WBq,
            (__nv_bfloat162*)wbqh, (__nv_bfloat162*)wbql, n4);
    }
    {
        int n4 = KR * HD * HID / 4;
        cvt_split<<<(n4 + 255) / 256, 256>>>((const float4*)WBk,
            (__nv_bfloat162*)wbkh, (__nv_bfloat162*)wbkl, n4);
    }
    {
        int n4 = VR * HD * HID / 4;
        cvt_split<<<(n4 + 255) / 256, 256>>>((const float4*)WBv,
            (__nv_bfloat162*)wbvh, (__nv_bfloat162*)wbvl, n4);
    }
    {
        int n4 = HID * HID / 4;
        cvt_split<<<(n4 + 255) / 256, 256>>>((const float4*)Wo,
            (__nv_bfloat162*)woh, (__nv_bfloat162*)wol, n4);
    }
    cvt_wa<<<(128 * HID + 255) / 256, 256>>>(WAq, WAk, WAv, wah, wal);

    // projections via mma.sync bf16x3
    mma_gemm<<<dim3(1, 32), 256, GEMM_SMEM>>>(xhi, xlo, wah, wal, gAcat, S_LEN, 128, HID);
    mma_gemm<<<dim3(12, 32), 256, GEMM_SMEM>>>(xhi, xlo, wbqh, wbql, gBq, S_LEN, QR * HD, HID);
    mma_gemm<<<dim3(4, 32), 256, GEMM_SMEM>>>(xhi, xlo, wbkh, wbkl, gBk, S_LEN, KR * HD, HID);
    mma_gemm<<<dim3(4, 32), 256, GEMM_SMEM>>>(xhi, xlo, wbvh, wbvl, gBv, S_LEN, VR * HD, HID);

    qkv_kernel<<<S_LEN, 256>>>(gAcat, gBq, gBk, gBv, fc, fs, qnw, knw, idx, gq, gk, gv);

    attn_kernel<<<dim3(S_LEN / BQ, NH), 256>>>(gq, gk, gv, idx, gattn);

    {
        int n4 = S_LEN * HID / 4;
        cvt_split<<<(n4 + 255) / 256, 256>>>((const float4*)gattn,
            (__nv_bfloat162*)ah, (__nv_bfloat162*)al, n4);
    }
    mma_gemm<<<dim3(16, 32), 256, GEMM_SMEM>>>(ah, al, woh, wol, out, S_LEN, HID, HID);
}

// round 5
// speedup vs baseline: 3.7292x; 2.1035x over previous
#include <cuda_runtime.h>
#include <cuda_bf16.h>
#include <math.h>
#include <stdint.h>

#define S_LEN 4096
#define HID 2048
#define NH 8
#define KVH 4
#define HD 256
#define QR 6
#define KR 2
#define VR 2
#define WINDOW 1024
#define SOFTCAP 50.0f
#define SCALING 0.0625f
#define EPS 1e-6f
#define NPROJ 2688           // 1536 Bq | 512 Bk | 512 Bv | 64 A | 64 pad

// ---------------- scratch ----------------
__device__ float g_proj[S_LEN * NPROJ];
__device__ float g_q[S_LEN * NH * HD];
__device__ float g_k[S_LEN * KVH * HD];
__device__ float g_v[S_LEN * KVH * HD];
__device__ float g_attn[S_LEN * NH * HD];

__device__ __nv_bfloat16 g_xhi[S_LEN * HID];
__device__ __nv_bfloat16 g_xlo[S_LEN * HID];
__device__ __nv_bfloat16 g_wcat_hi[NPROJ * HID];
__device__ __nv_bfloat16 g_wcat_lo[NPROJ * HID];
__device__ __nv_bfloat16 g_wo_hi[HID * HID];
__device__ __nv_bfloat16 g_wo_lo[HID * HID];
__device__ __nv_bfloat16 g_attnhi[S_LEN * HID];
__device__ __nv_bfloat16 g_attnlo[S_LEN * HID];

// ---------------- helpers ----------------
__device__ __forceinline__ uint32_t smem_u32(const void* p) {
    uint32_t a;
    asm("{ .reg .u64 t; cvta.to.shared.u64 t, %1; cvt.u32.u64 %0, t; }" : "=r"(a) : "l"(p));
    return a;
}

__device__ __forceinline__ float tf32r(float x) {
    uint32_t u;
    asm("cvt.rna.tf32.f32 %0, %1;" : "=r"(u) : "f"(x));
    return __uint_as_float(u);
}
__device__ __forceinline__ uint32_t tf32u(float x) {
    uint32_t u;
    asm("cvt.rna.tf32.f32 %0, %1;" : "=r"(u) : "f"(x));
    return u;
}

#define LDMX4(r0, r1, r2, r3, addr)                                              \
    asm volatile("ldmatrix.sync.aligned.m8n8.x4.shared.b16 {%0,%1,%2,%3}, [%4];" \
                 : "=r"(r0), "=r"(r1), "=r"(r2), "=r"(r3) : "r"(addr))
#define LDMX2(r0, r1, addr)                                                      \
    asm volatile("ldmatrix.sync.aligned.m8n8.x2.shared.b16 {%0,%1}, [%2];"       \
                 : "=r"(r0), "=r"(r1) : "r"(addr))
#define MMA16816(d, a, b)                                                        \
    asm volatile("mma.sync.aligned.m16n8k16.row.col.f32.bf16.bf16.f32 "          \
                 "{%0,%1,%2,%3}, {%4,%5,%6,%7}, {%8,%9}, {%0,%1,%2,%3};"         \
                 : "+f"((d)[0]), "+f"((d)[1]), "+f"((d)[2]), "+f"((d)[3])        \
                 : "r"((a)[0]), "r"((a)[1]), "r"((a)[2]), "r"((a)[3]),           \
                   "r"((b)[0]), "r"((b)[1]))
#define MMAT32(d, a, b)                                                          \
    asm volatile("mma.sync.aligned.m16n8k8.row.col.f32.tf32.tf32.f32 "           \
                 "{%0,%1,%2,%3}, {%4,%5,%6,%7}, {%8,%9}, {%0,%1,%2,%3};"         \
                 : "+f"((d)[0]), "+f"((d)[1]), "+f"((d)[2]), "+f"((d)[3])        \
                 : "r"((a)[0]), "r"((a)[1]), "r"((a)[2]), "r"((a)[3]),           \
                   "r"((b)[0]), "r"((b)[1]))
#define CP_ASYNC16(dst, src)                                                     \
    asm volatile("cp.async.cg.shared.global [%0], [%1], 16;" :: "r"(dst), "l"(src))
#define CP_ASYNC16Z(dst, src, sz)                                                \
    asm volatile("cp.async.cg.shared.global [%0], [%1], 16, %2;"                 \
                 :: "r"(dst), "l"(src), "r"(sz))

// ---------------- bf16x3 GEMM via mma.sync: C = A @ B^T --------------------
#define CK 32
#define ROW_B 80
#define MAT_B (128 * ROW_B)
#define BUF_B (4 * MAT_B)
#define GEMM_SMEM (2 * BUF_B)

__global__ __launch_bounds__(256, 2)
void mma_gemm(const __nv_bfloat16* __restrict__ Ah, const __nv_bfloat16* __restrict__ Al,
              const __nv_bfloat16* __restrict__ Bh, const __nv_bfloat16* __restrict__ Bl,
              float* __restrict__ C, int M, int N, int K)
{
    extern __shared__ char sm[];
    const uint32_t smb = smem_u32(sm);

    const int tid = threadIdx.x;
    const int wid = tid >> 5;
    const int lane = tid & 31;
    const int wm = wid & 3;
    const int wn = wid >> 2;
    const int bm = blockIdx.y;
    const int bn = blockIdx.x;

    const __nv_bfloat16* baseAh = Ah + (size_t)(bm * 128) * K;
    const __nv_bfloat16* baseAl = Al + (size_t)(bm * 128) * K;
    const __nv_bfloat16* baseBh = Bh + (size_t)(bn * 128) * K;
    const __nv_bfloat16* baseBl = Bl + (size_t)(bn * 128) * K;

    float acc[2][8][4];
    #pragma unroll
    for (int mi = 0; mi < 2; mi++)
        #pragma unroll
        for (int ni = 0; ni < 8; ni++)
            #pragma unroll
            for (int j = 0; j < 4; j++) acc[mi][ni][j] = 0.f;

    auto load_chunk = [&](int kb, int b) {
        uint32_t bufb = smb + b * BUF_B;
        #pragma unroll
        for (int it = 0; it < 8; it++) {
            const __nv_bfloat16* base =
                (it < 2) ? baseAh : (it < 4) ? baseAl : (it < 6) ? baseBh : baseBl;
            int idx = ((it & 1) << 8) + tid;
            int r = idx >> 2;
            int c = tid & 3;
            const void* src = base + (size_t)r * K + kb * CK + c * 8;
            uint32_t dst = bufb + (it >> 1) * MAT_B + r * ROW_B + c * 16;
            CP_ASYNC16(dst, src);
        }
        asm volatile("cp.async.commit_group;");
    };

    const int NC = K / CK;
    load_chunk(0, 0);

    for (int i = 0; i < NC; i++) {
        if (i + 1 < NC) {
            load_chunk(i + 1, (i + 1) & 1);
            asm volatile("cp.async.wait_group 1;");
        } else {
            asm volatile("cp.async.wait_group 0;");
        }
        __syncthreads();

        uint32_t sbase = smb + (i & 1) * BUF_B;
        uint32_t aoff_h = sbase + (wm * 32 + (lane & 15)) * ROW_B + (lane >> 4) * 16;
        uint32_t aoff_l = aoff_h + MAT_B;
        uint32_t boff_h = sbase + 2 * MAT_B
                        + (wn * 64 + (lane & 7)) * ROW_B + ((lane >> 3) & 1) * 16;
        uint32_t boff_l = boff_h + MAT_B;

        #pragma unroll
        for (int kk = 0; kk < 2; kk++) {
            uint32_t a_h[2][4], a_l[2][4];
            #pragma unroll
            for (int mi = 0; mi < 2; mi++) {
                LDMX4(a_h[mi][0], a_h[mi][1], a_h[mi][2], a_h[mi][3],
                      aoff_h + mi * 16 * ROW_B + kk * 32);
                LDMX4(a_l[mi][0], a_l[mi][1], a_l[mi][2], a_l[mi][3],
                      aoff_l + mi * 16 * ROW_B + kk * 32);
            }
            #pragma unroll
            for (int ni = 0; ni < 8; ni++) {
                uint32_t bh[2], bl[2];
                LDMX2(bh[0], bh[1], boff_h + ni * 8 * ROW_B + kk * 32);
                LDMX2(bl[0], bl[1], boff_l + ni * 8 * ROW_B + kk * 32);
                #pragma unroll
                for (int mi = 0; mi < 2; mi++) {
                    MMA16816(acc[mi][ni], a_h[mi], bh);
                    MMA16816(acc[mi][ni], a_h[mi], bl);
                    MMA16816(acc[mi][ni], a_l[mi], bh);
                }
            }
        }
        __syncthreads();
    }

    #pragma unroll
    for (int mi = 0; mi < 2; mi++) {
        int row0 = bm * 128 + wm * 32 + mi * 16 + (lane >> 2);
        #pragma unroll
        for (int ni = 0; ni < 8; ni++) {
            int col = bn * 128 + wn * 64 + ni * 8 + (lane & 3) * 2;
            *(float2*)(C + (size_t)row0 * N + col) =
                make_float2(acc[mi][ni][0], acc[mi][ni][1]);
            *(float2*)(C + (size_t)(row0 + 8) * N + col) =
                make_float2(acc[mi][ni][2], acc[mi][ni][3]);
        }
    }
}

// ---------------- conversions ----------------
__global__ __launch_bounds__(256) void cvt_split(
    const float4* __restrict__ x, __nv_bfloat162* __restrict__ hi,
    __nv_bfloat162* __restrict__ lo, int n4)
{
    int i = blockIdx.x * 256 + threadIdx.x;
    if (i >= n4) return;
    float4 v = x[i];
    __nv_bfloat16 h0 = __float2bfloat16_rn(v.x);
    __nv_bfloat16 h1 = __float2bfloat16_rn(v.y);
    __nv_bfloat16 h2 = __float2bfloat16_rn(v.z);
    __nv_bfloat16 h3 = __float2bfloat16_rn(v.w);
    hi[2 * i]     = __halves2bfloat162(h0, h1);
    hi[2 * i + 1] = __halves2bfloat162(h2, h3);
    lo[2 * i]     = __halves2bfloat162(
        __float2bfloat16_rn(v.x - __bfloat162float(h0)),
        __float2bfloat16_rn(v.y - __bfloat162float(h1)));
    lo[2 * i + 1] = __halves2bfloat162(
        __float2bfloat16_rn(v.z - __bfloat162float(h2)),
        __float2bfloat16_rn(v.w - __bfloat162float(h3)));
}

// build concatenated projection weight [NPROJ, HID] hi/lo
__global__ __launch_bounds__(256) void cvt_wcat(
    const float* __restrict__ wbq, const float* __restrict__ wbk,
    const float* __restrict__ wbv, const float* __restrict__ waq,
    const float* __restrict__ wak, const float* __restrict__ wav,
    __nv_bfloat16* __restrict__ hi, __nv_bfloat16* __restrict__ lo)
{
    int i = blockIdx.x * 256 + threadIdx.x;
    if (i >= NPROJ * HID) return;
    int row = i / HID, col = i - row * HID;
    float val = 0.f;
    if (row < 1536)      val = wbq[row * HID + col];
    else if (row < 2048) val = wbk[(row - 1536) * HID + col];
    else if (row < 2560) val = wbv[(row - 2048) * HID + col];
    else if (row < 2608) val = waq[(row - 2560) * HID + col];
    else if (row < 2616) val = wak[(row - 2608) * HID + col];
    else if (row < 2624) val = wav[(row - 2616) * HID + col];
    __nv_bfloat16 h = __float2bfloat16_rn(val);
    hi[i] = h;
    lo[i] = __float2bfloat16_rn(val - __bfloat162float(h));
}

// ---------------- fused RoPE + tensor-product + RMSNorm --------------------
__global__ __launch_bounds__(256) void qkv_kernel(
    const float* __restrict__ proj,
    const float* __restrict__ fcos, const float* __restrict__ fsin,
    const float* __restrict__ qnw, const float* __restrict__ knw,
    const int* __restrict__ idx,
    float* __restrict__ qo, float* __restrict__ ko, float* __restrict__ vo)
{
    int s = blockIdx.x;
    int tid = threadIdx.x;
    int d = tid;
    int warp = tid >> 5, lane = tid & 31;
    const float* row = proj + (size_t)s * NPROJ;

    __shared__ float sA[64];
    __shared__ float red[8][8];
    __shared__ float srstd[8];
    __shared__ float skrstd[4];

    if (tid < 64) sA[tid] = row[2560 + tid];
    __syncthreads();

    float c  = fcos[s * (HD / 2) + (d >> 1)];
    float sn = fsin[s * (HD / 2) + (d >> 1)];
    float seff = (d & 1) ? sn : -sn;

    float bq[QR];
    #pragma unroll
    for (int r = 0; r < QR; r++) {
        float x  = row[r * HD + d];
        float xn = row[r * HD + (d ^ 1)];
        bq[r] = x * c + xn * seff;
    }
    float qraw[NH];
    #pragma unroll
    for (int h = 0; h < NH; h++) {
        float a = 0.f;
        #pragma unroll
        for (int r = 0; r < QR; r++) a += sA[h * QR + r] * bq[r];
        qraw[h] = a * (1.f / QR);
    }
    #pragma unroll
    for (int h = 0; h < NH; h++) {
        float ss = qraw[h] * qraw[h];
        #pragma unroll
        for (int o = 16; o > 0; o >>= 1) ss += __shfl_xor_sync(0xffffffffu, ss, o);
        if (lane == 0) red[warp][h] = ss;
    }
    __syncthreads();
    if (tid < NH) {
        float t = 0.f;
        #pragma unroll
        for (int w = 0; w < 8; w++) t += red[w][tid];
        srstd[tid] = rsqrtf(t * (1.f / HD) + EPS);
    }
    __syncthreads();
    float qw = (1.f + qnw[d]) * SCALING;
    #pragma unroll
    for (int h = 0; h < NH; h++)
        qo[((size_t)s * NH + h) * HD + d] = tf32r(qraw[h] * srstd[h] * qw);

    float bk[KR];
    #pragma unroll
    for (int r = 0; r < KR; r++) {
        float x  = row[1536 + r * HD + d];
        float xn = row[1536 + r * HD + (d ^ 1)];
        bk[r] = x * c + xn * seff;
    }
    float kraw[KVH];
    #pragma unroll
    for (int kh = 0; kh < KVH; kh++)
        kraw[kh] = (sA[48 + kh * KR + 0] * bk[0] + sA[48 + kh * KR + 1] * bk[1]) * 0.5f;

    __syncthreads();
    #pragma unroll
    for (int kh = 0; kh < KVH; kh++) {
        float ss = kraw[kh] * kraw[kh];
        #pragma unroll
        for (int o = 16; o > 0; o >>= 1) ss += __shfl_xor_sync(0xffffffffu, ss, o);
        if (lane == 0) red[warp][kh] = ss;
    }
    __syncthreads();
    if (tid < KVH) {
        float t = 0.f;
        #pragma unroll
        for (int w = 0; w < 8; w++) t += red[w][tid];
        skrstd[tid] = rsqrtf(t * (1.f / HD) + EPS);
    }
    __syncthreads();

    int tpos = idx[s];
    float kw = 1.f + knw[d];
    #pragma unroll
    for (int kh = 0; kh < KVH; kh++)
        ko[((size_t)tpos * KVH + kh) * HD + d] = tf32r(kraw[kh] * skrstd[kh] * kw);

    float bv0 = row[2048 + 0 * HD + d];
    float bv1 = row[2048 + 1 * HD + d];
    #pragma unroll
    for (int kh = 0; kh < KVH; kh++)
        vo[((size_t)tpos * KVH + kh) * HD + d] =
            tf32r((sA[56 + kh * VR + 0] * bv0 + sA[56 + kh * VR + 1] * bv1) * 0.5f);
}

// ---------------- tf32 HMMA flash attention ----------------
// CTA: 64 queries x 1 head; 8 warps: 0-3 score (QK->P), 4-7 PV.
#define AQ 64
#define ACT 32
#define SKS 260
#define SVS 264
#define SPS 36
#define SK_F (ACT * SKS)
#define SV_F (ACT * SVS)
#define OFF_K0 0
#define OFF_K1 SK_F
#define OFF_V0 (2 * SK_F)
#define OFF_V1 (2 * SK_F + SV_F)
#define OFF_P  (2 * SK_F + 2 * SV_F)
#define OFF_DEN (OFF_P + AQ * SPS)
#define ATTN_SMEM ((OFF_DEN + AQ) * 4)

__global__ __launch_bounds__(256, 1)
void attn_mma(const float* __restrict__ q, const float* __restrict__ k,
              const float* __restrict__ v, const int* __restrict__ idx,
              float* __restrict__ out)
{
    extern __shared__ float smf[];
    __shared__ int spos[AQ];
    __shared__ int srange[2];

    const int s0 = blockIdx.x * AQ;
    const int h = blockIdx.y;
    const int kvh = h >> 1;
    const int tid = threadIdx.x;
    const int wid = tid >> 5;
    const int lane = tid & 31;

    if (tid < AQ) spos[tid] = idx[s0 + tid];
    __syncthreads();
    if (tid == 0) {
        int mn = spos[0], mx = spos[0];
        for (int i = 1; i < AQ; i++) { mn = min(mn, spos[i]); mx = max(mx, spos[i]); }
        srange[0] = max(0, mn - (WINDOW - 1));
        srange[1] = mx;
    }
    __syncthreads();
    const int kmin = srange[0];
    const int nch = (srange[1] - kmin) / ACT + 1;

    const uint32_t smb = smem_u32(smf);
    const float* kbase = k + (size_t)kvh * HD;
    const float* vbase = v + (size_t)kvh * HD;

    auto load_chunk = [&](int ci, int b) {
        int t0 = kmin + ci * ACT;
        #pragma unroll
        for (int j = 0; j < 8; j++) {
            int seg = tid + j * 256;
            int r = seg >> 6;
            int cs = seg & 63;
            int t = t0 + r;
            int sz = (t < S_LEN) ? 16 : 0;
            const void* srck = kbase + (size_t)t * (KVH * HD) + cs * 4;
            const void* srcv = vbase + (size_t)t * (KVH * HD) + cs * 4;
            CP_ASYNC16Z(smb + (((b ? OFF_K1 : OFF_K0) + r * SKS + cs * 4) << 2), srck, sz);
            CP_ASYNC16Z(smb + (((b ? OFF_V1 : OFF_V0) + r * SVS + cs * 4) << 2), srcv, sz);
        }
        asm volatile("cp.async.commit_group;");
    };

    load_chunk(0, 0);

    if (wid < 4) {
        // ---------------- score role ----------------
        const int rw = wid * 16;
        const int r0 = s0 + rw + (lane >> 2);
        const float* q0 = q + ((size_t)r0 * NH + h) * HD;
        const float* q1 = q + ((size_t)(r0 + 8) * NH + h) * HD;
        uint32_t qa[32][4];
        #pragma unroll
        for (int ks = 0; ks < 32; ks++) {
            int c = ks * 8 + (lane & 3);
            qa[ks][0] = __float_as_uint(q0[c]);
            qa[ks][1] = __float_as_uint(q1[c]);
            qa[ks][2] = __float_as_uint(q0[c + 4]);
            qa[ks][3] = __float_as_uint(q1[c + 4]);
        }
        const int qp0 = spos[rw + (lane >> 2)];
        const int qp1 = spos[rw + 8 + (lane >> 2)];
        float den0 = 0.f, den1 = 0.f;

        for (int i = 0; i < nch; i++) {
            __syncthreads();                               // B1
            if (i + 1 < nch) {
                load_chunk(i + 1, (i + 1) & 1);
                asm volatile("cp.async.wait_group 1;");
            } else {
                asm volatile("cp.async.wait_group 0;");
            }
            __syncthreads();                               // B2

            const uint32_t skb = smb + ((i & 1) ? OFF_K1 : OFF_K0) * 4;
            float sacc[4][4];
            #pragma unroll
            for (int j = 0; j < 4; j++)
                #pragma unroll
                for (int e = 0; e < 4; e++) sacc[j][e] = 0.f;

            #pragma unroll 8
            for (int ks = 0; ks < 32; ks++) {
                #pragma unroll
                for (int j = 0; j < 4; j++) {
                    uint32_t kb[2];
                    uint32_t a = skb + ((j * 8 + (lane >> 2)) * SKS + ks * 8 + (lane & 3)) * 4;
                    asm volatile("ld.shared.b32 %0, [%1];" : "=r"(kb[0]) : "r"(a));
                    asm volatile("ld.shared.b32 %0, [%1];" : "=r"(kb[1]) : "r"(a + 16));
                    MMAT32(sacc[j], qa[ks], kb);
                }
            }

            const int t0 = kmin + i * ACT;
            const uint32_t spb = smb + OFF_P * 4;
            #pragma unroll
            for (int j = 0; j < 4; j++) {
                int tk = t0 + j * 8 + (lane & 3) * 2;
                float p[4];
                #pragma unroll
                for (int e = 0; e < 4; e++) {
                    float s = sacc[j][e];
                    int qp = (e < 2) ? qp0 : qp1;
                    int tt = tk + (e & 1);
                    float x2 = (s * (1.f / SOFTCAP)) * (s * (1.f / SOFTCAP));
                    float r = 1.f + x2 * (-0.333333333f + x2 * (0.133333333f + x2 * -0.053968254f));
                    float pe = __expf(s * r);
                    p[e] = ((unsigned)(qp - tt) < WINDOW) ? pe : 0.f;
                }
                uint32_t u0 = tf32u(p[0]), u1 = tf32u(p[1]);
                uint32_t u2 = tf32u(p[2]), u3 = tf32u(p[3]);
                den0 += __uint_as_float(u0) + __uint_as_float(u1);
                den1 += __uint_as_float(u2) + __uint_as_float(u3);
                uint32_t a0 = spb + ((rw + (lane >> 2)) * SPS + j * 8 + (lane & 3) * 2) * 4;
                uint32_t a1 = spb + ((rw + 8 + (lane >> 2)) * SPS + j * 8 + (lane & 3) * 2) * 4;
                asm volatile("st.shared.v2.b32 [%0], {%1,%2};" :: "r"(a0), "r"(u0), "r"(u1));
                asm volatile("st.shared.v2.b32 [%0], {%1,%2};" :: "r"(a1), "r"(u2), "r"(u3));
            }
            __syncthreads();                               // B3
        }
        den0 += __shfl_xor_sync(0xffffffffu, den0, 1);
        den0 += __shfl_xor_sync(0xffffffffu, den0, 2);
        den1 += __shfl_xor_sync(0xffffffffu, den1, 1);
        den1 += __shfl_xor_sync(0xffffffffu, den1, 2);
        if ((lane & 3) == 0) {
            smf[OFF_DEN + rw + (lane >> 2)] = den0;
            smf[OFF_DEN + rw + 8 + (lane >> 2)] = den1;
        }
        __syncthreads();                                   // B4
    } else {
        // ---------------- PV role ----------------
        const int rw = (wid - 4) * 16;
        float oacc[32][4];
        #pragma unroll
        for (int n = 0; n < 32; n++)
            #pragma unroll
            for (int e = 0; e < 4; e++) oacc[n][e] = 0.f;

        for (int i = 0; i < nch; i++) {
            __syncthreads();                               // B1
            if (i + 1 < nch) {
                load_chunk(i + 1, (i + 1) & 1);
                asm volatile("cp.async.wait_group 1;");
            } else {
                asm volatile("cp.async.wait_group 0;");
            }
            __syncthreads();                               // B2
            __syncthreads();                               // B3 (P ready)

            const uint32_t svb = smb + ((i & 1) ? OFF_V1 : OFF_V0) * 4;
            const uint32_t spb = smb + OFF_P * 4;
            uint32_t pa[4][4];
            #pragma unroll
            for (int ks = 0; ks < 4; ks++) {
                uint32_t a = spb + ((rw + (lane >> 2)) * SPS + ks * 8 + (lane & 3)) * 4;
                uint32_t a8 = a + 8 * SPS * 4;
                asm volatile("ld.shared.b32 %0, [%1];" : "=r"(pa[ks][0]) : "r"(a));
                asm volatile("ld.shared.b32 %0, [%1];" : "=r"(pa[ks][1]) : "r"(a8));
                asm volatile("ld.shared.b32 %0, [%1];" : "=r"(pa[ks][2]) : "r"(a + 16));
                asm volatile("ld.shared.b32 %0, [%1];" : "=r"(pa[ks][3]) : "r"(a8 + 16));
            }
            #pragma unroll 8
            for (int n = 0; n < 32; n++) {
                #pragma unroll
                for (int ks = 0; ks < 4; ks++) {
                    uint32_t vb[2];
                    uint32_t a = svb + ((ks * 8 + (lane & 3)) * SVS + n * 8 + (lane >> 2)) * 4;
                    asm volatile("ld.shared.b32 %0, [%1];" : "=r"(vb[0]) : "r"(a));
                    asm volatile("ld.shared.b32 %0, [%1];" : "=r"(vb[1]) : "r"(a + 4 * SVS * 4));
                    MMAT32(oacc[n], pa[ks], vb);
                }
            }
        }
        __syncthreads();                                   // B4 (den ready)
        float inv0 = 1.f / smf[OFF_DEN + rw + (lane >> 2)];
        float inv1 = 1.f / smf[OFF_DEN + rw + 8 + (lane >> 2)];
        int grow0 = s0 + rw + (lane >> 2);
        float* o0 = out + (size_t)grow0 * (NH * HD) + h * HD;
        float* o1 = out + (size_t)(grow0 + 8) * (NH * HD) + h * HD;
        #pragma unroll
        for (int n = 0; n < 32; n++) {
            int col = n * 8 + (lane & 3) * 2;
            *(float2*)(o0 + col) = make_float2(oacc[n][0] * inv0, oacc[n][1] * inv0);
            *(float2*)(o1 + col) = make_float2(oacc[n][2] * inv1, oacc[n][3] * inv1);
        }
    }
}

// ---------------- launch ----------------------------------------------------
extern "C" void kernel_launch(void* const* d_in, const int* in_sizes, int n_in,
                              void* d_out, int out_size)
{
    const float* x   = (const float*)d_in[0];
    const float* fc  = (const float*)d_in[1];
    const float* fs  = (const float*)d_in[2];
    const float* WAq = (const float*)d_in[3];
    const float* WAk = (const float*)d_in[4];
    const float* WAv = (const float*)d_in[5];
    const float* WBq = (const float*)d_in[6];
    const float* WBk = (const float*)d_in[7];
    const float* WBv = (const float*)d_in[8];
    const float* Wo  = (const float*)d_in[9];
    const float* qnw = (const float*)d_in[10];
    const float* knw = (const float*)d_in[11];
    const int*   idx = (const int*)d_in[16];
    float* out = (float*)d_out;

    float *gproj, *gq, *gk, *gv, *gattn;
    __nv_bfloat16 *xhi, *xlo, *wch, *wcl, *woh, *wol, *ah, *al;
    cudaGetSymbolAddress((void**)&gproj, g_proj);
    cudaGetSymbolAddress((void**)&gq,  g_q);
    cudaGetSymbolAddress((void**)&gk,  g_k);
    cudaGetSymbolAddress((void**)&gv,  g_v);
    cudaGetSymbolAddress((void**)&gattn, g_attn);
    cudaGetSymbolAddress((void**)&xhi, g_xhi);
    cudaGetSymbolAddress((void**)&xlo, g_xlo);
    cudaGetSymbolAddress((void**)&wch, g_wcat_hi);
    cudaGetSymbolAddress((void**)&wcl, g_wcat_lo);
    cudaGetSymbolAddress((void**)&woh, g_wo_hi);
    cudaGetSymbolAddress((void**)&wol, g_wo_lo);
    cudaGetSymbolAddress((void**)&ah, g_attnhi);
    cudaGetSymbolAddress((void**)&al, g_attnlo);

    cudaFuncSetAttribute(mma_gemm, cudaFuncAttributeMaxDynamicSharedMemorySize, GEMM_SMEM);
    cudaFuncSetAttribute(attn_mma, cudaFuncAttributeMaxDynamicSharedMemorySize, ATTN_SMEM);

    cudaMemsetAsync(gk, 0, (size_t)S_LEN * KVH * HD * sizeof(float));
    cudaMemsetAsync(gv, 0, (size_t)S_LEN * KVH * HD * sizeof(float));

    {
        int n4 = S_LEN * HID / 4;
        cvt_split<<<(n4 + 255) / 256, 256>>>((const float4*)x,
            (__nv_bfloat162*)xhi, (__nv_bfloat162*)xlo, n4);
    }
    cvt_wcat<<<(NPROJ * HID + 255) / 256, 256>>>(WBq, WBk, WBv, WAq, WAk, WAv, wch, wcl);
    {
        int n4 = HID * HID / 4;
        cvt_split<<<(n4 + 255) / 256, 256>>>((const float4*)Wo,
            (__nv_bfloat162*)woh, (__nv_bfloat162*)wol, n4);
    }

    // single fused projection GEMM: [4096 x 2048] @ [2688 x 2048]^T
    mma_gemm<<<dim3(NPROJ / 128, 32), 256, GEMM_SMEM>>>(xhi, xlo, wch, wcl,
                                                        gproj, S_LEN, NPROJ, HID);

    qkv_kernel<<<S_LEN, 256>>>(gproj, fc, fs, qnw, knw, idx, gq, gk, gv);

    attn_mma<<<dim3(S_LEN / AQ, NH), 256, ATTN_SMEM>>>(gq, gk, gv, idx, gattn);

    {
        int n4 = S_LEN * HID / 4;
        cvt_split<<<(n4 + 255) / 256, 256>>>((const float4*)gattn,
            (__nv_bfloat162*)ah, (__nv_bfloat162*)al, n4);
    }
    mma_gemm<<<dim3(16, 32), 256, GEMM_SMEM>>>(ah, al, woh, wol, out, S_LEN, HID, HID);
}

// round 7
// speedup vs baseline: 4.1729x; 1.1190x over previous
#include <cuda_runtime.h>
#include <cuda_bf16.h>
#include <math.h>
#include <stdint.h>

#define S_LEN 4096
#define HID 2048
#define NH 8
#define KVH 4
#define HD 256
#define QR 6
#define KR 2
#define VR 2
#define WINDOW 1024
#define SOFTCAP 50.0f
#define SCALING 0.0625f
#define EPS 1e-6f
#define NPROJ 2688           // 1536 Bq | 512 Bk | 512 Bv | 64 A | 64 pad

// ---------------- scratch ----------------
__device__ float g_proj[S_LEN * NPROJ];
__device__ __nv_bfloat16 g_qhi[S_LEN * NH * HD];
__device__ __nv_bfloat16 g_qlo[S_LEN * NH * HD];
__device__ __nv_bfloat16 g_khi[S_LEN * KVH * HD];
__device__ __nv_bfloat16 g_klo[S_LEN * KVH * HD];
__device__ float g_v[S_LEN * KVH * HD];
__device__ float g_attn[S_LEN * NH * HD];

__device__ __nv_bfloat16 g_xhi[S_LEN * HID];
__device__ __nv_bfloat16 g_xlo[S_LEN * HID];
__device__ __nv_bfloat16 g_wcat_hi[NPROJ * HID];
__device__ __nv_bfloat16 g_wcat_lo[NPROJ * HID];
__device__ __nv_bfloat16 g_wo_hi[HID * HID];
__device__ __nv_bfloat16 g_wo_lo[HID * HID];
__device__ __nv_bfloat16 g_attnhi[S_LEN * HID];
__device__ __nv_bfloat16 g_attnlo[S_LEN * HID];

// ---------------- helpers ----------------
__device__ __forceinline__ uint32_t smem_u32(const void* p) {
    uint32_t a;
    asm("{ .reg .u64 t; cvta.to.shared.u64 t, %1; cvt.u32.u64 %0, t; }" : "=r"(a) : "l"(p));
    return a;
}

__device__ __forceinline__ float tf32r(float x) {
    uint32_t u;
    asm("cvt.rna.tf32.f32 %0, %1;" : "=r"(u) : "f"(x));
    return __uint_as_float(u);
}
__device__ __forceinline__ uint32_t tf32u(float x) {
    uint32_t u;
    asm("cvt.rna.tf32.f32 %0, %1;" : "=r"(u) : "f"(x));
    return u;
}

#define LDMX4(r0, r1, r2, r3, addr)                                              \
    asm volatile("ldmatrix.sync.aligned.m8n8.x4.shared.b16 {%0,%1,%2,%3}, [%4];" \
                 : "=r"(r0), "=r"(r1), "=r"(r2), "=r"(r3) : "r"(addr))
#define MMA16816(d, a, b)                                                        \
    asm volatile("mma.sync.aligned.m16n8k16.row.col.f32.bf16.bf16.f32 "          \
                 "{%0,%1,%2,%3}, {%4,%5,%6,%7}, {%8,%9}, {%0,%1,%2,%3};"         \
                 : "+f"((d)[0]), "+f"((d)[1]), "+f"((d)[2]), "+f"((d)[3])        \
                 : "r"((a)[0]), "r"((a)[1]), "r"((a)[2]), "r"((a)[3]),           \
                   "r"((b)[0]), "r"((b)[1]))
#define MMAT32(d, a, b)                                                          \
    asm volatile("mma.sync.aligned.m16n8k8.row.col.f32.tf32.tf32.f32 "           \
                 "{%0,%1,%2,%3}, {%4,%5,%6,%7}, {%8,%9}, {%0,%1,%2,%3};"         \
                 : "+f"((d)[0]), "+f"((d)[1]), "+f"((d)[2]), "+f"((d)[3])        \
                 : "r"((a)[0]), "r"((a)[1]), "r"((a)[2]), "r"((a)[3]),           \
                   "r"((b)[0]), "r"((b)[1]))
#define CP_ASYNC16(dst, src)                                                     \
    asm volatile("cp.async.cg.shared.global [%0], [%1], 16;" :: "r"(dst), "l"(src))
#define CP_ASYNC16Z(dst, src, sz)                                                \
    asm volatile("cp.async.cg.shared.global [%0], [%1], 16, %2;"                 \
                 :: "r"(dst), "l"(src), "r"(sz))

// ---------------- bf16x3 GEMM via mma.sync: C = A @ B^T --------------------
#define CK 32
#define ROW_B 80
#define MAT_B (128 * ROW_B)
#define BUF_B (4 * MAT_B)
#define GEMM_SMEM (2 * BUF_B)

__global__ __launch_bounds__(256, 2)
void mma_gemm(const __nv_bfloat16* __restrict__ Ah, const __nv_bfloat16* __restrict__ Al,
              const __nv_bfloat16* __restrict__ Bh, const __nv_bfloat16* __restrict__ Bl,
              float* __restrict__ C, int M, int N, int K)
{
    extern __shared__ char sm[];
    const uint32_t smb = smem_u32(sm);

    const int tid = threadIdx.x;
    const int wid = tid >> 5;
    const int lane = tid & 31;
    const int wm = wid & 3;
    const int wn = wid >> 2;
    const int bm = blockIdx.y;
    const int bn = blockIdx.x;

    const __nv_bfloat16* baseAh = Ah + (size_t)(bm * 128) * K;
    const __nv_bfloat16* baseAl = Al + (size_t)(bm * 128) * K;
    const __nv_bfloat16* baseBh = Bh + (size_t)(bn * 128) * K;
    const __nv_bfloat16* baseBl = Bl + (size_t)(bn * 128) * K;

    float acc[2][8][4];
    #pragma unroll
    for (int mi = 0; mi < 2; mi++)
        #pragma unroll
        for (int ni = 0; ni < 8; ni++)
            #pragma unroll
            for (int j = 0; j < 4; j++) acc[mi][ni][j] = 0.f;

    auto load_chunk = [&](int kb, int b) {
        uint32_t bufb = smb + b * BUF_B;
        #pragma unroll
        for (int it = 0; it < 8; it++) {
            const __nv_bfloat16* base =
                (it < 2) ? baseAh : (it < 4) ? baseAl : (it < 6) ? baseBh : baseBl;
            int idx = ((it & 1) << 8) + tid;
            int r = idx >> 2;
            int c = tid & 3;
            const void* src = base + (size_t)r * K + kb * CK + c * 8;
            uint32_t dst = bufb + (it >> 1) * MAT_B + r * ROW_B + c * 16;
            CP_ASYNC16(dst, src);
        }
        asm volatile("cp.async.commit_group;");
    };

    const int NC = K / CK;
    load_chunk(0, 0);

    for (int i = 0; i < NC; i++) {
        asm volatile("cp.async.wait_group 0;");
        __syncthreads();
        if (i + 1 < NC) load_chunk(i + 1, (i + 1) & 1);

        uint32_t sbase = smb + (i & 1) * BUF_B;
        uint32_t aoff_h = sbase + (wm * 32 + (lane & 15)) * ROW_B + (lane >> 4) * 16;
        uint32_t aoff_l = aoff_h + MAT_B;
        uint32_t bbase_h = sbase + 2 * MAT_B;

        #pragma unroll
        for (int kk = 0; kk < 2; kk++) {
            uint32_t a_h[2][4], a_l[2][4];
            #pragma unroll
            for (int mi = 0; mi < 2; mi++) {
                LDMX4(a_h[mi][0], a_h[mi][1], a_h[mi][2], a_h[mi][3],
                      aoff_h + mi * 16 * ROW_B + kk * 32);
                LDMX4(a_l[mi][0], a_l[mi][1], a_l[mi][2], a_l[mi][3],
                      aoff_l + mi * 16 * ROW_B + kk * 32);
            }
            uint32_t bh[4][4], bl[4][4];
            #pragma unroll
            for (int nip = 0; nip < 4; nip++) {
                uint32_t ab = bbase_h + (wn * 64 + nip * 16 + (lane & 15)) * ROW_B
                            + (lane >> 4) * 16 + kk * 32;
                LDMX4(bh[nip][0], bh[nip][1], bh[nip][2], bh[nip][3], ab);
                LDMX4(bl[nip][0], bl[nip][1], bl[nip][2], bl[nip][3], ab + MAT_B);
            }
            #pragma unroll
            for (int nip = 0; nip < 4; nip++) {
                #pragma unroll
                for (int half = 0; half < 2; half++) {
                    int ni = nip * 2 + half;
                    uint32_t bhf[2] = { bh[nip][half], bh[nip][half + 2] };
                    uint32_t blf[2] = { bl[nip][half], bl[nip][half + 2] };
                    #pragma unroll
                    for (int mi = 0; mi < 2; mi++) {
                        MMA16816(acc[mi][ni], a_h[mi], bhf);
                        MMA16816(acc[mi][ni], a_h[mi], blf);
                        MMA16816(acc[mi][ni], a_l[mi], bhf);
                    }
                }
            }
        }
    }

    #pragma unroll
    for (int mi = 0; mi < 2; mi++) {
        int row0 = bm * 128 + wm * 32 + mi * 16 + (lane >> 2);
        #pragma unroll
        for (int ni = 0; ni < 8; ni++) {
            int col = bn * 128 + wn * 64 + ni * 8 + (lane & 3) * 2;
            *(float2*)(C + (size_t)row0 * N + col) =
                make_float2(acc[mi][ni][0], acc[mi][ni][1]);
            *(float2*)(C + (size_t)(row0 + 8) * N + col) =
                make_float2(acc[mi][ni][2], acc[mi][ni][3]);
        }
    }
}

// ---------------- conversions ----------------
__global__ __launch_bounds__(256) void cvt_split(
    const float4* __restrict__ x, __nv_bfloat162* __restrict__ hi,
    __nv_bfloat162* __restrict__ lo, int n4)
{
    int i = blockIdx.x * 256 + threadIdx.x;
    if (i >= n4) return;
    float4 v = x[i];
    __nv_bfloat16 h0 = __float2bfloat16_rn(v.x);
    __nv_bfloat16 h1 = __float2bfloat16_rn(v.y);
    __nv_bfloat16 h2 = __float2bfloat16_rn(v.z);
    __nv_bfloat16 h3 = __float2bfloat16_rn(v.w);
    hi[2 * i]     = __halves2bfloat162(h0, h1);
    hi[2 * i + 1] = __halves2bfloat162(h2, h3);
    lo[2 * i]     = __halves2bfloat162(
        __float2bfloat16_rn(v.x - __bfloat162float(h0)),
        __float2bfloat16_rn(v.y - __bfloat162float(h1)));
    lo[2 * i + 1] = __halves2bfloat162(
        __float2bfloat16_rn(v.z - __bfloat162float(h2)),
        __float2bfloat16_rn(v.w - __bfloat162float(h3)));
}

__global__ __launch_bounds__(256) void cvt_wcat(
    const float* __restrict__ wbq, const float* __restrict__ wbk,
    const float* __restrict__ wbv, const float* __restrict__ waq,
    const float* __restrict__ wak, const float* __restrict__ wav,
    __nv_bfloat16* __restrict__ hi, __nv_bfloat16* __restrict__ lo)
{
    int i = blockIdx.x * 256 + threadIdx.x;
    if (i >= NPROJ * HID) return;
    int row = i / HID, col = i - row * HID;
    float val = 0.f;
    if (row < 1536)      val = wbq[row * HID + col];
    else if (row < 2048) val = wbk[(row - 1536) * HID + col];
    else if (row < 2560) val = wbv[(row - 2048) * HID + col];
    else if (row < 2608) val = waq[(row - 2560) * HID + col];
    else if (row < 2616) val = wak[(row - 2608) * HID + col];
    else if (row < 2624) val = wav[(row - 2616) * HID + col];
    __nv_bfloat16 h = __float2bfloat16_rn(val);
    hi[i] = h;
    lo[i] = __float2bfloat16_rn(val - __bfloat162float(h));
}

// ---------------- fused RoPE + tensor-product + RMSNorm --------------------
__global__ __launch_bounds__(256) void qkv_kernel(
    const float* __restrict__ proj,
    const float* __restrict__ fcos, const float* __restrict__ fsin,
    const float* __restrict__ qnw, const float* __restrict__ knw,
    const int* __restrict__ idx,
    __nv_bfloat16* __restrict__ qhi, __nv_bfloat16* __restrict__ qlo,
    __nv_bfloat16* __restrict__ khi, __nv_bfloat16* __restrict__ klo,
    float* __restrict__ vo)
{
    int s = blockIdx.x;
    int tid = threadIdx.x;
    int d = tid;
    int warp = tid >> 5, lane = tid & 31;
    const float* row = proj + (size_t)s * NPROJ;

    __shared__ float sA[64];
    __shared__ float red[8][8];
    __shared__ float srstd[8];
    __shared__ float skrstd[4];

    if (tid < 64) sA[tid] = row[2560 + tid];
    __syncthreads();

    float c  = fcos[s * (HD / 2) + (d >> 1)];
    float sn = fsin[s * (HD / 2) + (d >> 1)];
    float seff = (d & 1) ? sn : -sn;

    float bq[QR];
    #pragma unroll
    for (int r = 0; r < QR; r++) {
        float x  = row[r * HD + d];
        float xn = row[r * HD + (d ^ 1)];
        bq[r] = x * c + xn * seff;
    }
    float qraw[NH];
    #pragma unroll
    for (int h = 0; h < NH; h++) {
        float a = 0.f;
        #pragma unroll
        for (int r = 0; r < QR; r++) a += sA[h * QR + r] * bq[r];
        qraw[h] = a * (1.f / QR);
    }
    #pragma unroll
    for (int h = 0; h < NH; h++) {
        float ss = qraw[h] * qraw[h];
        #pragma unroll
        for (int o = 16; o > 0; o >>= 1) ss += __shfl_xor_sync(0xffffffffu, ss, o);
        if (lane == 0) red[warp][h] = ss;
    }
    __syncthreads();
    if (tid < NH) {
        float t = 0.f;
        #pragma unroll
        for (int w = 0; w < 8; w++) t += red[w][tid];
        srstd[tid] = rsqrtf(t * (1.f / HD) + EPS);
    }
    __syncthreads();
    float qw = (1.f + qnw[d]) * SCALING;
    #pragma unroll
    for (int h = 0; h < NH; h++) {
        float qv = qraw[h] * srstd[h] * qw;
        __nv_bfloat16 hh = __float2bfloat16_rn(qv);
        size_t off = ((size_t)s * NH + h) * HD + d;
        qhi[off] = hh;
        qlo[off] = __float2bfloat16_rn(qv - __bfloat162float(hh));
    }

    float bk[KR];
    #pragma unroll
    for (int r = 0; r < KR; r++) {
        float x  = row[1536 + r * HD + d];
        float xn = row[1536 + r * HD + (d ^ 1)];
        bk[r] = x * c + xn * seff;
    }
    float kraw[KVH];
    #pragma unroll
    for (int kh = 0; kh < KVH; kh++)
        kraw[kh] = (sA[48 + kh * KR + 0] * bk[0] + sA[48 + kh * KR + 1] * bk[1]) * 0.5f;

    __syncthreads();
    #pragma unroll
    for (int kh = 0; kh < KVH; kh++) {
        float ss = kraw[kh] * kraw[kh];
        #pragma unroll
        for (int o = 16; o > 0; o >>= 1) ss += __shfl_xor_sync(0xffffffffu, ss, o);
        if (lane == 0) red[warp][kh] = ss;
    }
    __syncthreads();
    if (tid < KVH) {
        float t = 0.f;
        #pragma unroll
        for (int w = 0; w < 8; w++) t += red[w][tid];
        skrstd[tid] = rsqrtf(t * (1.f / HD) + EPS);
    }
    __syncthreads();

    int tpos = idx[s];
    float kw = 1.f + knw[d];
    #pragma unroll
    for (int kh = 0; kh < KVH; kh++) {
        float kv = kraw[kh] * skrstd[kh] * kw;
        __nv_bfloat16 hh = __float2bfloat16_rn(kv);
        size_t off = ((size_t)tpos * KVH + kh) * HD + d;
        khi[off] = hh;
        klo[off] = __float2bfloat16_rn(kv - __bfloat162float(hh));
    }

    float bv0 = row[2048 + 0 * HD + d];
    float bv1 = row[2048 + 1 * HD + d];
    #pragma unroll
    for (int kh = 0; kh < KVH; kh++)
        vo[((size_t)tpos * KVH + kh) * HD + d] =
            tf32r((sA[56 + kh * VR + 0] * bv0 + sA[56 + kh * VR + 1] * bv1) * 0.5f);
}

// ---------------- flash attention: bf16x3 QK + tf32 PV ----------------
// CTA: 64 queries x 1 head; warps 0-3 score, 4-7 PV.
// smem bytes: Khi 2x16896 | Klo 2x16896 | V 2x33792 | P 9216 | den 256
#define AQ 64
#define ACT 32
#define KROWB 528
#define KBUF 16896
#define KLOOFF 33792
#define VOFFB 67584
#define VROWB 1056
#define VBUF 33792
#define POFFB 135168
#define PROWB 144
#define DENF_IDX 36096            // byte 144384 / 4
#define ATTN_SMEM 144640

__global__ __launch_bounds__(256, 1)
void attn_mma(const __nv_bfloat16* __restrict__ qh_, const __nv_bfloat16* __restrict__ ql_,
              const __nv_bfloat16* __restrict__ kh_, const __nv_bfloat16* __restrict__ kl_,
              const float* __restrict__ v, const int* __restrict__ idx,
              float* __restrict__ out)
{
    extern __shared__ float smf[];
    __shared__ int spos[AQ];
    __shared__ int srange[2];

    const int s0 = blockIdx.x * AQ;
    const int h = blockIdx.y;
    const int kvh = h >> 1;
    const int tid = threadIdx.x;
    const int wid = tid >> 5;
    const int lane = tid & 31;

    if (tid < AQ) spos[tid] = idx[s0 + tid];
    __syncthreads();
    if (tid == 0) {
        int mn = spos[0], mx = spos[0];
        for (int i = 1; i < AQ; i++) { mn = min(mn, spos[i]); mx = max(mx, spos[i]); }
        srange[0] = max(0, mn - (WINDOW - 1));
        srange[1] = mx;
    }
    __syncthreads();
    const int kmin = srange[0];
    const int nch = (srange[1] - kmin) / ACT + 1;

    const uint32_t smb = smem_u32(smf);
    const __nv_bfloat16* khbase = kh_ + (size_t)kvh * HD;
    const __nv_bfloat16* klbase = kl_ + (size_t)kvh * HD;
    const float* vbase = v + (size_t)kvh * HD;

    auto load_chunk = [&](int ci, int b) {
        int t0 = kmin + ci * ACT;
        #pragma unroll
        for (int j = 0; j < 4; j++) {               // K hi: 1024 x 16B
            int seg = tid + j * 256;
            int r = seg >> 5;
            int c = seg & 31;
            int t = t0 + r;
            int sz = (t < S_LEN) ? 16 : 0;
            const void* src = khbase + (size_t)t * (KVH * HD) + c * 8;
            CP_ASYNC16Z(smb + b * KBUF + r * KROWB + c * 16, src, sz);
        }
        #pragma unroll
        for (int j = 0; j < 4; j++) {               // K lo
            int seg = tid + j * 256;
            int r = seg >> 5;
            int c = seg & 31;
            int t = t0 + r;
            int sz = (t < S_LEN) ? 16 : 0;
            const void* src = klbase + (size_t)t * (KVH * HD) + c * 8;
            CP_ASYNC16Z(smb + KLOOFF + b * KBUF + r * KROWB + c * 16, src, sz);
        }
        #pragma unroll
        for (int j = 0; j < 8; j++) {               // V fp32: 2048 x 16B
            int seg = tid + j * 256;
            int r = seg >> 6;
            int c = seg & 63;
            int t = t0 + r;
            int sz = (t < S_LEN) ? 16 : 0;
            const void* src = vbase + (size_t)t * (KVH * HD) + c * 4;
            CP_ASYNC16Z(smb + VOFFB + b * VBUF + r * VROWB + c * 16, src, sz);
        }
        asm volatile("cp.async.commit_group;");
    };

    load_chunk(0, 0);

    if (wid < 4) {
        // ---------------- score role (bf16x3 QK) ----------------
        const int rw = wid * 16;
        const int r0 = s0 + rw + (lane >> 2);
        const __nv_bfloat16* q0h = qh_ + ((size_t)r0 * NH + h) * HD;
        const __nv_bfloat16* q1h = qh_ + ((size_t)(r0 + 8) * NH + h) * HD;
        const __nv_bfloat16* q0l = ql_ + ((size_t)r0 * NH + h) * HD;
        const __nv_bfloat16* q1l = ql_ + ((size_t)(r0 + 8) * NH + h) * HD;
        uint32_t qah[16][4], qal[16][4];
        #pragma unroll
        for (int ks = 0; ks < 16; ks++) {
            int c = ks * 16 + 2 * (lane & 3);
            qah[ks][0] = *(const uint32_t*)(q0h + c);
            qah[ks][1] = *(const uint32_t*)(q1h + c);
            qah[ks][2] = *(const uint32_t*)(q0h + c + 8);
            qah[ks][3] = *(const uint32_t*)(q1h + c + 8);
            qal[ks][0] = *(const uint32_t*)(q0l + c);
            qal[ks][1] = *(const uint32_t*)(q1l + c);
            qal[ks][2] = *(const uint32_t*)(q0l + c + 8);
            qal[ks][3] = *(const uint32_t*)(q1l + c + 8);
        }
        const int qp0 = spos[rw + (lane >> 2)];
        const int qp1 = spos[rw + 8 + (lane >> 2)];
        float den0 = 0.f, den1 = 0.f;

        for (int i = 0; i < nch; i++) {
            __syncthreads();                               // B1
            if (i + 1 < nch) {
                load_chunk(i + 1, (i + 1) & 1);
                asm volatile("cp.async.wait_group 1;");
            } else {
                asm volatile("cp.async.wait_group 0;");
            }
            __syncthreads();                               // B2

            const uint32_t skh = smb + (i & 1) * KBUF;
            const uint32_t skl = smb + KLOOFF + (i & 1) * KBUF;
            float sacc[4][4];
            #pragma unroll
            for (int j = 0; j < 4; j++)
                #pragma unroll
                for (int e = 0; e < 4; e++) sacc[j][e] = 0.f;

            #pragma unroll
            for (int ksp = 0; ksp < 8; ksp++) {
                uint32_t kbh[4][4], kbl[4][4];
                #pragma unroll
                for (int j = 0; j < 4; j++) {
                    uint32_t arow = (j * 8 + (lane & 7)) * KROWB + ksp * 64 + (lane >> 3) * 16;
                    LDMX4(kbh[j][0], kbh[j][1], kbh[j][2], kbh[j][3], skh + arow);
                    LDMX4(kbl[j][0], kbl[j][1], kbl[j][2], kbl[j][3], skl + arow);
                }
                #pragma unroll
                for (int j = 0; j < 4; j++) {
                    uint32_t b0h[2] = { kbh[j][0], kbh[j][1] };
                    uint32_t b1h[2] = { kbh[j][2], kbh[j][3] };
                    uint32_t b0l[2] = { kbl[j][0], kbl[j][1] };
                    uint32_t b1l[2] = { kbl[j][2], kbl[j][3] };
                    MMA16816(sacc[j], qah[2 * ksp],     b0h);
                    MMA16816(sacc[j], qah[2 * ksp + 1], b1h);
                    MMA16816(sacc[j], qah[2 * ksp],     b0l);
                    MMA16816(sacc[j], qah[2 * ksp + 1], b1l);
                    MMA16816(sacc[j], qal[2 * ksp],     b0h);
                    MMA16816(sacc[j], qal[2 * ksp + 1], b1h);
                }
            }

            const int t0 = kmin + i * ACT;
            #pragma unroll
            for (int j = 0; j < 4; j++) {
                int tk = t0 + j * 8 + (lane & 3) * 2;
                float p[4];
                #pragma unroll
                for (int e = 0; e < 4; e++) {
                    float s = sacc[j][e];
                    int qp = (e < 2) ? qp0 : qp1;
                    int tt = tk + (e & 1);
                    float x2 = (s * (1.f / SOFTCAP)) * (s * (1.f / SOFTCAP));
                    float r = 1.f + x2 * (-0.333333333f + x2 * (0.133333333f + x2 * -0.053968254f));
                    float pe = __expf(s * r);
                    p[e] = ((unsigned)(qp - tt) < WINDOW) ? pe : 0.f;
                }
                uint32_t u0 = tf32u(p[0]), u1 = tf32u(p[1]);
                uint32_t u2 = tf32u(p[2]), u3 = tf32u(p[3]);
                den0 += __uint_as_float(u0) + __uint_as_float(u1);
                den1 += __uint_as_float(u2) + __uint_as_float(u3);
                uint32_t a0 = smb + POFFB + (rw + (lane >> 2)) * PROWB + (j * 8 + (lane & 3) * 2) * 4;
                uint32_t a1 = a0 + 8 * PROWB;
                asm volatile("st.shared.v2.b32 [%0], {%1,%2};" :: "r"(a0), "r"(u0), "r"(u1));
                asm volatile("st.shared.v2.b32 [%0], {%1,%2};" :: "r"(a1), "r"(u2), "r"(u3));
            }
            __syncthreads();                               // B3
        }
        den0 += __shfl_xor_sync(0xffffffffu, den0, 1);
        den0 += __shfl_xor_sync(0xffffffffu, den0, 2);
        den1 += __shfl_xor_sync(0xffffffffu, den1, 1);
        den1 += __shfl_xor_sync(0xffffffffu, den1, 2);
        if ((lane & 3) == 0) {
            smf[DENF_IDX + rw + (lane >> 2)] = den0;
            smf[DENF_IDX + rw + 8 + (lane >> 2)] = den1;
        }
        __syncthreads();                                   // B4
    } else {
        // ---------------- PV role (tf32) ----------------
        const int rw = (wid - 4) * 16;
        float oacc[32][4];
        #pragma unroll
        for (int n = 0; n < 32; n++)
            #pragma unroll
            for (int e = 0; e < 4; e++) oacc[n][e] = 0.f;

        for (int i = 0; i < nch; i++) {
            __syncthreads();                               // B1
            if (i + 1 < nch) {
                load_chunk(i + 1, (i + 1) & 1);
                asm volatile("cp.async.wait_group 1;");
            } else {
                asm volatile("cp.async.wait_group 0;");
            }
            __syncthreads();                               // B2
            __syncthreads();                               // B3 (P ready)

            const uint32_t svb = smb + VOFFB + (i & 1) * VBUF;
            uint32_t pa[4][4];
            #pragma unroll
            for (int ks = 0; ks < 4; ks++) {
                uint32_t a = smb + POFFB + (rw + (lane >> 2)) * PROWB + (ks * 8 + (lane & 3)) * 4;
                uint32_t a8 = a + 8 * PROWB;
                asm volatile("ld.shared.b32 %0, [%1];" : "=r"(pa[ks][0]) : "r"(a));
                asm volatile("ld.shared.b32 %0, [%1];" : "=r"(pa[ks][1]) : "r"(a8));
                asm volatile("ld.shared.b32 %0, [%1];" : "=r"(pa[ks][2]) : "r"(a + 16));
                asm volatile("ld.shared.b32 %0, [%1];" : "=r"(pa[ks][3]) : "r"(a8 + 16));
            }
            #pragma unroll 8
            for (int n = 0; n < 32; n++) {
                #pragma unroll
                for (int ks = 0; ks < 4; ks++) {
                    uint32_t vb[2];
                    uint32_t a = svb + ((ks * 8 + (lane & 3)) * VROWB) + (n * 8 + (lane >> 2)) * 4;
                    asm volatile("ld.shared.b32 %0, [%1];" : "=r"(vb[0]) : "r"(a));
                    asm volatile("ld.shared.b32 %0, [%1];" : "=r"(vb[1]) : "r"(a + 4 * VROWB));
                    MMAT32(oacc[n], pa[ks], vb);
                }
            }
        }
        __syncthreads();                                   // B4 (den ready)
        float inv0 = 1.f / smf[DENF_IDX + rw + (lane >> 2)];
        float inv1 = 1.f / smf[DENF_IDX + rw + 8 + (lane >> 2)];
        int grow0 = s0 + rw + (lane >> 2);
        float* o0 = out + (size_t)grow0 * (NH * HD) + h * HD;
        float* o1 = out + (size_t)(grow0 + 8) * (NH * HD) + h * HD;
        #pragma unroll
        for (int n = 0; n < 32; n++) {
            int col = n * 8 + (lane & 3) * 2;
            *(float2*)(o0 + col) = make_float2(oacc[n][0] * inv0, oacc[n][1] * inv0);
            *(float2*)(o1 + col) = make_float2(oacc[n][2] * inv1, oacc[n][3] * inv1);
        }
    }
}

// ---------------- launch ----------------------------------------------------
extern "C" void kernel_launch(void* const* d_in, const int* in_sizes, int n_in,
                              void* d_out, int out_size)
{
    const float* x   = (const float*)d_in[0];
    const float* fc  = (const float*)d_in[1];
    const float* fs  = (const float*)d_in[2];
    const float* WAq = (const float*)d_in[3];
    const float* WAk = (const float*)d_in[4];
    const float* WAv = (const float*)d_in[5];
    const float* WBq = (const float*)d_in[6];
    const float* WBk = (const float*)d_in[7];
    const float* WBv = (const float*)d_in[8];
    const float* Wo  = (const float*)d_in[9];
    const float* qnw = (const float*)d_in[10];
    const float* knw = (const float*)d_in[11];
    const int*   idx = (const int*)d_in[16];
    float* out = (float*)d_out;

    float *gproj, *gv, *gattn;
    __nv_bfloat16 *gqh, *gql, *gkh, *gkl;
    __nv_bfloat16 *xhi, *xlo, *wch, *wcl, *woh, *wol, *ah, *al;
    cudaGetSymbolAddress((void**)&gproj, g_proj);
    cudaGetSymbolAddress((void**)&gqh, g_qhi);
    cudaGetSymbolAddress((void**)&gql, g_qlo);
    cudaGetSymbolAddress((void**)&gkh, g_khi);
    cudaGetSymbolAddress((void**)&gkl, g_klo);
    cudaGetSymbolAddress((void**)&gv,  g_v);
    cudaGetSymbolAddress((void**)&gattn, g_attn);
    cudaGetSymbolAddress((void**)&xhi, g_xhi);
    cudaGetSymbolAddress((void**)&xlo, g_xlo);
    cudaGetSymbolAddress((void**)&wch, g_wcat_hi);
    cudaGetSymbolAddress((void**)&wcl, g_wcat_lo);
    cudaGetSymbolAddress((void**)&woh, g_wo_hi);
    cudaGetSymbolAddress((void**)&wol, g_wo_lo);
    cudaGetSymbolAddress((void**)&ah, g_attnhi);
    cudaGetSymbolAddress((void**)&al, g_attnlo);

    cudaFuncSetAttribute(mma_gemm, cudaFuncAttributeMaxDynamicSharedMemorySize, GEMM_SMEM);
    cudaFuncSetAttribute(attn_mma, cudaFuncAttributeMaxDynamicSharedMemorySize, ATTN_SMEM);

    cudaMemsetAsync(gkh, 0, (size_t)S_LEN * KVH * HD * sizeof(__nv_bfloat16));
    cudaMemsetAsync(gkl, 0, (size_t)S_LEN * KVH * HD * sizeof(__nv_bfloat16));
    cudaMemsetAsync(gv, 0, (size_t)S_LEN * KVH * HD * sizeof(float));

    {
        int n4 = S_LEN * HID / 4;
        cvt_split<<<(n4 + 255) / 256, 256>>>((const float4*)x,
            (__nv_bfloat162*)xhi, (__nv_bfloat162*)xlo, n4);
    }
    cvt_wcat<<<(NPROJ * HID + 255) / 256, 256>>>(WBq, WBk, WBv, WAq, WAk, WAv, wch, wcl);
    {
        int n4 = HID * HID / 4;
        cvt_split<<<(n4 + 255) / 256, 256>>>((const float4*)Wo,
            (__nv_bfloat162*)woh, (__nv_bfloat162*)wol, n4);
    }

    mma_gemm<<<dim3(NPROJ / 128, 32), 256, GEMM_SMEM>>>(xhi, xlo, wch, wcl,
                                                        gproj, S_LEN, NPROJ, HID);

    qkv_kernel<<<S_LEN, 256>>>(gproj, fc, fs, qnw, knw, idx,
                               gqh, gql, gkh, gkl, gv);

    attn_mma<<<dim3(S_LEN / AQ, NH), 256, ATTN_SMEM>>>(gqh, gql, gkh, gkl, gv, idx, gattn);

    {
        int n4 = S_LEN * HID / 4;
        cvt_split<<<(n4 + 255) / 256, 256>>>((const float4*)gattn,
            (__nv_bfloat162*)ah, (__nv_bfloat162*)al, n4);
    }
    mma_gemm<<<dim3(16, 32), 256, GEMM_SMEM>>>(ah, al, woh, wol, out, S_LEN, HID, HID);
}

// round 8
// speedup vs baseline: 4.3980x; 1.0540x over previous
#include <cuda_runtime.h>
#include <cuda_bf16.h>
#include <math.h>
#include <stdint.h>

#define S_LEN 4096
#define HID 2048
#define NH 8
#define KVH 4
#define HD 256
#define QR 6
#define KR 2
#define VR 2
#define WINDOW 1024
#define SOFTCAP 50.0f
#define SCALING 0.0625f
#define EPS 1e-6f
#define NPROJ 2688           // 1536 Bq | 512 Bk | 512 Bv | 64 A | 64 pad

// ---------------- scratch ----------------
__device__ float g_proj[S_LEN * NPROJ];
__device__ __nv_bfloat16 g_qhi[S_LEN * NH * HD];
__device__ __nv_bfloat16 g_qlo[S_LEN * NH * HD];
__device__ __nv_bfloat16 g_khi[S_LEN * KVH * HD];
__device__ __nv_bfloat16 g_klo[S_LEN * KVH * HD];
__device__ float g_v[S_LEN * KVH * HD];

__device__ __nv_bfloat16 g_xhi[S_LEN * HID];
__device__ __nv_bfloat16 g_xlo[S_LEN * HID];
__device__ __nv_bfloat16 g_wcat_hi[NPROJ * HID];
__device__ __nv_bfloat16 g_wcat_lo[NPROJ * HID];
__device__ __nv_bfloat16 g_wo_hi[HID * HID];
__device__ __nv_bfloat16 g_wo_lo[HID * HID];
__device__ __nv_bfloat16 g_attnhi[S_LEN * HID];
__device__ __nv_bfloat16 g_attnlo[S_LEN * HID];

// ---------------- helpers ----------------
__device__ __forceinline__ uint32_t smem_u32(const void* p) {
    uint32_t a;
    asm("{ .reg .u64 t; cvta.to.shared.u64 t, %1; cvt.u32.u64 %0, t; }" : "=r"(a) : "l"(p));
    return a;
}

__device__ __forceinline__ float tf32r(float x) {
    uint32_t u;
    asm("cvt.rna.tf32.f32 %0, %1;" : "=r"(u) : "f"(x));
    return __uint_as_float(u);
}
__device__ __forceinline__ uint32_t tf32u(float x) {
    uint32_t u;
    asm("cvt.rna.tf32.f32 %0, %1;" : "=r"(u) : "f"(x));
    return u;
}

#define LDMX4(r0, r1, r2, r3, addr)                                              \
    asm volatile("ldmatrix.sync.aligned.m8n8.x4.shared.b16 {%0,%1,%2,%3}, [%4];" \
                 : "=r"(r0), "=r"(r1), "=r"(r2), "=r"(r3) : "r"(addr))
#define MMA16816(d, a, b)                                                        \
    asm volatile("mma.sync.aligned.m16n8k16.row.col.f32.bf16.bf16.f32 "          \
                 "{%0,%1,%2,%3}, {%4,%5,%6,%7}, {%8,%9}, {%0,%1,%2,%3};"         \
                 : "+f"((d)[0]), "+f"((d)[1]), "+f"((d)[2]), "+f"((d)[3])        \
                 : "r"((a)[0]), "r"((a)[1]), "r"((a)[2]), "r"((a)[3]),           \
                   "r"((b)[0]), "r"((b)[1]))
#define MMAT32(d, a, b)                                                          \
    asm volatile("mma.sync.aligned.m16n8k8.row.col.f32.tf32.tf32.f32 "           \
                 "{%0,%1,%2,%3}, {%4,%5,%6,%7}, {%8,%9}, {%0,%1,%2,%3};"         \
                 : "+f"((d)[0]), "+f"((d)[1]), "+f"((d)[2]), "+f"((d)[3])        \
                 : "r"((a)[0]), "r"((a)[1]), "r"((a)[2]), "r"((a)[3]),           \
                   "r"((b)[0]), "r"((b)[1]))
#define CP_ASYNC16(dst, src)                                                     \
    asm volatile("cp.async.cg.shared.global [%0], [%1], 16;" :: "r"(dst), "l"(src))
#define CP_ASYNC16Z(dst, src, sz)                                                \
    asm volatile("cp.async.cg.shared.global [%0], [%1], 16, %2;"                 \
                 :: "r"(dst), "l"(src), "r"(sz))

// ---------------- bf16x3 GEMM via mma.sync: C = A @ B^T --------------------
#define CK 32
#define ROW_B 80
#define MAT_B (128 * ROW_B)
#define BUF_B (4 * MAT_B)
#define GEMM_SMEM (2 * BUF_B)

__global__ __launch_bounds__(256, 2)
void mma_gemm(const __nv_bfloat16* __restrict__ Ah, const __nv_bfloat16* __restrict__ Al,
              const __nv_bfloat16* __restrict__ Bh, const __nv_bfloat16* __restrict__ Bl,
              float* __restrict__ C, int M, int N, int K)
{
    extern __shared__ char sm[];
    const uint32_t smb = smem_u32(sm);

    const int tid = threadIdx.x;
    const int wid = tid >> 5;
    const int lane = tid & 31;
    const int wm = wid & 3;
    const int wn = wid >> 2;
    const int bm = blockIdx.y;
    const int bn = blockIdx.x;

    const __nv_bfloat16* baseAh = Ah + (size_t)(bm * 128) * K;
    const __nv_bfloat16* baseAl = Al + (size_t)(bm * 128) * K;
    const __nv_bfloat16* baseBh = Bh + (size_t)(bn * 128) * K;
    const __nv_bfloat16* baseBl = Bl + (size_t)(bn * 128) * K;

    float acc[2][8][4];
    #pragma unroll
    for (int mi = 0; mi < 2; mi++)
        #pragma unroll
        for (int ni = 0; ni < 8; ni++)
            #pragma unroll
            for (int j = 0; j < 4; j++) acc[mi][ni][j] = 0.f;

    auto load_chunk = [&](int kb, int b) {
        uint32_t bufb = smb + b * BUF_B;
        #pragma unroll
        for (int it = 0; it < 8; it++) {
            const __nv_bfloat16* base =
                (it < 2) ? baseAh : (it < 4) ? baseAl : (it < 6) ? baseBh : baseBl;
            int idx = ((it & 1) << 8) + tid;
            int r = idx >> 2;
            int c = tid & 3;
            const void* src = base + (size_t)r * K + kb * CK + c * 8;
            uint32_t dst = bufb + (it >> 1) * MAT_B + r * ROW_B + c * 16;
            CP_ASYNC16(dst, src);
        }
        asm volatile("cp.async.commit_group;");
    };

    const int NC = K / CK;
    load_chunk(0, 0);

    for (int i = 0; i < NC; i++) {
        asm volatile("cp.async.wait_group 0;");
        __syncthreads();
        if (i + 1 < NC) load_chunk(i + 1, (i + 1) & 1);

        uint32_t sbase = smb + (i & 1) * BUF_B;
        uint32_t aoff_h = sbase + (wm * 32 + (lane & 15)) * ROW_B + (lane >> 4) * 16;
        uint32_t aoff_l = aoff_h + MAT_B;
        uint32_t bbase_h = sbase + 2 * MAT_B;

        #pragma unroll
        for (int kk = 0; kk < 2; kk++) {
            uint32_t a_h[2][4], a_l[2][4];
            #pragma unroll
            for (int mi = 0; mi < 2; mi++) {
                LDMX4(a_h[mi][0], a_h[mi][1], a_h[mi][2], a_h[mi][3],
                      aoff_h + mi * 16 * ROW_B + kk * 32);
                LDMX4(a_l[mi][0], a_l[mi][1], a_l[mi][2], a_l[mi][3],
                      aoff_l + mi * 16 * ROW_B + kk * 32);
            }
            uint32_t bh[4][4], bl[4][4];
            #pragma unroll
            for (int nip = 0; nip < 4; nip++) {
                uint32_t ab = bbase_h + (wn * 64 + nip * 16 + (lane & 15)) * ROW_B
                            + (lane >> 4) * 16 + kk * 32;
                LDMX4(bh[nip][0], bh[nip][1], bh[nip][2], bh[nip][3], ab);
                LDMX4(bl[nip][0], bl[nip][1], bl[nip][2], bl[nip][3], ab + MAT_B);
            }
            #pragma unroll
            for (int nip = 0; nip < 4; nip++) {
                #pragma unroll
                for (int half = 0; half < 2; half++) {
                    int ni = nip * 2 + half;
                    uint32_t bhf[2] = { bh[nip][half], bh[nip][half + 2] };
                    uint32_t blf[2] = { bl[nip][half], bl[nip][half + 2] };
                    #pragma unroll
                    for (int mi = 0; mi < 2; mi++) {
                        MMA16816(acc[mi][ni], a_h[mi], bhf);
                        MMA16816(acc[mi][ni], a_h[mi], blf);
                        MMA16816(acc[mi][ni], a_l[mi], bhf);
                    }
                }
            }
        }
    }

    #pragma unroll
    for (int mi = 0; mi < 2; mi++) {
        int row0 = bm * 128 + wm * 32 + mi * 16 + (lane >> 2);
        #pragma unroll
        for (int ni = 0; ni < 8; ni++) {
            int col = bn * 128 + wn * 64 + ni * 8 + (lane & 3) * 2;
            *(float2*)(C + (size_t)row0 * N + col) =
                make_float2(acc[mi][ni][0], acc[mi][ni][1]);
            *(float2*)(C + (size_t)(row0 + 8) * N + col) =
                make_float2(acc[mi][ni][2], acc[mi][ni][3]);
        }
    }
}

// ---------------- conversions ----------------
__global__ __launch_bounds__(256) void cvt_split(
    const float4* __restrict__ x, __nv_bfloat162* __restrict__ hi,
    __nv_bfloat162* __restrict__ lo, int n4)
{
    int i = blockIdx.x * 256 + threadIdx.x;
    if (i >= n4) return;
    float4 v = x[i];
    __nv_bfloat16 h0 = __float2bfloat16_rn(v.x);
    __nv_bfloat16 h1 = __float2bfloat16_rn(v.y);
    __nv_bfloat16 h2 = __float2bfloat16_rn(v.z);
    __nv_bfloat16 h3 = __float2bfloat16_rn(v.w);
    hi[2 * i]     = __halves2bfloat162(h0, h1);
    hi[2 * i + 1] = __halves2bfloat162(h2, h3);
    lo[2 * i]     = __halves2bfloat162(
        __float2bfloat16_rn(v.x - __bfloat162float(h0)),
        __float2bfloat16_rn(v.y - __bfloat162float(h1)));
    lo[2 * i + 1] = __halves2bfloat162(
        __float2bfloat16_rn(v.z - __bfloat162float(h2)),
        __float2bfloat16_rn(v.w - __bfloat162float(h3)));
}

__global__ __launch_bounds__(256) void cvt_wcat(
    const float* __restrict__ wbq, const float* __restrict__ wbk,
    const float* __restrict__ wbv, const float* __restrict__ waq,
    const float* __restrict__ wak, const float* __restrict__ wav,
    __nv_bfloat16* __restrict__ hi, __nv_bfloat16* __restrict__ lo)
{
    int i = blockIdx.x * 256 + threadIdx.x;
    if (i >= NPROJ * HID) return;
    int row = i / HID, col = i - row * HID;
    float val = 0.f;
    if (row < 1536)      val = wbq[row * HID + col];
    else if (row < 2048) val = wbk[(row - 1536) * HID + col];
    else if (row < 2560) val = wbv[(row - 2048) * HID + col];
    else if (row < 2608) val = waq[(row - 2560) * HID + col];
    else if (row < 2616) val = wak[(row - 2608) * HID + col];
    else if (row < 2624) val = wav[(row - 2616) * HID + col];
    __nv_bfloat16 h = __float2bfloat16_rn(val);
    hi[i] = h;
    lo[i] = __float2bfloat16_rn(val - __bfloat162float(h));
}

// ---------------- fused RoPE + tensor-product + RMSNorm --------------------
__global__ __launch_bounds__(256) void qkv_kernel(
    const float* __restrict__ proj,
    const float* __restrict__ fcos, const float* __restrict__ fsin,
    const float* __restrict__ qnw, const float* __restrict__ knw,
    const int* __restrict__ idx,
    __nv_bfloat16* __restrict__ qhi, __nv_bfloat16* __restrict__ qlo,
    __nv_bfloat16* __restrict__ khi, __nv_bfloat16* __restrict__ klo,
    float* __restrict__ vo)
{
    int s = blockIdx.x;
    int tid = threadIdx.x;
    int d = tid;
    int warp = tid >> 5, lane = tid & 31;
    const float* row = proj + (size_t)s * NPROJ;

    __shared__ float sA[64];
    __shared__ float red[8][8];
    __shared__ float srstd[8];
    __shared__ float skrstd[4];

    if (tid < 64) sA[tid] = row[2560 + tid];
    __syncthreads();

    float c  = fcos[s * (HD / 2) + (d >> 1)];
    float sn = fsin[s * (HD / 2) + (d >> 1)];
    float seff = (d & 1) ? sn : -sn;

    float bq[QR];
    #pragma unroll
    for (int r = 0; r < QR; r++) {
        float x  = row[r * HD + d];
        float xn = row[r * HD + (d ^ 1)];
        bq[r] = x * c + xn * seff;
    }
    float qraw[NH];
    #pragma unroll
    for (int h = 0; h < NH; h++) {
        float a = 0.f;
        #pragma unroll
        for (int r = 0; r < QR; r++) a += sA[h * QR + r] * bq[r];
        qraw[h] = a * (1.f / QR);
    }
    #pragma unroll
    for (int h = 0; h < NH; h++) {
        float ss = qraw[h] * qraw[h];
        #pragma unroll
        for (int o = 16; o > 0; o >>= 1) ss += __shfl_xor_sync(0xffffffffu, ss, o);
        if (lane == 0) red[warp][h] = ss;
    }
    __syncthreads();
    if (tid < NH) {
        float t = 0.f;
        #pragma unroll
        for (int w = 0; w < 8; w++) t += red[w][tid];
        srstd[tid] = rsqrtf(t * (1.f / HD) + EPS);
    }
    __syncthreads();
    float qw = (1.f + qnw[d]) * SCALING;
    #pragma unroll
    for (int h = 0; h < NH; h++) {
        float qv = qraw[h] * srstd[h] * qw;
        __nv_bfloat16 hh = __float2bfloat16_rn(qv);
        size_t off = ((size_t)s * NH + h) * HD + d;
        qhi[off] = hh;
        qlo[off] = __float2bfloat16_rn(qv - __bfloat162float(hh));
    }

    float bk[KR];
    #pragma unroll
    for (int r = 0; r < KR; r++) {
        float x  = row[1536 + r * HD + d];
        float xn = row[1536 + r * HD + (d ^ 1)];
        bk[r] = x * c + xn * seff;
    }
    float kraw[KVH];
    #pragma unroll
    for (int kh = 0; kh < KVH; kh++)
        kraw[kh] = (sA[48 + kh * KR + 0] * bk[0] + sA[48 + kh * KR + 1] * bk[1]) * 0.5f;

    __syncthreads();
    #pragma unroll
    for (int kh = 0; kh < KVH; kh++) {
        float ss = kraw[kh] * kraw[kh];
        #pragma unroll
        for (int o = 16; o > 0; o >>= 1) ss += __shfl_xor_sync(0xffffffffu, ss, o);
        if (lane == 0) red[warp][kh] = ss;
    }
    __syncthreads();
    if (tid < KVH) {
        float t = 0.f;
        #pragma unroll
        for (int w = 0; w < 8; w++) t += red[w][tid];
        skrstd[tid] = rsqrtf(t * (1.f / HD) + EPS);
    }
    __syncthreads();

    int tpos = idx[s];
    float kw = 1.f + knw[d];
    #pragma unroll
    for (int kh = 0; kh < KVH; kh++) {
        float kv = kraw[kh] * skrstd[kh] * kw;
        __nv_bfloat16 hh = __float2bfloat16_rn(kv);
        size_t off = ((size_t)tpos * KVH + kh) * HD + d;
        khi[off] = hh;
        klo[off] = __float2bfloat16_rn(kv - __bfloat162float(hh));
    }

    float bv0 = row[2048 + 0 * HD + d];
    float bv1 = row[2048 + 1 * HD + d];
    #pragma unroll
    for (int kh = 0; kh < KVH; kh++)
        vo[((size_t)tpos * KVH + kh) * HD + d] =
            tf32r((sA[56 + kh * VR + 0] * bv0 + sA[56 + kh * VR + 1] * bv1) * 0.5f);
}

// ---------------- flash attention: bf16x3 QK + tf32 PV, skewed pipeline ----
// CTA: 64 queries x 1 head; warps 0-3 score (chunk i), 4-7 PV (chunk i-1).
// smem bytes: Khi 2x16896 | Klo 2x16896 | V 3x33792 | P 2x9216 | den 256
#define AQ 64
#define ACT 32
#define KROWB 528
#define KBUF 16896
#define KLOOFF 33792
#define VOFFB 67584
#define VROWB 1056
#define VBUF 33792
#define POFFB 168960
#define PBUF 9216
#define PROWB 144
#define DENF_IDX 46848            // byte 187392 / 4
#define ATTN_SMEM 187648

__global__ __launch_bounds__(256, 1)
void attn_mma(const __nv_bfloat16* __restrict__ qh_, const __nv_bfloat16* __restrict__ ql_,
              const __nv_bfloat16* __restrict__ kh_, const __nv_bfloat16* __restrict__ kl_,
              const float* __restrict__ v, const int* __restrict__ idx,
              __nv_bfloat16* __restrict__ outh, __nv_bfloat16* __restrict__ outl)
{
    extern __shared__ float smf[];
    __shared__ int spos[AQ];
    __shared__ int srange[2];

    const int s0 = blockIdx.x * AQ;
    const int h = blockIdx.y;
    const int kvh = h >> 1;
    const int tid = threadIdx.x;
    const int wid = tid >> 5;
    const int lane = tid & 31;

    if (tid < AQ) spos[tid] = idx[s0 + tid];
    __syncthreads();
    if (tid == 0) {
        int mn = spos[0], mx = spos[0];
        for (int i = 1; i < AQ; i++) { mn = min(mn, spos[i]); mx = max(mx, spos[i]); }
        srange[0] = max(0, mn - (WINDOW - 1));
        srange[1] = mx;
    }
    __syncthreads();
    const int kmin = srange[0];
    const int nch = (srange[1] - kmin) / ACT + 1;

    const uint32_t smb = smem_u32(smf);
    const __nv_bfloat16* khbase = kh_ + (size_t)kvh * HD;
    const __nv_bfloat16* klbase = kl_ + (size_t)kvh * HD;
    const float* vbase = v + (size_t)kvh * HD;

    // load chunk ci: K into buf ci&1, V into buf ci%3
    auto load_chunk = [&](int ci) {
        int t0 = kmin + ci * ACT;
        int kb = ci & 1;
        int vb = ci % 3;
        #pragma unroll
        for (int j = 0; j < 4; j++) {               // K hi
            int seg = tid + j * 256;
            int r = seg >> 5;
            int c = seg & 31;
            int t = t0 + r;
            int sz = (t < S_LEN) ? 16 : 0;
            const void* src = khbase + (size_t)t * (KVH * HD) + c * 8;
            CP_ASYNC16Z(smb + kb * KBUF + r * KROWB + c * 16, src, sz);
        }
        #pragma unroll
        for (int j = 0; j < 4; j++) {               // K lo
            int seg = tid + j * 256;
            int r = seg >> 5;
            int c = seg & 31;
            int t = t0 + r;
            int sz = (t < S_LEN) ? 16 : 0;
            const void* src = klbase + (size_t)t * (KVH * HD) + c * 8;
            CP_ASYNC16Z(smb + KLOOFF + kb * KBUF + r * KROWB + c * 16, src, sz);
        }
        #pragma unroll
        for (int j = 0; j < 8; j++) {               // V fp32
            int seg = tid + j * 256;
            int r = seg >> 6;
            int c = seg & 63;
            int t = t0 + r;
            int sz = (t < S_LEN) ? 16 : 0;
            const void* src = vbase + (size_t)t * (KVH * HD) + c * 4;
            CP_ASYNC16Z(smb + VOFFB + vb * VBUF + r * VROWB + c * 16, src, sz);
        }
        asm volatile("cp.async.commit_group;");
    };

    load_chunk(0);

    if (wid < 4) {
        // ---------------- score role: QK chunk i (bf16x3) ----------------
        const int rw = wid * 16;
        const int r0 = s0 + rw + (lane >> 2);
        const __nv_bfloat16* q0h = qh_ + ((size_t)r0 * NH + h) * HD;
        const __nv_bfloat16* q1h = qh_ + ((size_t)(r0 + 8) * NH + h) * HD;
        const __nv_bfloat16* q0l = ql_ + ((size_t)r0 * NH + h) * HD;
        const __nv_bfloat16* q1l = ql_ + ((size_t)(r0 + 8) * NH + h) * HD;
        uint32_t qah[16][4], qal[16][4];
        #pragma unroll
        for (int ks = 0; ks < 16; ks++) {
            int c = ks * 16 + 2 * (lane & 3);
            qah[ks][0] = *(const uint32_t*)(q0h + c);
            qah[ks][1] = *(const uint32_t*)(q1h + c);
            qah[ks][2] = *(const uint32_t*)(q0h + c + 8);
            qah[ks][3] = *(const uint32_t*)(q1h + c + 8);
            qal[ks][0] = *(const uint32_t*)(q0l + c);
            qal[ks][1] = *(const uint32_t*)(q1l + c);
            qal[ks][2] = *(const uint32_t*)(q0l + c + 8);
            qal[ks][3] = *(const uint32_t*)(q1l + c + 8);
        }
        const int qp0 = spos[rw + (lane >> 2)];
        const int qp1 = spos[rw + 8 + (lane >> 2)];
        float den0 = 0.f, den1 = 0.f;

        for (int i = 0; i < nch; i++) {
            __syncthreads();                               // A: buffers free, P_{i-1} visible
            if (i + 1 < nch) {
                load_chunk(i + 1);
                asm volatile("cp.async.wait_group 1;");
            } else {
                asm volatile("cp.async.wait_group 0;");
            }
            __syncthreads();                               // B: chunk i visible

            const uint32_t skh = smb + (i & 1) * KBUF;
            const uint32_t skl = smb + KLOOFF + (i & 1) * KBUF;
            float sacc[4][4];
            #pragma unroll
            for (int j = 0; j < 4; j++)
                #pragma unroll
                for (int e = 0; e < 4; e++) sacc[j][e] = 0.f;

            #pragma unroll
            for (int ksp = 0; ksp < 8; ksp++) {
                uint32_t kbh[4][4], kbl[4][4];
                #pragma unroll
                for (int j = 0; j < 4; j++) {
                    uint32_t arow = (j * 8 + (lane & 7)) * KROWB + ksp * 64 + (lane >> 3) * 16;
                    LDMX4(kbh[j][0], kbh[j][1], kbh[j][2], kbh[j][3], skh + arow);
                    LDMX4(kbl[j][0], kbl[j][1], kbl[j][2], kbl[j][3], skl + arow);
                }
                #pragma unroll
                for (int j = 0; j < 4; j++) {
                    uint32_t b0h[2] = { kbh[j][0], kbh[j][1] };
                    uint32_t b1h[2] = { kbh[j][2], kbh[j][3] };
                    uint32_t b0l[2] = { kbl[j][0], kbl[j][1] };
                    uint32_t b1l[2] = { kbl[j][2], kbl[j][3] };
                    MMA16816(sacc[j], qah[2 * ksp],     b0h);
                    MMA16816(sacc[j], qah[2 * ksp + 1], b1h);
                    MMA16816(sacc[j], qah[2 * ksp],     b0l);
                    MMA16816(sacc[j], qah[2 * ksp + 1], b1l);
                    MMA16816(sacc[j], qal[2 * ksp],     b0h);
                    MMA16816(sacc[j], qal[2 * ksp + 1], b1h);
                }
            }

            const int t0 = kmin + i * ACT;
            const uint32_t pbb = smb + POFFB + (i & 1) * PBUF;
            #pragma unroll
            for (int j = 0; j < 4; j++) {
                int tk = t0 + j * 8 + (lane & 3) * 2;
                float p[4];
                #pragma unroll
                for (int e = 0; e < 4; e++) {
                    float s = sacc[j][e];
                    int qp = (e < 2) ? qp0 : qp1;
                    int tt = tk + (e & 1);
                    float x2 = (s * (1.f / SOFTCAP)) * (s * (1.f / SOFTCAP));
                    float r = 1.f + x2 * (-0.333333333f + x2 * (0.133333333f + x2 * -0.053968254f));
                    float pe = __expf(s * r);
                    p[e] = ((unsigned)(qp - tt) < WINDOW) ? pe : 0.f;
                }
                uint32_t u0 = tf32u(p[0]), u1 = tf32u(p[1]);
                uint32_t u2 = tf32u(p[2]), u3 = tf32u(p[3]);
                den0 += __uint_as_float(u0) + __uint_as_float(u1);
                den1 += __uint_as_float(u2) + __uint_as_float(u3);
                uint32_t a0 = pbb + (rw + (lane >> 2)) * PROWB + (j * 8 + (lane & 3) * 2) * 4;
                uint32_t a1 = a0 + 8 * PROWB;
                asm volatile("st.shared.v2.b32 [%0], {%1,%2};" :: "r"(a0), "r"(u0), "r"(u1));
                asm volatile("st.shared.v2.b32 [%0], {%1,%2};" :: "r"(a1), "r"(u2), "r"(u3));
            }
        }
        __syncthreads();                                   // C: last P visible
        den0 += __shfl_xor_sync(0xffffffffu, den0, 1);
        den0 += __shfl_xor_sync(0xffffffffu, den0, 2);
        den1 += __shfl_xor_sync(0xffffffffu, den1, 1);
        den1 += __shfl_xor_sync(0xffffffffu, den1, 2);
        if ((lane & 3) == 0) {
            smf[DENF_IDX + rw + (lane >> 2)] = den0;
            smf[DENF_IDX + rw + 8 + (lane >> 2)] = den1;
        }
        __syncthreads();                                   // D: den ready
    } else {
        // ---------------- PV role: chunk i-1 (tf32) ----------------
        const int rw = (wid - 4) * 16;
        float oacc[32][4];
        #pragma unroll
        for (int n = 0; n < 32; n++)
            #pragma unroll
            for (int e = 0; e < 4; e++) oacc[n][e] = 0.f;

        auto pv_compute = [&](int ci) {
            const uint32_t svb = smb + VOFFB + (ci % 3) * VBUF;
            const uint32_t pbb = smb + POFFB + (ci & 1) * PBUF;
            uint32_t pa[4][4];
            #pragma unroll
            for (int ks = 0; ks < 4; ks++) {
                uint32_t a = pbb + (rw + (lane >> 2)) * PROWB + (ks * 8 + (lane & 3)) * 4;
                uint32_t a8 = a + 8 * PROWB;
                asm volatile("ld.shared.b32 %0, [%1];" : "=r"(pa[ks][0]) : "r"(a));
                asm volatile("ld.shared.b32 %0, [%1];" : "=r"(pa[ks][1]) : "r"(a8));
                asm volatile("ld.shared.b32 %0, [%1];" : "=r"(pa[ks][2]) : "r"(a + 16));
                asm volatile("ld.shared.b32 %0, [%1];" : "=r"(pa[ks][3]) : "r"(a8 + 16));
            }
            #pragma unroll 8
            for (int n = 0; n < 32; n++) {
                #pragma unroll
                for (int ks = 0; ks < 4; ks++) {
                    uint32_t vb[2];
                    uint32_t a = svb + ((ks * 8 + (lane & 3)) * VROWB) + (n * 8 + (lane >> 2)) * 4;
                    asm volatile("ld.shared.b32 %0, [%1];" : "=r"(vb[0]) : "r"(a));
                    asm volatile("ld.shared.b32 %0, [%1];" : "=r"(vb[1]) : "r"(a + 4 * VROWB));
                    MMAT32(oacc[n], pa[ks], vb);
                }
            }
        };

        for (int i = 0; i < nch; i++) {
            __syncthreads();                               // A
            if (i + 1 < nch) {
                load_chunk(i + 1);
                asm volatile("cp.async.wait_group 1;");
            } else {
                asm volatile("cp.async.wait_group 0;");
            }
            __syncthreads();                               // B
            if (i > 0) pv_compute(i - 1);
        }
        __syncthreads();                                   // C: P_{nch-1} visible
        pv_compute(nch - 1);
        __syncthreads();                                   // D: den ready
        float inv0 = 1.f / smf[DENF_IDX + rw + (lane >> 2)];
        float inv1 = 1.f / smf[DENF_IDX + rw + 8 + (lane >> 2)];
        int grow0 = s0 + rw + (lane >> 2);
        __nv_bfloat16* oh0 = outh + (size_t)grow0 * HID + h * HD;
        __nv_bfloat16* oh1 = outh + (size_t)(grow0 + 8) * HID + h * HD;
        __nv_bfloat16* ol0 = outl + (size_t)grow0 * HID + h * HD;
        __nv_bfloat16* ol1 = outl + (size_t)(grow0 + 8) * HID + h * HD;
        #pragma unroll
        for (int n = 0; n < 32; n++) {
            int col = n * 8 + (lane & 3) * 2;
            float v00 = oacc[n][0] * inv0, v01 = oacc[n][1] * inv0;
            float v10 = oacc[n][2] * inv1, v11 = oacc[n][3] * inv1;
            __nv_bfloat16 h00 = __float2bfloat16_rn(v00), h01 = __float2bfloat16_rn(v01);
            __nv_bfloat16 h10 = __float2bfloat16_rn(v10), h11 = __float2bfloat16_rn(v11);
            *(__nv_bfloat162*)(oh0 + col) = __halves2bfloat162(h00, h01);
            *(__nv_bfloat162*)(oh1 + col) = __halves2bfloat162(h10, h11);
            *(__nv_bfloat162*)(ol0 + col) = __halves2bfloat162(
                __float2bfloat16_rn(v00 - __bfloat162float(h00)),
                __float2bfloat16_rn(v01 - __bfloat162float(h01)));
            *(__nv_bfloat162*)(ol1 + col) = __halves2bfloat162(
                __float2bfloat16_rn(v10 - __bfloat162float(h10)),
                __float2bfloat16_rn(v11 - __bfloat162float(h11)));
        }
    }
}

// ---------------- launch ----------------------------------------------------
extern "C" void kernel_launch(void* const* d_in, const int* in_sizes, int n_in,
                              void* d_out, int out_size)
{
    const float* x   = (const float*)d_in[0];
    const float* fc  = (const float*)d_in[1];
    const float* fs  = (const float*)d_in[2];
    const float* WAq = (const float*)d_in[3];
    const float* WAk = (const float*)d_in[4];
    const float* WAv = (const float*)d_in[5];
    const float* WBq = (const float*)d_in[6];
    const float* WBk = (const float*)d_in[7];
    const float* WBv = (const float*)d_in[8];
    const float* Wo  = (const float*)d_in[9];
    const float* qnw = (const float*)d_in[10];
    const float* knw = (const float*)d_in[11];
    const int*   idx = (const int*)d_in[16];
    float* out = (float*)d_out;

    float *gproj, *gv;
    __nv_bfloat16 *gqh, *gql, *gkh, *gkl;
    __nv_bfloat16 *xhi, *xlo, *wch, *wcl, *woh, *wol, *ah, *al;
    cudaGetSymbolAddress((void**)&gproj, g_proj);
    cudaGetSymbolAddress((void**)&gqh, g_qhi);
    cudaGetSymbolAddress((void**)&gql, g_qlo);
    cudaGetSymbolAddress((void**)&gkh, g_khi);
    cudaGetSymbolAddress((void**)&gkl, g_klo);
    cudaGetSymbolAddress((void**)&gv,  g_v);
    cudaGetSymbolAddress((void**)&xhi, g_xhi);
    cudaGetSymbolAddress((void**)&xlo, g_xlo);
    cudaGetSymbolAddress((void**)&wch, g_wcat_hi);
    cudaGetSymbolAddress((void**)&wcl, g_wcat_lo);
    cudaGetSymbolAddress((void**)&woh, g_wo_hi);
    cudaGetSymbolAddress((void**)&wol, g_wo_lo);
    cudaGetSymbolAddress((void**)&ah, g_attnhi);
    cudaGetSymbolAddress((void**)&al, g_attnlo);

    cudaFuncSetAttribute(mma_gemm, cudaFuncAttributeMaxDynamicSharedMemorySize, GEMM_SMEM);
    cudaFuncSetAttribute(attn_mma, cudaFuncAttributeMaxDynamicSharedMemorySize, ATTN_SMEM);

    cudaMemsetAsync(gkh, 0, (size_t)S_LEN * KVH * HD * sizeof(__nv_bfloat16));
    cudaMemsetAsync(gkl, 0, (size_t)S_LEN * KVH * HD * sizeof(__nv_bfloat16));
    cudaMemsetAsync(gv, 0, (size_t)S_LEN * KVH * HD * sizeof(float));

    {
        int n4 = S_LEN * HID / 4;
        cvt_split<<<(n4 + 255) / 256, 256>>>((const float4*)x,
            (__nv_bfloat162*)xhi, (__nv_bfloat162*)xlo, n4);
    }
    cvt_wcat<<<(NPROJ * HID + 255) / 256, 256>>>(WBq, WBk, WBv, WAq, WAk, WAv, wch, wcl);
    {
        int n4 = HID * HID / 4;
        cvt_split<<<(n4 + 255) / 256, 256>>>((const float4*)Wo,
            (__nv_bfloat162*)woh, (__nv_bfloat162*)wol, n4);
    }

    mma_gemm<<<dim3(NPROJ / 128, 32), 256, GEMM_SMEM>>>(xhi, xlo, wch, wcl,
                                                        gproj, S_LEN, NPROJ, HID);

    qkv_kernel<<<S_LEN, 256>>>(gproj, fc, fs, qnw, knw, idx,
                               gqh, gql, gkh, gkl, gv);

    attn_mma<<<dim3(S_LEN / AQ, NH), 256, ATTN_SMEM>>>(gqh, gql, gkh, gkl, gv, idx, ah, al);

    mma_gemm<<<dim3(16, 32), 256, GEMM_SMEM>>>(ah, al, woh, wol, out, S_LEN, HID, HID);
}

// round 9
// speedup vs baseline: 5.4915x; 1.2486x over previous
#include <cuda_runtime.h>
#include <cuda_bf16.h>
#include <cuda_fp16.h>
#include <math.h>
#include <stdint.h>

#define S_LEN 4096
#define HID 2048
#define NH 8
#define KVH 4
#define HD 256
#define QR 6
#define KR 2
#define VR 2
#define WINDOW 1024
#define SOFTCAP 50.0f
#define SCALING 0.0625f
#define EPS 1e-6f
#define NPROJ 2688           // 1536 Bq | 512 Bk | 512 Bv | 64 A | 64 pad

// ---------------- scratch ----------------
__device__ float g_proj[S_LEN * NPROJ];
__device__ __nv_bfloat16 g_qhi[S_LEN * NH * HD];
__device__ __nv_bfloat16 g_qlo[S_LEN * NH * HD];
__device__ __nv_bfloat16 g_khi[S_LEN * KVH * HD];
__device__ __nv_bfloat16 g_klo[S_LEN * KVH * HD];
__device__ float g_v[S_LEN * KVH * HD];

__device__ __half g_xhi[S_LEN * HID];
__device__ __half g_xlo[S_LEN * HID];
__device__ __half g_wcat[NPROJ * HID];
__device__ __half g_wo[HID * HID];
__device__ __half g_attnhi[S_LEN * HID];
__device__ __half g_attnlo[S_LEN * HID];

// ---------------- helpers ----------------
__device__ __forceinline__ uint32_t smem_u32(const void* p) {
    uint32_t a;
    asm("{ .reg .u64 t; cvta.to.shared.u64 t, %1; cvt.u32.u64 %0, t; }" : "=r"(a) : "l"(p));
    return a;
}

__device__ __forceinline__ float tf32r(float x) {
    uint32_t u;
    asm("cvt.rna.tf32.f32 %0, %1;" : "=r"(u) : "f"(x));
    return __uint_as_float(u);
}
__device__ __forceinline__ uint32_t tf32u(float x) {
    uint32_t u;
    asm("cvt.rna.tf32.f32 %0, %1;" : "=r"(u) : "f"(x));
    return u;
}

#define LDMX4(r0, r1, r2, r3, addr)                                              \
    asm volatile("ldmatrix.sync.aligned.m8n8.x4.shared.b16 {%0,%1,%2,%3}, [%4];" \
                 : "=r"(r0), "=r"(r1), "=r"(r2), "=r"(r3) : "r"(addr))
#define MMAF16(d, a, b)                                                          \
    asm volatile("mma.sync.aligned.m16n8k16.row.col.f32.f16.f16.f32 "            \
                 "{%0,%1,%2,%3}, {%4,%5,%6,%7}, {%8,%9}, {%0,%1,%2,%3};"         \
                 : "+f"((d)[0]), "+f"((d)[1]), "+f"((d)[2]), "+f"((d)[3])        \
                 : "r"((a)[0]), "r"((a)[1]), "r"((a)[2]), "r"((a)[3]),           \
                   "r"((b)[0]), "r"((b)[1]))
#define MMA16816(d, a, b)                                                        \
    asm volatile("mma.sync.aligned.m16n8k16.row.col.f32.bf16.bf16.f32 "          \
                 "{%0,%1,%2,%3}, {%4,%5,%6,%7}, {%8,%9}, {%0,%1,%2,%3};"         \
                 : "+f"((d)[0]), "+f"((d)[1]), "+f"((d)[2]), "+f"((d)[3])        \
                 : "r"((a)[0]), "r"((a)[1]), "r"((a)[2]), "r"((a)[3]),           \
                   "r"((b)[0]), "r"((b)[1]))
#define MMAT32(d, a, b)                                                          \
    asm volatile("mma.sync.aligned.m16n8k8.row.col.f32.tf32.tf32.f32 "           \
                 "{%0,%1,%2,%3}, {%4,%5,%6,%7}, {%8,%9}, {%0,%1,%2,%3};"         \
                 : "+f"((d)[0]), "+f"((d)[1]), "+f"((d)[2]), "+f"((d)[3])        \
                 : "r"((a)[0]), "r"((a)[1]), "r"((a)[2]), "r"((a)[3]),           \
                   "r"((b)[0]), "r"((b)[1]))
#define CP_ASYNC16(dst, src)                                                     \
    asm volatile("cp.async.cg.shared.global [%0], [%1], 16;" :: "r"(dst), "l"(src))
#define CP_ASYNC16Z(dst, src, sz)                                                \
    asm volatile("cp.async.cg.shared.global [%0], [%1], 16, %2;"                 \
                 :: "r"(dst), "l"(src), "r"(sz))

// ---------------- fp16x2 GEMM via mma.sync: C = (Ah+Al) @ B^T ---------------
// A split fp16 hi/lo, B single fp16. CTA 128x128, 8 warps 32x64, CK=64.
#define CK 64
#define ROW_B 144                 // 128B data + 16B pad
#define MAT_B (128 * ROW_B)       // 18432
#define BUF_B (3 * MAT_B)         // 55296 (Ah | Al | B)
#define GEMM_SMEM (2 * BUF_B)     // 110592 -> 2 CTAs/SM

__global__ __launch_bounds__(256, 2)
void mma_gemm(const __half* __restrict__ Ah, const __half* __restrict__ Al,
              const __half* __restrict__ B,
              float* __restrict__ C, int M, int N, int K)
{
    extern __shared__ char sm[];
    const uint32_t smb = smem_u32(sm);

    const int tid = threadIdx.x;
    const int wid = tid >> 5;
    const int lane = tid & 31;
    const int wm = wid & 3;
    const int wn = wid >> 2;
    const int bm = blockIdx.y;
    const int bn = blockIdx.x;

    const __half* baseAh = Ah + (size_t)(bm * 128) * K;
    const __half* baseAl = Al + (size_t)(bm * 128) * K;
    const __half* baseB  = B  + (size_t)(bn * 128) * K;

    float acc[2][8][4];
    #pragma unroll
    for (int mi = 0; mi < 2; mi++)
        #pragma unroll
        for (int ni = 0; ni < 8; ni++)
            #pragma unroll
            for (int j = 0; j < 4; j++) acc[mi][ni][j] = 0.f;

    // chunk: 3 matrices x 128 rows x 128B
    auto load_chunk = [&](int kb, int b) {
        uint32_t bufb = smb + b * BUF_B;
        #pragma unroll
        for (int it = 0; it < 12; it++) {
            const __half* base = (it < 4) ? baseAh : (it < 8) ? baseAl : baseB;
            int idx = ((it & 3) << 8) + tid;     // 0..1023
            int r = idx >> 3;
            int c = idx & 7;
            const void* src = base + (size_t)r * K + kb * CK + c * 8;
            uint32_t dst = bufb + (it >> 2) * MAT_B + r * ROW_B + c * 16;
            CP_ASYNC16(dst, src);
        }
        asm volatile("cp.async.commit_group;");
    };

    const int NC = K / CK;
    load_chunk(0, 0);

    for (int i = 0; i < NC; i++) {
        asm volatile("cp.async.wait_group 0;");
        __syncthreads();
        if (i + 1 < NC) load_chunk(i + 1, (i + 1) & 1);

        uint32_t sbase = smb + (i & 1) * BUF_B;
        uint32_t aoff = sbase + (wm * 32 + (lane & 15)) * ROW_B + (lane >> 4) * 16;
        uint32_t bbase = sbase + 2 * MAT_B;

        #pragma unroll
        for (int kk = 0; kk < 4; kk++) {
            uint32_t a_h[2][4], a_l[2][4];
            #pragma unroll
            for (int mi = 0; mi < 2; mi++) {
                LDMX4(a_h[mi][0], a_h[mi][1], a_h[mi][2], a_h[mi][3],
                      aoff + mi * 16 * ROW_B + kk * 32);
                LDMX4(a_l[mi][0], a_l[mi][1], a_l[mi][2], a_l[mi][3],
                      aoff + MAT_B + mi * 16 * ROW_B + kk * 32);
            }
            uint32_t bf[4][4];
            #pragma unroll
            for (int nip = 0; nip < 4; nip++) {
                LDMX4(bf[nip][0], bf[nip][1], bf[nip][2], bf[nip][3],
                      bbase + (wn * 64 + nip * 16 + (lane & 15)) * ROW_B
                            + (lane >> 4) * 16 + kk * 32);
            }
            #pragma unroll
            for (int nip = 0; nip < 4; nip++) {
                #pragma unroll
                for (int half = 0; half < 2; half++) {
                    int ni = nip * 2 + half;
                    uint32_t bb[2] = { bf[nip][half], bf[nip][half + 2] };
                    #pragma unroll
                    for (int mi = 0; mi < 2; mi++) {
                        MMAF16(acc[mi][ni], a_h[mi], bb);
                        MMAF16(acc[mi][ni], a_l[mi], bb);
                    }
                }
            }
        }
    }

    #pragma unroll
    for (int mi = 0; mi < 2; mi++) {
        int row0 = bm * 128 + wm * 32 + mi * 16 + (lane >> 2);
        #pragma unroll
        for (int ni = 0; ni < 8; ni++) {
            int col = bn * 128 + wn * 64 + ni * 8 + (lane & 3) * 2;
            *(float2*)(C + (size_t)row0 * N + col) =
                make_float2(acc[mi][ni][0], acc[mi][ni][1]);
            *(float2*)(C + (size_t)(row0 + 8) * N + col) =
                make_float2(acc[mi][ni][2], acc[mi][ni][3]);
        }
    }
}

// ---------------- conversions ----------------
// fp32 -> fp16 hi/lo split
__global__ __launch_bounds__(256) void cvt_split_h(
    const float4* __restrict__ x, __half2* __restrict__ hi,
    __half2* __restrict__ lo, int n4)
{
    int i = blockIdx.x * 256 + threadIdx.x;
    if (i >= n4) return;
    float4 v = x[i];
    __half h0 = __float2half_rn(v.x);
    __half h1 = __float2half_rn(v.y);
    __half h2 = __float2half_rn(v.z);
    __half h3 = __float2half_rn(v.w);
    hi[2 * i]     = __halves2half2(h0, h1);
    hi[2 * i + 1] = __halves2half2(h2, h3);
    lo[2 * i]     = __halves2half2(
        __float2half_rn(v.x - __half2float(h0)),
        __float2half_rn(v.y - __half2float(h1)));
    lo[2 * i + 1] = __halves2half2(
        __float2half_rn(v.z - __half2float(h2)),
        __float2half_rn(v.w - __half2float(h3)));
}

// concat projection weights -> single fp16 [NPROJ, HID]
__global__ __launch_bounds__(256) void cvt_wcat_h(
    const float* __restrict__ wbq, const float* __restrict__ wbk,
    const float* __restrict__ wbv, const float* __restrict__ waq,
    const float* __restrict__ wak, const float* __restrict__ wav,
    __half* __restrict__ w)
{
    int i = blockIdx.x * 256 + threadIdx.x;
    if (i >= NPROJ * HID) return;
    int row = i / HID, col = i - row * HID;
    float val = 0.f;
    if (row < 1536)      val = wbq[row * HID + col];
    else if (row < 2048) val = wbk[(row - 1536) * HID + col];
    else if (row < 2560) val = wbv[(row - 2048) * HID + col];
    else if (row < 2608) val = waq[(row - 2560) * HID + col];
    else if (row < 2616) val = wak[(row - 2608) * HID + col];
    else if (row < 2624) val = wav[(row - 2616) * HID + col];
    w[i] = __float2half_rn(val);
}

__global__ __launch_bounds__(256) void cvt_h(
    const float4* __restrict__ x, __half2* __restrict__ w, int n4)
{
    int i = blockIdx.x * 256 + threadIdx.x;
    if (i >= n4) return;
    float4 v = x[i];
    w[2 * i]     = __halves2half2(__float2half_rn(v.x), __float2half_rn(v.y));
    w[2 * i + 1] = __halves2half2(__float2half_rn(v.z), __float2half_rn(v.w));
}

// ---------------- fused RoPE + tensor-product + RMSNorm --------------------
__global__ __launch_bounds__(256) void qkv_kernel(
    const float* __restrict__ proj,
    const float* __restrict__ fcos, const float* __restrict__ fsin,
    const float* __restrict__ qnw, const float* __restrict__ knw,
    const int* __restrict__ idx,
    __nv_bfloat16* __restrict__ qhi, __nv_bfloat16* __restrict__ qlo,
    __nv_bfloat16* __restrict__ khi, __nv_bfloat16* __restrict__ klo,
    float* __restrict__ vo)
{
    int s = blockIdx.x;
    int tid = threadIdx.x;
    int d = tid;
    int warp = tid >> 5, lane = tid & 31;
    const float* row = proj + (size_t)s * NPROJ;

    __shared__ float sA[64];
    __shared__ float red[8][8];
    __shared__ float srstd[8];
    __shared__ float skrstd[4];

    if (tid < 64) sA[tid] = row[2560 + tid];
    __syncthreads();

    float c  = fcos[s * (HD / 2) + (d >> 1)];
    float sn = fsin[s * (HD / 2) + (d >> 1)];
    float seff = (d & 1) ? sn : -sn;

    float bq[QR];
    #pragma unroll
    for (int r = 0; r < QR; r++) {
        float x  = row[r * HD + d];
        float xn = row[r * HD + (d ^ 1)];
        bq[r] = x * c + xn * seff;
    }
    float qraw[NH];
    #pragma unroll
    for (int h = 0; h < NH; h++) {
        float a = 0.f;
        #pragma unroll
        for (int r = 0; r < QR; r++) a += sA[h * QR + r] * bq[r];
        qraw[h] = a * (1.f / QR);
    }
    #pragma unroll
    for (int h = 0; h < NH; h++) {
        float ss = qraw[h] * qraw[h];
        #pragma unroll
        for (int o = 16; o > 0; o >>= 1) ss += __shfl_xor_sync(0xffffffffu, ss, o);
        if (lane == 0) red[warp][h] = ss;
    }
    __syncthreads();
    if (tid < NH) {
        float t = 0.f;
        #pragma unroll
        for (int w = 0; w < 8; w++) t += red[w][tid];
        srstd[tid] = rsqrtf(t * (1.f / HD) + EPS);
    }
    __syncthreads();
    float qw = (1.f + qnw[d]) * SCALING;
    #pragma unroll
    for (int h = 0; h < NH; h++) {
        float qv = qraw[h] * srstd[h] * qw;
        __nv_bfloat16 hh = __float2bfloat16_rn(qv);
        size_t off = ((size_t)s * NH + h) * HD + d;
        qhi[off] = hh;
        qlo[off] = __float2bfloat16_rn(qv - __bfloat162float(hh));
    }

    float bk[KR];
    #pragma unroll
    for (int r = 0; r < KR; r++) {
        float x  = row[1536 + r * HD + d];
        float xn = row[1536 + r * HD + (d ^ 1)];
        bk[r] = x * c + xn * seff;
    }
    float kraw[KVH];
    #pragma unroll
    for (int kh = 0; kh < KVH; kh++)
        kraw[kh] = (sA[48 + kh * KR + 0] * bk[0] + sA[48 + kh * KR + 1] * bk[1]) * 0.5f;

    __syncthreads();
    #pragma unroll
    for (int kh = 0; kh < KVH; kh++) {
        float ss = kraw[kh] * kraw[kh];
        #pragma unroll
        for (int o = 16; o > 0; o >>= 1) ss += __shfl_xor_sync(0xffffffffu, ss, o);
        if (lane == 0) red[warp][kh] = ss;
    }
    __syncthreads();
    if (tid < KVH) {
        float t = 0.f;
        #pragma unroll
        for (int w = 0; w < 8; w++) t += red[w][tid];
        skrstd[tid] = rsqrtf(t * (1.f / HD) + EPS);
    }
    __syncthreads();

    int tpos = idx[s];
    float kw = 1.f + knw[d];
    #pragma unroll
    for (int kh = 0; kh < KVH; kh++) {
        float kv = kraw[kh] * skrstd[kh] * kw;
        __nv_bfloat16 hh = __float2bfloat16_rn(kv);
        size_t off = ((size_t)tpos * KVH + kh) * HD + d;
        khi[off] = hh;
        klo[off] = __float2bfloat16_rn(kv - __bfloat162float(hh));
    }

    float bv0 = row[2048 + 0 * HD + d];
    float bv1 = row[2048 + 1 * HD + d];
    #pragma unroll
    for (int kh = 0; kh < KVH; kh++)
        vo[((size_t)tpos * KVH + kh) * HD + d] =
            tf32r((sA[56 + kh * VR + 0] * bv0 + sA[56 + kh * VR + 1] * bv1) * 0.5f);
}

// ---------------- flash attention: bf16x3 QK + tf32 PV, skewed pipeline ----
#define AQ 64
#define ACT 32
#define KROWB 528
#define KBUF 16896
#define KLOOFF 33792
#define VOFFB 67584
#define VROWB 1056
#define VBUF 33792
#define POFFB 168960
#define PBUF 9216
#define PROWB 144
#define DENF_IDX 46848
#define ATTN_SMEM 187648

__global__ __launch_bounds__(256, 1)
void attn_mma(const __nv_bfloat16* __restrict__ qh_, const __nv_bfloat16* __restrict__ ql_,
              const __nv_bfloat16* __restrict__ kh_, const __nv_bfloat16* __restrict__ kl_,
              const float* __restrict__ v, const int* __restrict__ idx,
              __half* __restrict__ outh, __half* __restrict__ outl)
{
    extern __shared__ float smf[];
    __shared__ int spos[AQ];
    __shared__ int srange[2];

    const int s0 = blockIdx.x * AQ;
    const int h = blockIdx.y;
    const int kvh = h >> 1;
    const int tid = threadIdx.x;
    const int wid = tid >> 5;
    const int lane = tid & 31;

    if (tid < AQ) spos[tid] = idx[s0 + tid];
    __syncthreads();
    if (tid == 0) {
        int mn = spos[0], mx = spos[0];
        for (int i = 1; i < AQ; i++) { mn = min(mn, spos[i]); mx = max(mx, spos[i]); }
        srange[0] = max(0, mn - (WINDOW - 1));
        srange[1] = mx;
    }
    __syncthreads();
    const int kmin = srange[0];
    const int nch = (srange[1] - kmin) / ACT + 1;

    const uint32_t smb = smem_u32(smf);
    const __nv_bfloat16* khbase = kh_ + (size_t)kvh * HD;
    const __nv_bfloat16* klbase = kl_ + (size_t)kvh * HD;
    const float* vbase = v + (size_t)kvh * HD;

    auto load_chunk = [&](int ci) {
        int t0 = kmin + ci * ACT;
        int kb = ci & 1;
        int vb = ci % 3;
        #pragma unroll
        for (int j = 0; j < 4; j++) {
            int seg = tid + j * 256;
            int r = seg >> 5;
            int c = seg & 31;
            int t = t0 + r;
            int sz = (t < S_LEN) ? 16 : 0;
            const void* src = khbase + (size_t)t * (KVH * HD) + c * 8;
            CP_ASYNC16Z(smb + kb * KBUF + r * KROWB + c * 16, src, sz);
        }
        #pragma unroll
        for (int j = 0; j < 4; j++) {
            int seg = tid + j * 256;
            int r = seg >> 5;
            int c = seg & 31;
            int t = t0 + r;
            int sz = (t < S_LEN) ? 16 : 0;
            const void* src = klbase + (size_t)t * (KVH * HD) + c * 8;
            CP_ASYNC16Z(smb + KLOOFF + kb * KBUF + r * KROWB + c * 16, src, sz);
        }
        #pragma unroll
        for (int j = 0; j < 8; j++) {
            int seg = tid + j * 256;
            int r = seg >> 6;
            int c = seg & 63;
            int t = t0 + r;
            int sz = (t < S_LEN) ? 16 : 0;
            const void* src = vbase + (size_t)t * (KVH * HD) + c * 4;
            CP_ASYNC16Z(smb + VOFFB + vb * VBUF + r * VROWB + c * 16, src, sz);
        }
        asm volatile("cp.async.commit_group;");
    };

    load_chunk(0);

    if (wid < 4) {
        const int rw = wid * 16;
        const int r0 = s0 + rw + (lane >> 2);
        const __nv_bfloat16* q0h = qh_ + ((size_t)r0 * NH + h) * HD;
        const __nv_bfloat16* q1h = qh_ + ((size_t)(r0 + 8) * NH + h) * HD;
        const __nv_bfloat16* q0l = ql_ + ((size_t)r0 * NH + h) * HD;
        const __nv_bfloat16* q1l = ql_ + ((size_t)(r0 + 8) * NH + h) * HD;
        uint32_t qah[16][4], qal[16][4];
        #pragma unroll
        for (int ks = 0; ks < 16; ks++) {
            int c = ks * 16 + 2 * (lane & 3);
            qah[ks][0] = *(const uint32_t*)(q0h + c);
            qah[ks][1] = *(const uint32_t*)(q1h + c);
            qah[ks][2] = *(const uint32_t*)(q0h + c + 8);
            qah[ks][3] = *(const uint32_t*)(q1h + c + 8);
            qal[ks][0] = *(const uint32_t*)(q0l + c);
            qal[ks][1] = *(const uint32_t*)(q1l + c);
            qal[ks][2] = *(const uint32_t*)(q0l + c + 8);
            qal[ks][3] = *(const uint32_t*)(q1l + c + 8);
        }
        const int qp0 = spos[rw + (lane >> 2)];
        const int qp1 = spos[rw + 8 + (lane >> 2)];
        float den0 = 0.f, den1 = 0.f;

        for (int i = 0; i < nch; i++) {
            __syncthreads();                               // A
            if (i + 1 < nch) {
                load_chunk(i + 1);
                asm volatile("cp.async.wait_group 1;");
            } else {
                asm volatile("cp.async.wait_group 0;");
            }
            __syncthreads();                               // B

            const uint32_t skh = smb + (i & 1) * KBUF;
            const uint32_t skl = smb + KLOOFF + (i & 1) * KBUF;
            float sacc[4][4];
            #pragma unroll
            for (int j = 0; j < 4; j++)
                #pragma unroll
                for (int e = 0; e < 4; e++) sacc[j][e] = 0.f;

            #pragma unroll
            for (int ksp = 0; ksp < 8; ksp++) {
                uint32_t kbh[4][4], kbl[4][4];
                #pragma unroll
                for (int j = 0; j < 4; j++) {
                    uint32_t arow = (j * 8 + (lane & 7)) * KROWB + ksp * 64 + (lane >> 3) * 16;
                    LDMX4(kbh[j][0], kbh[j][1], kbh[j][2], kbh[j][3], skh + arow);
                    LDMX4(kbl[j][0], kbl[j][1], kbl[j][2], kbl[j][3], skl + arow);
                }
                #pragma unroll
                for (int j = 0; j < 4; j++) {
                    uint32_t b0h[2] = { kbh[j][0], kbh[j][1] };
                    uint32_t b1h[2] = { kbh[j][2], kbh[j][3] };
                    uint32_t b0l[2] = { kbl[j][0], kbl[j][1] };
                    uint32_t b1l[2] = { kbl[j][2], kbl[j][3] };
                    MMA16816(sacc[j], qah[2 * ksp],     b0h);
                    MMA16816(sacc[j], qah[2 * ksp + 1], b1h);
                    MMA16816(sacc[j], qah[2 * ksp],     b0l);
                    MMA16816(sacc[j], qah[2 * ksp + 1], b1l);
                    MMA16816(sacc[j], qal[2 * ksp],     b0h);
                    MMA16816(sacc[j], qal[2 * ksp + 1], b1h);
                }
            }

            const int t0 = kmin + i * ACT;
            const uint32_t pbb = smb + POFFB + (i & 1) * PBUF;
            #pragma unroll
            for (int j = 0; j < 4; j++) {
                int tk = t0 + j * 8 + (lane & 3) * 2;
                float p[4];
                #pragma unroll
                for (int e = 0; e < 4; e++) {
                    float s = sacc[j][e];
                    int qp = (e < 2) ? qp0 : qp1;
                    int tt = tk + (e & 1);
                    float x2 = (s * (1.f / SOFTCAP)) * (s * (1.f / SOFTCAP));
                    float r = 1.f + x2 * (-0.333333333f + x2 * (0.133333333f + x2 * -0.053968254f));
                    float pe = __expf(s * r);
                    p[e] = ((unsigned)(qp - tt) < WINDOW) ? pe : 0.f;
                }
                uint32_t u0 = tf32u(p[0]), u1 = tf32u(p[1]);
                uint32_t u2 = tf32u(p[2]), u3 = tf32u(p[3]);
                den0 += __uint_as_float(u0) + __uint_as_float(u1);
                den1 += __uint_as_float(u2) + __uint_as_float(u3);
                uint32_t a0 = pbb + (rw + (lane >> 2)) * PROWB + (j * 8 + (lane & 3) * 2) * 4;
                uint32_t a1 = a0 + 8 * PROWB;
                asm volatile("st.shared.v2.b32 [%0], {%1,%2};" :: "r"(a0), "r"(u0), "r"(u1));
                asm volatile("st.shared.v2.b32 [%0], {%1,%2};" :: "r"(a1), "r"(u2), "r"(u3));
            }
        }
        __syncthreads();                                   // C
        den0 += __shfl_xor_sync(0xffffffffu, den0, 1);
        den0 += __shfl_xor_sync(0xffffffffu, den0, 2);
        den1 += __shfl_xor_sync(0xffffffffu, den1, 1);
        den1 += __shfl_xor_sync(0xffffffffu, den1, 2);
        if ((lane & 3) == 0) {
            smf[DENF_IDX + rw + (lane >> 2)] = den0;
            smf[DENF_IDX + rw + 8 + (lane >> 2)] = den1;
        }
        __syncthreads();                                   // D
    } else {
        const int rw = (wid - 4) * 16;
        float oacc[32][4];
        #pragma unroll
        for (int n = 0; n < 32; n++)
            #pragma unroll
            for (int e = 0; e < 4; e++) oacc[n][e] = 0.f;

        auto pv_compute = [&](int ci) {
            const uint32_t svb = smb + VOFFB + (ci % 3) * VBUF;
            const uint32_t pbb = smb + POFFB + (ci & 1) * PBUF;
            uint32_t pa[4][4];
            #pragma unroll
            for (int ks = 0; ks < 4; ks++) {
                uint32_t a = pbb + (rw + (lane >> 2)) * PROWB + (ks * 8 + (lane & 3)) * 4;
                uint32_t a8 = a + 8 * PROWB;
                asm volatile("ld.shared.b32 %0, [%1];" : "=r"(pa[ks][0]) : "r"(a));
                asm volatile("ld.shared.b32 %0, [%1];" : "=r"(pa[ks][1]) : "r"(a8));
                asm volatile("ld.shared.b32 %0, [%1];" : "=r"(pa[ks][2]) : "r"(a + 16));
                asm volatile("ld.shared.b32 %0, [%1];" : "=r"(pa[ks][3]) : "r"(a8 + 16));
            }
            #pragma unroll 8
            for (int n = 0; n < 32; n++) {
                #pragma unroll
                for (int ks = 0; ks < 4; ks++) {
                    uint32_t vb[2];
                    uint32_t a = svb + ((ks * 8 + (lane & 3)) * VROWB) + (n * 8 + (lane >> 2)) * 4;
                    asm volatile("ld.shared.b32 %0, [%1];" : "=r"(vb[0]) : "r"(a));
                    asm volatile("ld.shared.b32 %0, [%1];" : "=r"(vb[1]) : "r"(a + 4 * VROWB));
                    MMAT32(oacc[n], pa[ks], vb);
                }
            }
        };

        for (int i = 0; i < nch; i++) {
            __syncthreads();                               // A
            if (i + 1 < nch) {
                load_chunk(i + 1);
                asm volatile("cp.async.wait_group 1;");
            } else {
                asm volatile("cp.async.wait_group 0;");
            }
            __syncthreads();                               // B
            if (i > 0) pv_compute(i - 1);
        }
        __syncthreads();                                   // C
        pv_compute(nch - 1);
        __syncthreads();                                   // D
        float inv0 = 1.f / smf[DENF_IDX + rw + (lane >> 2)];
        float inv1 = 1.f / smf[DENF_IDX + rw + 8 + (lane >> 2)];
        int grow0 = s0 + rw + (lane >> 2);
        __half* oh0 = outh + (size_t)grow0 * HID + h * HD;
        __half* oh1 = outh + (size_t)(grow0 + 8) * HID + h * HD;
        __half* ol0 = outl + (size_t)grow0 * HID + h * HD;
        __half* ol1 = outl + (size_t)(grow0 + 8) * HID + h * HD;
        #pragma unroll
        for (int n = 0; n < 32; n++) {
            int col = n * 8 + (lane & 3) * 2;
            float v00 = oacc[n][0] * inv0, v01 = oacc[n][1] * inv0;
            float v10 = oacc[n][2] * inv1, v11 = oacc[n][3] * inv1;
            __half h00 = __float2half_rn(v00), h01 = __float2half_rn(v01);
            __half h10 = __float2half_rn(v10), h11 = __float2half_rn(v11);
            *(__half2*)(oh0 + col) = __halves2half2(h00, h01);
            *(__half2*)(oh1 + col) = __halves2half2(h10, h11);
            *(__half2*)(ol0 + col) = __halves2half2(
                __float2half_rn(v00 - __half2float(h00)),
                __float2half_rn(v01 - __half2float(h01)));
            *(__half2*)(ol1 + col) = __halves2half2(
                __float2half_rn(v10 - __half2float(h10)),
                __float2half_rn(v11 - __half2float(h11)));
        }
    }
}

// ---------------- launch ----------------------------------------------------
extern "C" void kernel_launch(void* const* d_in, const int* in_sizes, int n_in,
                              void* d_out, int out_size)
{
    const float* x   = (const float*)d_in[0];
    const float* fc  = (const float*)d_in[1];
    const float* fs  = (const float*)d_in[2];
    const float* WAq = (const float*)d_in[3];
    const float* WAk = (const float*)d_in[4];
    const float* WAv = (const float*)d_in[5];
    const float* WBq = (const float*)d_in[6];
    const float* WBk = (const float*)d_in[7];
    const float* WBv = (const float*)d_in[8];
    const float* Wo  = (const float*)d_in[9];
    const float* qnw = (const float*)d_in[10];
    const float* knw = (const float*)d_in[11];
    const int*   idx = (const int*)d_in[16];
    float* out = (float*)d_out;

    float *gproj, *gv;
    __nv_bfloat16 *gqh, *gql, *gkh, *gkl;
    __half *xhi, *xlo, *wcat, *wo, *ah, *al;
    cudaGetSymbolAddress((void**)&gproj, g_proj);
    cudaGetSymbolAddress((void**)&gqh, g_qhi);
    cudaGetSymbolAddress((void**)&gql, g_qlo);
    cudaGetSymbolAddress((void**)&gkh, g_khi);
    cudaGetSymbolAddress((void**)&gkl, g_klo);
    cudaGetSymbolAddress((void**)&gv,  g_v);
    cudaGetSymbolAddress((void**)&xhi, g_xhi);
    cudaGetSymbolAddress((void**)&xlo, g_xlo);
    cudaGetSymbolAddress((void**)&wcat, g_wcat);
    cudaGetSymbolAddress((void**)&wo, g_wo);
    cudaGetSymbolAddress((void**)&ah, g_attnhi);
    cudaGetSymbolAddress((void**)&al, g_attnlo);

    cudaFuncSetAttribute(mma_gemm, cudaFuncAttributeMaxDynamicSharedMemorySize, GEMM_SMEM);
    cudaFuncSetAttribute(attn_mma, cudaFuncAttributeMaxDynamicSharedMemorySize, ATTN_SMEM);

    cudaMemsetAsync(gkh, 0, (size_t)S_LEN * KVH * HD * sizeof(__nv_bfloat16));
    cudaMemsetAsync(gkl, 0, (size_t)S_LEN * KVH * HD * sizeof(__nv_bfloat16));
    cudaMemsetAsync(gv, 0, (size_t)S_LEN * KVH * HD * sizeof(float));

    {
        int n4 = S_LEN * HID / 4;
        cvt_split_h<<<(n4 + 255) / 256, 256>>>((const float4*)x,
            (__half2*)xhi, (__half2*)xlo, n4);
    }
    cvt_wcat_h<<<(NPROJ * HID + 255) / 256, 256>>>(WBq, WBk, WBv, WAq, WAk, WAv, wcat);
    {
        int n4 = HID * HID / 4;
        cvt_h<<<(n4 + 255) / 256, 256>>>((const float4*)Wo, (__half2*)wo, n4);
    }

    // projection GEMM: [4096 x 2048] @ [2688 x 2048]^T, fp16x2
    mma_gemm<<<dim3(NPROJ / 128, 32), 256, GEMM_SMEM>>>(xhi, xlo, wcat,
                                                        gproj, S_LEN, NPROJ, HID);

    qkv_kernel<<<S_LEN, 256>>>(gproj, fc, fs, qnw, knw, idx,
                               gqh, gql, gkh, gkl, gv);

    attn_mma<<<dim3(S_LEN / AQ, NH), 256, ATTN_SMEM>>>(gqh, gql, gkh, gkl, gv, idx, ah, al);

    // output GEMM: [4096 x 2048] @ [2048 x 2048]^T, fp16x2
    mma_gemm<<<dim3(16, 32), 256, GEMM_SMEM>>>(ah, al, wo, out, S_LEN, HID, HID);
}

// round 12
// speedup vs baseline: 6.6923x; 1.2187x over previous
#include <cuda_runtime.h>
#include <cuda_bf16.h>
#include <cuda_fp16.h>
#include <math.h>
#include <stdint.h>

#define S_LEN 4096
#define HID 2048
#define NH 8
#define KVH 4
#define HD 256
#define QR 6
#define KR 2
#define VR 2
#define WINDOW 1024
#define SOFTCAP 50.0f
#define SCALING 0.0625f
#define EPS 1e-6f
#define NPROJ 2688
#define PSHIFT 8.0f

// ---------------- scratch ----------------
__device__ float g_proj[S_LEN * NPROJ];
__device__ __nv_bfloat16 g_qhi[S_LEN * NH * HD];
__device__ __nv_bfloat16 g_qlo[S_LEN * NH * HD];
__device__ __nv_bfloat16 g_khi[S_LEN * KVH * HD];
__device__ __nv_bfloat16 g_klo[S_LEN * KVH * HD];
__device__ __half g_v[S_LEN * KVH * HD];

__device__ __half g_xhi[S_LEN * HID];
__device__ __half g_xlo[S_LEN * HID];
__device__ __half g_wcat[NPROJ * HID];
__device__ __half g_wo[HID * HID];
__device__ __half g_attnhi[S_LEN * HID];
__device__ __half g_attnlo[S_LEN * HID];

// ---------------- helpers ----------------
__device__ __forceinline__ uint32_t smem_u32(const void* p) {
    uint32_t a;
    asm("{ .reg .u64 t; cvta.to.shared.u64 t, %1; cvt.u32.u64 %0, t; }" : "=r"(a) : "l"(p));
    return a;
}

#define LDMX4(r0, r1, r2, r3, addr)                                              \
    asm volatile("ldmatrix.sync.aligned.m8n8.x4.shared.b16 {%0,%1,%2,%3}, [%4];" \
                 : "=r"(r0), "=r"(r1), "=r"(r2), "=r"(r3) : "r"(addr))
#define LDMX4T(r0, r1, r2, r3, addr)                                             \
    asm volatile("ldmatrix.sync.aligned.m8n8.x4.trans.shared.b16 {%0,%1,%2,%3}, [%4];" \
                 : "=r"(r0), "=r"(r1), "=r"(r2), "=r"(r3) : "r"(addr))
#define MMAF16(d, a, b)                                                          \
    asm volatile("mma.sync.aligned.m16n8k16.row.col.f32.f16.f16.f32 "            \
                 "{%0,%1,%2,%3}, {%4,%5,%6,%7}, {%8,%9}, {%0,%1,%2,%3};"         \
                 : "+f"((d)[0]), "+f"((d)[1]), "+f"((d)[2]), "+f"((d)[3])        \
                 : "r"((a)[0]), "r"((a)[1]), "r"((a)[2]), "r"((a)[3]),           \
                   "r"((b)[0]), "r"((b)[1]))
#define MMABF16(d, a, b)                                                         \
    asm volatile("mma.sync.aligned.m16n8k16.row.col.f32.bf16.bf16.f32 "          \
                 "{%0,%1,%2,%3}, {%4,%5,%6,%7}, {%8,%9}, {%0,%1,%2,%3};"         \
                 : "+f"((d)[0]), "+f"((d)[1]), "+f"((d)[2]), "+f"((d)[3])        \
                 : "r"((a)[0]), "r"((a)[1]), "r"((a)[2]), "r"((a)[3]),           \
                   "r"((b)[0]), "r"((b)[1]))
#define CP_ASYNC16(dst, src)                                                     \
    asm volatile("cp.async.cg.shared.global [%0], [%1], 16;" :: "r"(dst), "l"(src))
#define CP_ASYNC16Z(dst, src, sz)                                                \
    asm volatile("cp.async.cg.shared.global [%0], [%1], 16, %2;"                 \
                 :: "r"(dst), "l"(src), "r"(sz))

// ---------------- fp16x2 GEMM via mma.sync: C = (Ah+Al) @ B^T ---------------
#define CK 64
#define ROW_B 144
#define MAT_B (128 * ROW_B)
#define BUF_B (3 * MAT_B)
#define GEMM_SMEM (2 * BUF_B)

__global__ __launch_bounds__(256, 2)
void mma_gemm(const __half* __restrict__ Ah, const __half* __restrict__ Al,
              const __half* __restrict__ B,
              float* __restrict__ C, int M, int N, int K)
{
    extern __shared__ char sm[];
    const uint32_t smb = smem_u32(sm);

    const int tid = threadIdx.x;
    const int wid = tid >> 5;
    const int lane = tid & 31;
    const int wm = wid & 3;
    const int wn = wid >> 2;
    const int bm = blockIdx.y;
    const int bn = blockIdx.x;

    const __half* baseAh = Ah + (size_t)(bm * 128) * K;
    const __half* baseAl = Al + (size_t)(bm * 128) * K;
    const __half* baseB  = B  + (size_t)(bn * 128) * K;

    float acc[2][8][4];
    #pragma unroll
    for (int mi = 0; mi < 2; mi++)
        #pragma unroll
        for (int ni = 0; ni < 8; ni++)
            #pragma unroll
            for (int j = 0; j < 4; j++) acc[mi][ni][j] = 0.f;

    auto load_chunk = [&](int kb, int b) {
        uint32_t bufb = smb + b * BUF_B;
        #pragma unroll
        for (int it = 0; it < 12; it++) {
            const __half* base = (it < 4) ? baseAh : (it < 8) ? baseAl : baseB;
            int idx = ((it & 3) << 8) + tid;
            int r = idx >> 3;
            int c = idx & 7;
            const void* src = base + (size_t)r * K + kb * CK + c * 8;
            uint32_t dst = bufb + (it >> 2) * MAT_B + r * ROW_B + c * 16;
            CP_ASYNC16(dst, src);
        }
        asm volatile("cp.async.commit_group;");
    };

    const int NC = K / CK;
    load_chunk(0, 0);

    for (int i = 0; i < NC; i++) {
        asm volatile("cp.async.wait_group 0;");
        __syncthreads();
        if (i + 1 < NC) load_chunk(i + 1, (i + 1) & 1);

        uint32_t sbase = smb + (i & 1) * BUF_B;
        uint32_t aoff = sbase + (wm * 32 + (lane & 15)) * ROW_B + (lane >> 4) * 16;
        uint32_t bbase = sbase + 2 * MAT_B;

        #pragma unroll
        for (int kk = 0; kk < 4; kk++) {
            uint32_t a_h[2][4], a_l[2][4];
            #pragma unroll
            for (int mi = 0; mi < 2; mi++) {
                LDMX4(a_h[mi][0], a_h[mi][1], a_h[mi][2], a_h[mi][3],
                      aoff + mi * 16 * ROW_B + kk * 32);
                LDMX4(a_l[mi][0], a_l[mi][1], a_l[mi][2], a_l[mi][3],
                      aoff + MAT_B + mi * 16 * ROW_B + kk * 32);
            }
            uint32_t bf[4][4];
            #pragma unroll
            for (int nip = 0; nip < 4; nip++) {
                LDMX4(bf[nip][0], bf[nip][1], bf[nip][2], bf[nip][3],
                      bbase + (wn * 64 + nip * 16 + (lane & 15)) * ROW_B
                            + (lane >> 4) * 16 + kk * 32);
            }
            #pragma unroll
            for (int nip = 0; nip < 4; nip++) {
                #pragma unroll
                for (int half = 0; half < 2; half++) {
                    int ni = nip * 2 + half;
                    uint32_t bb[2] = { bf[nip][half], bf[nip][half + 2] };
                    #pragma unroll
                    for (int mi = 0; mi < 2; mi++) {
                        MMAF16(acc[mi][ni], a_h[mi], bb);
                        MMAF16(acc[mi][ni], a_l[mi], bb);
                    }
                }
            }
        }
    }

    #pragma unroll
    for (int mi = 0; mi < 2; mi++) {
        int row0 = bm * 128 + wm * 32 + mi * 16 + (lane >> 2);
        #pragma unroll
        for (int ni = 0; ni < 8; ni++) {
            int col = bn * 128 + wn * 64 + ni * 8 + (lane & 3) * 2;
            *(float2*)(C + (size_t)row0 * N + col) =
                make_float2(acc[mi][ni][0], acc[mi][ni][1]);
            *(float2*)(C + (size_t)(row0 + 8) * N + col) =
                make_float2(acc[mi][ni][2], acc[mi][ni][3]);
        }
    }
}

// ---------------- conversions ----------------
__global__ __launch_bounds__(256) void cvt_split_h(
    const float4* __restrict__ x, __half2* __restrict__ hi,
    __half2* __restrict__ lo, int n4)
{
    int i = blockIdx.x * 256 + threadIdx.x;
    if (i >= n4) return;
    float4 v = x[i];
    __half h0 = __float2half_rn(v.x);
    __half h1 = __float2half_rn(v.y);
    __half h2 = __float2half_rn(v.z);
    __half h3 = __float2half_rn(v.w);
    hi[2 * i]     = __halves2half2(h0, h1);
    hi[2 * i + 1] = __halves2half2(h2, h3);
    lo[2 * i]     = __halves2half2(
        __float2half_rn(v.x - __half2float(h0)),
        __float2half_rn(v.y - __half2float(h1)));
    lo[2 * i + 1] = __halves2half2(
        __float2half_rn(v.z - __half2float(h2)),
        __float2half_rn(v.w - __half2float(h3)));
}

__global__ __launch_bounds__(256) void cvt_wcat_h(
    const float* __restrict__ wbq, const float* __restrict__ wbk,
    const float* __restrict__ wbv, const float* __restrict__ waq,
    const float* __restrict__ wak, const float* __restrict__ wav,
    __half* __restrict__ w)
{
    int i = blockIdx.x * 256 + threadIdx.x;
    if (i >= NPROJ * HID) return;
    int row = i / HID, col = i - row * HID;
    float val = 0.f;
    if (row < 1536)      val = wbq[row * HID + col];
    else if (row < 2048) val = wbk[(row - 1536) * HID + col];
    else if (row < 2560) val = wbv[(row - 2048) * HID + col];
    else if (row < 2608) val = waq[(row - 2560) * HID + col];
    else if (row < 2616) val = wak[(row - 2608) * HID + col];
    else if (row < 2624) val = wav[(row - 2616) * HID + col];
    w[i] = __float2half_rn(val);
}

__global__ __launch_bounds__(256) void cvt_h(
    const float4* __restrict__ x, __half2* __restrict__ w, int n4)
{
    int i = blockIdx.x * 256 + threadIdx.x;
    if (i >= n4) return;
    float4 v = x[i];
    w[2 * i]     = __halves2half2(__float2half_rn(v.x), __float2half_rn(v.y));
    w[2 * i + 1] = __halves2half2(__float2half_rn(v.z), __float2half_rn(v.w));
}

// ---------------- fused RoPE + tensor-product + RMSNorm --------------------
__global__ __launch_bounds__(256) void qkv_kernel(
    const float* __restrict__ proj,
    const float* __restrict__ fcos, const float* __restrict__ fsin,
    const float* __restrict__ qnw, const float* __restrict__ knw,
    const int* __restrict__ idx,
    __nv_bfloat16* __restrict__ qhi, __nv_bfloat16* __restrict__ qlo,
    __nv_bfloat16* __restrict__ khi, __nv_bfloat16* __restrict__ klo,
    __half* __restrict__ vo)
{
    int s = blockIdx.x;
    int tid = threadIdx.x;
    int d = tid;
    int warp = tid >> 5, lane = tid & 31;
    const float* row = proj + (size_t)s * NPROJ;

    __shared__ float sA[64];
    __shared__ float red[8][8];
    __shared__ float srstd[8];
    __shared__ float skrstd[4];

    if (tid < 64) sA[tid] = row[2560 + tid];
    __syncthreads();

    float c  = fcos[s * (HD / 2) + (d >> 1)];
    float sn = fsin[s * (HD / 2) + (d >> 1)];
    float seff = (d & 1) ? sn : -sn;

    float bq[QR];
    #pragma unroll
    for (int r = 0; r < QR; r++) {
        float x  = row[r * HD + d];
        float xn = row[r * HD + (d ^ 1)];
        bq[r] = x * c + xn * seff;
    }
    float qraw[NH];
    #pragma unroll
    for (int h = 0; h < NH; h++) {
        float a = 0.f;
        #pragma unroll
        for (int r = 0; r < QR; r++) a += sA[h * QR + r] * bq[r];
        qraw[h] = a * (1.f / QR);
    }
    #pragma unroll
    for (int h = 0; h < NH; h++) {
        float ss = qraw[h] * qraw[h];
        #pragma unroll
        for (int o = 16; o > 0; o >>= 1) ss += __shfl_xor_sync(0xffffffffu, ss, o);
        if (lane == 0) red[warp][h] = ss;
    }
    __syncthreads();
    if (tid < NH) {
        float t = 0.f;
        #pragma unroll
        for (int w = 0; w < 8; w++) t += red[w][tid];
        srstd[tid] = rsqrtf(t * (1.f / HD) + EPS);
    }
    __syncthreads();
    float qw = (1.f + qnw[d]) * SCALING;
    #pragma unroll
    for (int h = 0; h < NH; h++) {
        float qv = qraw[h] * srstd[h] * qw;
        __nv_bfloat16 hh = __float2bfloat16_rn(qv);
        size_t off = ((size_t)s * NH + h) * HD + d;
        qhi[off] = hh;
        qlo[off] = __float2bfloat16_rn(qv - __bfloat162float(hh));
    }

    float bk[KR];
    #pragma unroll
    for (int r = 0; r < KR; r++) {
        float x  = row[1536 + r * HD + d];
        float xn = row[1536 + r * HD + (d ^ 1)];
        bk[r] = x * c + xn * seff;
    }
    float kraw[KVH];
    #pragma unroll
    for (int kh = 0; kh < KVH; kh++)
        kraw[kh] = (sA[48 + kh * KR + 0] * bk[0] + sA[48 + kh * KR + 1] * bk[1]) * 0.5f;

    __syncthreads();
    #pragma unroll
    for (int kh = 0; kh < KVH; kh++) {
        float ss = kraw[kh] * kraw[kh];
        #pragma unroll
        for (int o = 16; o > 0; o >>= 1) ss += __shfl_xor_sync(0xffffffffu, ss, o);
        if (lane == 0) red[warp][kh] = ss;
    }
    __syncthreads();
    if (tid < KVH) {
        float t = 0.f;
        #pragma unroll
        for (int w = 0; w < 8; w++) t += red[w][tid];
        skrstd[tid] = rsqrtf(t * (1.f / HD) + EPS);
    }
    __syncthreads();

    int tpos = idx[s];
    float kw = 1.f + knw[d];
    #pragma unroll
    for (int kh = 0; kh < KVH; kh++) {
        float kv = kraw[kh] * skrstd[kh] * kw;
        __nv_bfloat16 hh = __float2bfloat16_rn(kv);
        size_t off = ((size_t)tpos * KVH + kh) * HD + d;
        khi[off] = hh;
        klo[off] = __float2bfloat16_rn(kv - __bfloat162float(hh));
    }

    float bv0 = row[2048 + 0 * HD + d];
    float bv1 = row[2048 + 1 * HD + d];
    #pragma unroll
    for (int kh = 0; kh < KVH; kh++)
        vo[((size_t)tpos * KVH + kh) * HD + d] = __float2half_rn(
            (sA[56 + kh * VR + 0] * bv0 + sA[56 + kh * VR + 1] * bv1) * 0.5f);
}

// ---------------- flash attention: bf16x3 QK + fp16 PV, skewed pipeline ----
// smem bytes: Khi 2x16896 | Klo 2x16896 | V(fp16) 3x16896 | P(fp16) 2x5120 | den 256
#define AQ 64
#define ACT 32
#define KROWB 528
#define KBUF 16896
#define KLOOFF 33792
#define VOFFB 67584
#define VROWB 528
#define VBUF 16896
#define POFFB 118272
#define PROWB 80
#define PBUF 5120
#define DENF_IDX 32128
#define ATTN_SMEM 128768

__global__ __launch_bounds__(256, 1)
void attn_mma(const __nv_bfloat16* __restrict__ qh_, const __nv_bfloat16* __restrict__ ql_,
              const __nv_bfloat16* __restrict__ kh_, const __nv_bfloat16* __restrict__ kl_,
              const __half* __restrict__ v, const int* __restrict__ idx,
              __half* __restrict__ outh, __half* __restrict__ outl)
{
    extern __shared__ float smf[];
    __shared__ int spos[AQ];
    __shared__ int srange[2];

    const int s0 = blockIdx.x * AQ;
    const int h = blockIdx.y;
    const int kvh = h >> 1;
    const int tid = threadIdx.x;
    const int wid = tid >> 5;
    const int lane = tid & 31;

    if (tid < AQ) spos[tid] = idx[s0 + tid];
    __syncthreads();
    if (tid == 0) {
        int mn = spos[0], mx = spos[0];
        for (int i = 1; i < AQ; i++) { mn = min(mn, spos[i]); mx = max(mx, spos[i]); }
        srange[0] = max(0, mn - (WINDOW - 1));
        srange[1] = mx;
    }
    __syncthreads();
    const int kmin = srange[0];
    const int nch = (srange[1] - kmin) / ACT + 1;

    const uint32_t smb = smem_u32(smf);
    const __nv_bfloat16* khbase = kh_ + (size_t)kvh * HD;
    const __nv_bfloat16* klbase = kl_ + (size_t)kvh * HD;
    const __half* vbase = v + (size_t)kvh * HD;

    // single merged loader pass: each thread covers one (row, col16) slot
    // for all three 32x512B tiles (Khi, Klo, V).
    auto load_chunk = [&](int ci) {
        int t0 = kmin + ci * ACT;
        uint32_t kdst = smb + (ci & 1) * KBUF;
        uint32_t vdst = smb + VOFFB + (ci % 3) * VBUF;
        #pragma unroll
        for (int j = 0; j < 4; j++) {
            int seg = tid + j * 256;
            int r = seg >> 5;
            int c = seg & 31;
            int t = t0 + r;
            int sz = (t < S_LEN) ? 16 : 0;
            size_t goff = (size_t)t * (KVH * HD) + c * 8;
            uint32_t soff = r * KROWB + c * 16;
            CP_ASYNC16Z(kdst + soff, khbase + goff, sz);
            CP_ASYNC16Z(kdst + KLOOFF + soff, klbase + goff, sz);
            CP_ASYNC16Z(vdst + soff, vbase + goff, sz);
        }
        asm volatile("cp.async.commit_group;");
    };

    load_chunk(0);

    if (wid < 4) {
        // ---------------- score role: QK chunk i (bf16x3) ----------------
        const int rw = wid * 16;
        const int r0 = s0 + rw + (lane >> 2);
        const __nv_bfloat16* q0h = qh_ + ((size_t)r0 * NH + h) * HD;
        const __nv_bfloat16* q1h = qh_ + ((size_t)(r0 + 8) * NH + h) * HD;
        const __nv_bfloat16* q0l = ql_ + ((size_t)r0 * NH + h) * HD;
        const __nv_bfloat16* q1l = ql_ + ((size_t)(r0 + 8) * NH + h) * HD;
        uint32_t qah[16][4], qal[16][4];
        #pragma unroll
        for (int ks = 0; ks < 16; ks++) {
            int c = ks * 16 + 2 * (lane & 3);
            qah[ks][0] = *(const uint32_t*)(q0h + c);
            qah[ks][1] = *(const uint32_t*)(q1h + c);
            qah[ks][2] = *(const uint32_t*)(q0h + c + 8);
            qah[ks][3] = *(const uint32_t*)(q1h + c + 8);
            qal[ks][0] = *(const uint32_t*)(q0l + c);
            qal[ks][1] = *(const uint32_t*)(q1l + c);
            qal[ks][2] = *(const uint32_t*)(q0l + c + 8);
            qal[ks][3] = *(const uint32_t*)(q1l + c + 8);
        }
        const int qp0 = spos[rw + (lane >> 2)];
        const int qp1 = spos[rw + 8 + (lane >> 2)];
        float den0 = 0.f, den1 = 0.f;

        for (int i = 0; i < nch; i++) {
            __syncthreads();                               // A
            if (i + 1 < nch) {
                load_chunk(i + 1);
                asm volatile("cp.async.wait_group 1;");
            } else {
                asm volatile("cp.async.wait_group 0;");
            }
            __syncthreads();                               // B

            const uint32_t skh = smb + (i & 1) * KBUF;
            const uint32_t skl = skh + KLOOFF;
            float sacc[4][4];
            #pragma unroll
            for (int j = 0; j < 4; j++)
                #pragma unroll
                for (int e = 0; e < 4; e++) sacc[j][e] = 0.f;

            #pragma unroll
            for (int ksp = 0; ksp < 8; ksp++) {
                uint32_t kbh[4][4], kbl[4][4];
                #pragma unroll
                for (int j = 0; j < 4; j++) {
                    uint32_t arow = (j * 8 + (lane & 7)) * KROWB + ksp * 64 + (lane >> 3) * 16;
                    LDMX4(kbh[j][0], kbh[j][1], kbh[j][2], kbh[j][3], skh + arow);
                    LDMX4(kbl[j][0], kbl[j][1], kbl[j][2], kbl[j][3], skl + arow);
                }
                #pragma unroll
                for (int j = 0; j < 4; j++) {
                    uint32_t b0h[2] = { kbh[j][0], kbh[j][1] };
                    uint32_t b1h[2] = { kbh[j][2], kbh[j][3] };
                    uint32_t b0l[2] = { kbl[j][0], kbl[j][1] };
                    uint32_t b1l[2] = { kbl[j][2], kbl[j][3] };
                    MMABF16(sacc[j], qah[2 * ksp],     b0h);
                    MMABF16(sacc[j], qah[2 * ksp + 1], b1h);
                    MMABF16(sacc[j], qah[2 * ksp],     b0l);
                    MMABF16(sacc[j], qah[2 * ksp + 1], b1l);
                    MMABF16(sacc[j], qal[2 * ksp],     b0h);
                    MMABF16(sacc[j], qal[2 * ksp + 1], b1h);
                }
            }

            const int t0 = kmin + i * ACT;
            const uint32_t pbb = smb + POFFB + (i & 1) * PBUF;
            #pragma unroll
            for (int j = 0; j < 4; j++) {
                int tk = t0 + j * 8 + (lane & 3) * 2;
                float p[4];
                #pragma unroll
                for (int e = 0; e < 4; e++) {
                    float s = sacc[j][e];
                    int qp = (e < 2) ? qp0 : qp1;
                    int tt = tk + (e & 1);
                    float x2 = (s * (1.f / SOFTCAP)) * (s * (1.f / SOFTCAP));
                    float r = 1.f + x2 * (-0.333333333f + x2 * (0.133333333f + x2 * -0.053968254f));
                    float pe = __expf(fmaf(s, r, -PSHIFT));
                    p[e] = ((unsigned)(qp - tt) < WINDOW) ? pe : 0.f;
                }
                __half2 hp0 = __floats2half2_rn(p[0], p[1]);
                __half2 hp1 = __floats2half2_rn(p[2], p[3]);
                float2 f0 = __half22float2(hp0);
                float2 f1 = __half22float2(hp1);
                den0 += f0.x + f0.y;
                den1 += f1.x + f1.y;
                uint32_t a0 = pbb + (rw + (lane >> 2)) * PROWB + (j * 8 + (lane & 3) * 2) * 2;
                uint32_t a1 = a0 + 8 * PROWB;
                asm volatile("st.shared.b32 [%0], %1;" :: "r"(a0), "r"(*(uint32_t*)&hp0));
                asm volatile("st.shared.b32 [%0], %1;" :: "r"(a1), "r"(*(uint32_t*)&hp1));
            }
        }
        __syncthreads();                                   // C
        den0 += __shfl_xor_sync(0xffffffffu, den0, 1);
        den0 += __shfl_xor_sync(0xffffffffu, den0, 2);
        den1 += __shfl_xor_sync(0xffffffffu, den1, 1);
        den1 += __shfl_xor_sync(0xffffffffu, den1, 2);
        if ((lane & 3) == 0) {
            smf[DENF_IDX + rw + (lane >> 2)] = den0;
            smf[DENF_IDX + rw + 8 + (lane >> 2)] = den1;
        }
        __syncthreads();                                   // D
    } else {
        // ---------------- PV role: chunk i-1 (fp16 HMMA) ----------------
        const int rw = (wid - 4) * 16;
        float oacc[32][4];
        #pragma unroll
        for (int n = 0; n < 32; n++)
            #pragma unroll
            for (int e = 0; e < 4; e++) oacc[n][e] = 0.f;

        auto pv_compute = [&](int ci) {
            const uint32_t svb = smb + VOFFB + (ci % 3) * VBUF;
            const uint32_t pbb = smb + POFFB + (ci & 1) * PBUF;
            uint32_t pa[2][4];
            #pragma unroll
            for (int kk = 0; kk < 2; kk++)
                LDMX4(pa[kk][0], pa[kk][1], pa[kk][2], pa[kk][3],
                      pbb + (rw + (lane & 15)) * PROWB + kk * 32 + (lane >> 4) * 16);
            uint32_t vrow = ((lane >> 3) & 1) * 8 + (lane & 7);
            uint32_t vcol = (lane >> 4) * 8;
            #pragma unroll
            for (int np = 0; np < 16; np++) {
                #pragma unroll
                for (int kk = 0; kk < 2; kk++) {
                    uint32_t vb[4];
                    LDMX4T(vb[0], vb[1], vb[2], vb[3],
                           svb + (kk * 16 + vrow) * VROWB + (np * 16 + vcol) * 2);
                    uint32_t b0[2] = { vb[0], vb[1] };
                    uint32_t b1[2] = { vb[2], vb[3] };
                    MMAF16(oacc[2 * np],     pa[kk], b0);
                    MMAF16(oacc[2 * np + 1], pa[kk], b1);
                }
            }
        };

        for (int i = 0; i < nch; i++) {
            __syncthreads();                               // A
            if (i + 1 < nch) {
                load_chunk(i + 1);
                asm volatile("cp.async.wait_group 1;");
            } else {
                asm volatile("cp.async.wait_group 0;");
            }
            __syncthreads();                               // B
            if (i > 0) pv_compute(i - 1);
        }
        __syncthreads();                                   // C
        pv_compute(nch - 1);
        __syncthreads();                                   // D
        float inv0 = 1.f / smf[DENF_IDX + rw + (lane >> 2)];
        float inv1 = 1.f / smf[DENF_IDX + rw + 8 + (lane >> 2)];
        int grow0 = s0 + rw + (lane >> 2);
        __half* oh0 = outh + (size_t)grow0 * HID + h * HD;
        __half* oh1 = outh + (size_t)(grow0 + 8) * HID + h * HD;
        __half* ol0 = outl + (size_t)grow0 * HID + h * HD;
        __half* ol1 = outl + (size_t)(grow0 + 8) * HID + h * HD;
        #pragma unroll
        for (int n = 0; n < 32; n++) {
            int col = n * 8 + (lane & 3) * 2;
            float v00 = oacc[n][0] * inv0, v01 = oacc[n][1] * inv0;
            float v10 = oacc[n][2] * inv1, v11 = oacc[n][3] * inv1;
            __half h00 = __float2half_rn(v00), h01 = __float2half_rn(v01);
            __half h10 = __float2half_rn(v10), h11 = __float2half_rn(v11);
            *(__half2*)(oh0 + col) = __halves2half2(h00, h01);
            *(__half2*)(oh1 + col) = __halves2half2(h10, h11);
            *(__half2*)(ol0 + col) = __halves2half2(
                __float2half_rn(v00 - __half2float(h00)),
                __float2half_rn(v01 - __half2float(h01)));
            *(__half2*)(ol1 + col) = __halves2half2(
                __float2half_rn(v10 - __half2float(h10)),
                __float2half_rn(v11 - __half2float(h11)));
        }
    }
}

// ---------------- launch ----------------------------------------------------
extern "C" void kernel_launch(void* const* d_in, const int* in_sizes, int n_in,
                              void* d_out, int out_size)
{
    const float* x   = (const float*)d_in[0];
    const float* fc  = (const float*)d_in[1];
    const float* fs  = (const float*)d_in[2];
    const float* WAq = (const float*)d_in[3];
    const float* WAk = (const float*)d_in[4];
    const float* WAv = (const float*)d_in[5];
    const float* WBq = (const float*)d_in[6];
    const float* WBk = (const float*)d_in[7];
    const float* WBv = (const float*)d_in[8];
    const float* Wo  = (const float*)d_in[9];
    const float* qnw = (const float*)d_in[10];
    const float* knw = (const float*)d_in[11];
    const int*   idx = (const int*)d_in[16];
    float* out = (float*)d_out;

    float* gproj;
    __nv_bfloat16 *gqh, *gql, *gkh, *gkl;
    __half *gv, *xhi, *xlo, *wcat, *wo, *ah, *al;
    cudaGetSymbolAddress((void**)&gproj, g_proj);
    cudaGetSymbolAddress((void**)&gqh, g_qhi);
    cudaGetSymbolAddress((void**)&gql, g_qlo);
    cudaGetSymbolAddress((void**)&gkh, g_khi);
    cudaGetSymbolAddress((void**)&gkl, g_klo);
    cudaGetSymbolAddress((void**)&gv,  g_v);
    cudaGetSymbolAddress((void**)&xhi, g_xhi);
    cudaGetSymbolAddress((void**)&xlo, g_xlo);
    cudaGetSymbolAddress((void**)&wcat, g_wcat);
    cudaGetSymbolAddress((void**)&wo, g_wo);
    cudaGetSymbolAddress((void**)&ah, g_attnhi);
    cudaGetSymbolAddress((void**)&al, g_attnlo);

    cudaFuncSetAttribute(mma_gemm, cudaFuncAttributeMaxDynamicSharedMemorySize, GEMM_SMEM);
    cudaFuncSetAttribute(attn_mma, cudaFuncAttributeMaxDynamicSharedMemorySize, ATTN_SMEM);

    cudaMemsetAsync(gkh, 0, (size_t)S_LEN * KVH * HD * sizeof(__nv_bfloat16));
    cudaMemsetAsync(gkl, 0, (size_t)S_LEN * KVH * HD * sizeof(__nv_bfloat16));
    cudaMemsetAsync(gv, 0, (size_t)S_LEN * KVH * HD * sizeof(__half));

    {
        int n4 = S_LEN * HID / 4;
        cvt_split_h<<<(n4 + 255) / 256, 256>>>((const float4*)x,
            (__half2*)xhi, (__half2*)xlo, n4);
    }
    cvt_wcat_h<<<(NPROJ * HID + 255) / 256, 256>>>(WBq, WBk, WBv, WAq, WAk, WAv, wcat);
    {
        int n4 = HID * HID / 4;
        cvt_h<<<(n4 + 255) / 256, 256>>>((const float4*)Wo, (__half2*)wo, n4);
    }

    mma_gemm<<<dim3(NPROJ / 128, 32), 256, GEMM_SMEM>>>(xhi, xlo, wcat,
                                                        gproj, S_LEN, NPROJ, HID);

    qkv_kernel<<<S_LEN, 256>>>(gproj, fc, fs, qnw, knw, idx,
                               gqh, gql, gkh, gkl, gv);

    attn_mma<<<dim3(S_LEN / AQ, NH), 256, ATTN_SMEM>>>(gqh, gql, gkh, gkl, gv, idx, ah, al);

    mma_gemm<<<dim3(16, 32), 256, GEMM_SMEM>>>(ah, al, wo, out, S_LEN, HID, HID);
}

// round 13
// speedup vs baseline: 7.1981x; 1.0756x over previous
#include <cuda_runtime.h>
#include <cuda_bf16.h>
#include <cuda_fp16.h>
#include <math.h>
#include <stdint.h>

#define S_LEN 4096
#define HID 2048
#define NH 8
#define KVH 4
#define HD 256
#define QR 6
#define KR 2
#define VR 2
#define WINDOW 1024
#define SOFTCAP 50.0f
#define SCALING 0.0625f
#define EPS 1e-6f
#define NPROJ 2688
#define PSHIFT 8.0f

// ---------------- scratch ----------------
__device__ float g_proj[S_LEN * NPROJ];
__device__ __half g_qhi[S_LEN * NH * HD];
__device__ __half g_qlo[S_LEN * NH * HD];
__device__ __half g_kf[S_LEN * KVH * HD];
__device__ __half g_v[S_LEN * KVH * HD];

__device__ __half g_xhi[S_LEN * HID];
__device__ __half g_xlo[S_LEN * HID];
__device__ __half g_wcat[NPROJ * HID];
__device__ __half g_wo[HID * HID];
__device__ __half g_attnhi[S_LEN * HID];
__device__ __half g_attnlo[S_LEN * HID];

// ---------------- helpers ----------------
__device__ __forceinline__ uint32_t smem_u32(const void* p) {
    uint32_t a;
    asm("{ .reg .u64 t; cvta.to.shared.u64 t, %1; cvt.u32.u64 %0, t; }" : "=r"(a) : "l"(p));
    return a;
}

#define LDMX4(r0, r1, r2, r3, addr)                                              \
    asm volatile("ldmatrix.sync.aligned.m8n8.x4.shared.b16 {%0,%1,%2,%3}, [%4];" \
                 : "=r"(r0), "=r"(r1), "=r"(r2), "=r"(r3) : "r"(addr))
#define LDMX4T(r0, r1, r2, r3, addr)                                             \
    asm volatile("ldmatrix.sync.aligned.m8n8.x4.trans.shared.b16 {%0,%1,%2,%3}, [%4];" \
                 : "=r"(r0), "=r"(r1), "=r"(r2), "=r"(r3) : "r"(addr))
#define MMAF16(d, a, b)                                                          \
    asm volatile("mma.sync.aligned.m16n8k16.row.col.f32.f16.f16.f32 "            \
                 "{%0,%1,%2,%3}, {%4,%5,%6,%7}, {%8,%9}, {%0,%1,%2,%3};"         \
                 : "+f"((d)[0]), "+f"((d)[1]), "+f"((d)[2]), "+f"((d)[3])        \
                 : "r"((a)[0]), "r"((a)[1]), "r"((a)[2]), "r"((a)[3]),           \
                   "r"((b)[0]), "r"((b)[1]))
#define CP_ASYNC16(dst, src)                                                     \
    asm volatile("cp.async.cg.shared.global [%0], [%1], 16;" :: "r"(dst), "l"(src))
#define CP_ASYNC16Z(dst, src, sz)                                                \
    asm volatile("cp.async.cg.shared.global [%0], [%1], 16, %2;"                 \
                 :: "r"(dst), "l"(src), "r"(sz))

// ---------------- fp16x2 GEMM via mma.sync: C = (Ah+Al) @ B^T ---------------
#define CK 64
#define ROW_B 144
#define MAT_B (128 * ROW_B)
#define BUF_B (3 * MAT_B)
#define GEMM_SMEM (2 * BUF_B)

__global__ __launch_bounds__(256, 2)
void mma_gemm(const __half* __restrict__ Ah, const __half* __restrict__ Al,
              const __half* __restrict__ B,
              float* __restrict__ C, int M, int N, int K)
{
    extern __shared__ char sm[];
    const uint32_t smb = smem_u32(sm);

    const int tid = threadIdx.x;
    const int wid = tid >> 5;
    const int lane = tid & 31;
    const int wm = wid & 3;
    const int wn = wid >> 2;
    const int bm = blockIdx.y;
    const int bn = blockIdx.x;

    const __half* baseAh = Ah + (size_t)(bm * 128) * K;
    const __half* baseAl = Al + (size_t)(bm * 128) * K;
    const __half* baseB  = B  + (size_t)(bn * 128) * K;

    float acc[2][8][4];
    #pragma unroll
    for (int mi = 0; mi < 2; mi++)
        #pragma unroll
        for (int ni = 0; ni < 8; ni++)
            #pragma unroll
            for (int j = 0; j < 4; j++) acc[mi][ni][j] = 0.f;

    auto load_chunk = [&](int kb, int b) {
        uint32_t bufb = smb + b * BUF_B;
        #pragma unroll
        for (int it = 0; it < 12; it++) {
            const __half* base = (it < 4) ? baseAh : (it < 8) ? baseAl : baseB;
            int idx = ((it & 3) << 8) + tid;
            int r = idx >> 3;
            int c = idx & 7;
            const void* src = base + (size_t)r * K + kb * CK + c * 8;
            uint32_t dst = bufb + (it >> 2) * MAT_B + r * ROW_B + c * 16;
            CP_ASYNC16(dst, src);
        }
        asm volatile("cp.async.commit_group;");
    };

    const int NC = K / CK;
    load_chunk(0, 0);

    for (int i = 0; i < NC; i++) {
        asm volatile("cp.async.wait_group 0;");
        __syncthreads();
        if (i + 1 < NC) load_chunk(i + 1, (i + 1) & 1);

        uint32_t sbase = smb + (i & 1) * BUF_B;
        uint32_t aoff = sbase + (wm * 32 + (lane & 15)) * ROW_B + (lane >> 4) * 16;
        uint32_t bbase = sbase + 2 * MAT_B;

        #pragma unroll
        for (int kk = 0; kk < 4; kk++) {
            uint32_t a_h[2][4], a_l[2][4];
            #pragma unroll
            for (int mi = 0; mi < 2; mi++) {
                LDMX4(a_h[mi][0], a_h[mi][1], a_h[mi][2], a_h[mi][3],
                      aoff + mi * 16 * ROW_B + kk * 32);
                LDMX4(a_l[mi][0], a_l[mi][1], a_l[mi][2], a_l[mi][3],
                      aoff + MAT_B + mi * 16 * ROW_B + kk * 32);
            }
            uint32_t bf[4][4];
            #pragma unroll
            for (int nip = 0; nip < 4; nip++) {
                LDMX4(bf[nip][0], bf[nip][1], bf[nip][2], bf[nip][3],
                      bbase + (wn * 64 + nip * 16 + (lane & 15)) * ROW_B
                            + (lane >> 4) * 16 + kk * 32);
            }
            #pragma unroll
            for (int nip = 0; nip < 4; nip++) {
                #pragma unroll
                for (int half = 0; half < 2; half++) {
                    int ni = nip * 2 + half;
                    uint32_t bb[2] = { bf[nip][half], bf[nip][half + 2] };
                    #pragma unroll
                    for (int mi = 0; mi < 2; mi++) {
                        MMAF16(acc[mi][ni], a_h[mi], bb);
                        MMAF16(acc[mi][ni], a_l[mi], bb);
                    }
                }
            }
        }
    }

    #pragma unroll
    for (int mi = 0; mi < 2; mi++) {
        int row0 = bm * 128 + wm * 32 + mi * 16 + (lane >> 2);
        #pragma unroll
        for (int ni = 0; ni < 8; ni++) {
            int col = bn * 128 + wn * 64 + ni * 8 + (lane & 3) * 2;
            *(float2*)(C + (size_t)row0 * N + col) =
                make_float2(acc[mi][ni][0], acc[mi][ni][1]);
            *(float2*)(C + (size_t)(row0 + 8) * N + col) =
                make_float2(acc[mi][ni][2], acc[mi][ni][3]);
        }
    }
}

// ---------------- conversions ----------------
__global__ __launch_bounds__(256) void cvt_split_h(
    const float4* __restrict__ x, __half2* __restrict__ hi,
    __half2* __restrict__ lo, int n4)
{
    int i = blockIdx.x * 256 + threadIdx.x;
    if (i >= n4) return;
    float4 v = x[i];
    __half h0 = __float2half_rn(v.x);
    __half h1 = __float2half_rn(v.y);
    __half h2 = __float2half_rn(v.z);
    __half h3 = __float2half_rn(v.w);
    hi[2 * i]     = __halves2half2(h0, h1);
    hi[2 * i + 1] = __halves2half2(h2, h3);
    lo[2 * i]     = __halves2half2(
        __float2half_rn(v.x - __half2float(h0)),
        __float2half_rn(v.y - __half2float(h1)));
    lo[2 * i + 1] = __halves2half2(
        __float2half_rn(v.z - __half2float(h2)),
        __float2half_rn(v.w - __half2float(h3)));
}

__global__ __launch_bounds__(256) void cvt_wcat_h(
    const float* __restrict__ wbq, const float* __restrict__ wbk,
    const float* __restrict__ wbv, const float* __restrict__ waq,
    const float* __restrict__ wak, const float* __restrict__ wav,
    __half* __restrict__ w)
{
    int i = blockIdx.x * 256 + threadIdx.x;
    if (i >= NPROJ * HID) return;
    int row = i / HID, col = i - row * HID;
    float val = 0.f;
    if (row < 1536)      val = wbq[row * HID + col];
    else if (row < 2048) val = wbk[(row - 1536) * HID + col];
    else if (row < 2560) val = wbv[(row - 2048) * HID + col];
    else if (row < 2608) val = waq[(row - 2560) * HID + col];
    else if (row < 2616) val = wak[(row - 2608) * HID + col];
    else if (row < 2624) val = wav[(row - 2616) * HID + col];
    w[i] = __float2half_rn(val);
}

__global__ __launch_bounds__(256) void cvt_h(
    const float4* __restrict__ x, __half2* __restrict__ w, int n4)
{
    int i = blockIdx.x * 256 + threadIdx.x;
    if (i >= n4) return;
    float4 v = x[i];
    w[2 * i]     = __halves2half2(__float2half_rn(v.x), __float2half_rn(v.y));
    w[2 * i + 1] = __halves2half2(__float2half_rn(v.z), __float2half_rn(v.w));
}

// ---------------- fused RoPE + tensor-product + RMSNorm --------------------
__global__ __launch_bounds__(256) void qkv_kernel(
    const float* __restrict__ proj,
    const float* __restrict__ fcos, const float* __restrict__ fsin,
    const float* __restrict__ qnw, const float* __restrict__ knw,
    const int* __restrict__ idx,
    __half* __restrict__ qhi, __half* __restrict__ qlo,
    __half* __restrict__ kf, __half* __restrict__ vo)
{
    int s = blockIdx.x;
    int tid = threadIdx.x;
    int d = tid;
    int warp = tid >> 5, lane = tid & 31;
    const float* row = proj + (size_t)s * NPROJ;

    __shared__ float sA[64];
    __shared__ float red[8][8];
    __shared__ float srstd[8];
    __shared__ float skrstd[4];

    if (tid < 64) sA[tid] = row[2560 + tid];
    __syncthreads();

    float c  = fcos[s * (HD / 2) + (d >> 1)];
    float sn = fsin[s * (HD / 2) + (d >> 1)];
    float seff = (d & 1) ? sn : -sn;

    float bq[QR];
    #pragma unroll
    for (int r = 0; r < QR; r++) {
        float x  = row[r * HD + d];
        float xn = row[r * HD + (d ^ 1)];
        bq[r] = x * c + xn * seff;
    }
    float qraw[NH];
    #pragma unroll
    for (int h = 0; h < NH; h++) {
        float a = 0.f;
        #pragma unroll
        for (int r = 0; r < QR; r++) a += sA[h * QR + r] * bq[r];
        qraw[h] = a * (1.f / QR);
    }
    #pragma unroll
    for (int h = 0; h < NH; h++) {
        float ss = qraw[h] * qraw[h];
        #pragma unroll
        for (int o = 16; o > 0; o >>= 1) ss += __shfl_xor_sync(0xffffffffu, ss, o);
        if (lane == 0) red[warp][h] = ss;
    }
    __syncthreads();
    if (tid < NH) {
        float t = 0.f;
        #pragma unroll
        for (int w = 0; w < 8; w++) t += red[w][tid];
        srstd[tid] = rsqrtf(t * (1.f / HD) + EPS);
    }
    __syncthreads();
    float qw = (1.f + qnw[d]) * SCALING;
    #pragma unroll
    for (int h = 0; h < NH; h++) {
        float qv = qraw[h] * srstd[h] * qw;
        __half hh = __float2half_rn(qv);
        size_t off = ((size_t)s * NH + h) * HD + d;
        qhi[off] = hh;
        qlo[off] = __float2half_rn(qv - __half2float(hh));
    }

    float bk[KR];
    #pragma unroll
    for (int r = 0; r < KR; r++) {
        float x  = row[1536 + r * HD + d];
        float xn = row[1536 + r * HD + (d ^ 1)];
        bk[r] = x * c + xn * seff;
    }
    float kraw[KVH];
    #pragma unroll
    for (int kh = 0; kh < KVH; kh++)
        kraw[kh] = (sA[48 + kh * KR + 0] * bk[0] + sA[48 + kh * KR + 1] * bk[1]) * 0.5f;

    __syncthreads();
    #pragma unroll
    for (int kh = 0; kh < KVH; kh++) {
        float ss = kraw[kh] * kraw[kh];
        #pragma unroll
        for (int o = 16; o > 0; o >>= 1) ss += __shfl_xor_sync(0xffffffffu, ss, o);
        if (lane == 0) red[warp][kh] = ss;
    }
    __syncthreads();
    if (tid < KVH) {
        float t = 0.f;
        #pragma unroll
        for (int w = 0; w < 8; w++) t += red[w][tid];
        skrstd[tid] = rsqrtf(t * (1.f / HD) + EPS);
    }
    __syncthreads();

    int tpos = idx[s];
    float kw = 1.f + knw[d];
    #pragma unroll
    for (int kh = 0; kh < KVH; kh++)
        kf[((size_t)tpos * KVH + kh) * HD + d] =
            __float2half_rn(kraw[kh] * skrstd[kh] * kw);

    float bv0 = row[2048 + 0 * HD + d];
    float bv1 = row[2048 + 1 * HD + d];
    #pragma unroll
    for (int kh = 0; kh < KVH; kh++)
        vo[((size_t)tpos * KVH + kh) * HD + d] = __float2half_rn(
            (sA[56 + kh * VR + 0] * bv0 + sA[56 + kh * VR + 1] * bv1) * 0.5f);
}

// ---------------- flash attention: fp16x2 QK + fp16 PV, skewed pipeline ----
// smem bytes: K(fp16) 2x16896 | V(fp16) 3x16896 | P(fp16) 2x5120 | den 256
#define AQ 64
#define ACT 32
#define KROWB 528
#define KBUF 16896
#define VOFFB 33792
#define VROWB 528
#define VBUF 16896
#define POFFB 84480
#define PROWB 80
#define PBUF 5120
#define DENF_IDX 23680
#define ATTN_SMEM 94976

__global__ __launch_bounds__(256, 1)
void attn_mma(const __half* __restrict__ qh_, const __half* __restrict__ ql_,
              const __half* __restrict__ kf_, const __half* __restrict__ v,
              const int* __restrict__ idx,
              __half* __restrict__ outh, __half* __restrict__ outl)
{
    extern __shared__ float smf[];
    __shared__ int spos[AQ];
    __shared__ int srange[2];

    const int s0 = blockIdx.x * AQ;
    const int h = blockIdx.y;
    const int kvh = h >> 1;
    const int tid = threadIdx.x;
    const int wid = tid >> 5;
    const int lane = tid & 31;

    if (tid < AQ) spos[tid] = idx[s0 + tid];
    __syncthreads();
    if (tid == 0) {
        int mn = spos[0], mx = spos[0];
        for (int i = 1; i < AQ; i++) { mn = min(mn, spos[i]); mx = max(mx, spos[i]); }
        srange[0] = max(0, mn - (WINDOW - 1));
        srange[1] = mx;
    }
    __syncthreads();
    const int kmin = srange[0];
    const int nch = (srange[1] - kmin) / ACT + 1;

    const uint32_t smb = smem_u32(smf);
    const __half* kbase = kf_ + (size_t)kvh * HD;
    const __half* vbase = v + (size_t)kvh * HD;

    auto load_chunk = [&](int ci) {
        int t0 = kmin + ci * ACT;
        uint32_t kdst = smb + (ci & 1) * KBUF;
        uint32_t vdst = smb + VOFFB + (ci % 3) * VBUF;
        #pragma unroll
        for (int j = 0; j < 4; j++) {
            int seg = tid + j * 256;
            int r = seg >> 5;
            int c = seg & 31;
            int t = t0 + r;
            int sz = (t < S_LEN) ? 16 : 0;
            size_t goff = (size_t)t * (KVH * HD) + c * 8;
            uint32_t soff = r * KROWB + c * 16;
            CP_ASYNC16Z(kdst + soff, kbase + goff, sz);
            CP_ASYNC16Z(vdst + soff, vbase + goff, sz);
        }
        asm volatile("cp.async.commit_group;");
    };

    load_chunk(0);

    if (wid < 4) {
        // ---------------- score role: QK chunk i (fp16x2: q hi/lo, k single) ----
        const int rw = wid * 16;
        const int r0 = s0 + rw + (lane >> 2);
        const __half* q0h = qh_ + ((size_t)r0 * NH + h) * HD;
        const __half* q1h = qh_ + ((size_t)(r0 + 8) * NH + h) * HD;
        const __half* q0l = ql_ + ((size_t)r0 * NH + h) * HD;
        const __half* q1l = ql_ + ((size_t)(r0 + 8) * NH + h) * HD;
        uint32_t qah[16][4], qal[16][4];
        #pragma unroll
        for (int ks = 0; ks < 16; ks++) {
            int c = ks * 16 + 2 * (lane & 3);
            qah[ks][0] = *(const uint32_t*)(q0h + c);
            qah[ks][1] = *(const uint32_t*)(q1h + c);
            qah[ks][2] = *(const uint32_t*)(q0h + c + 8);
            qah[ks][3] = *(const uint32_t*)(q1h + c + 8);
            qal[ks][0] = *(const uint32_t*)(q0l + c);
            qal[ks][1] = *(const uint32_t*)(q1l + c);
            qal[ks][2] = *(const uint32_t*)(q0l + c + 8);
            qal[ks][3] = *(const uint32_t*)(q1l + c + 8);
        }
        const int qp0 = spos[rw + (lane >> 2)];
        const int qp1 = spos[rw + 8 + (lane >> 2)];
        float den0 = 0.f, den1 = 0.f;

        for (int i = 0; i < nch; i++) {
            __syncthreads();                               // A
            if (i + 1 < nch) {
                load_chunk(i + 1);
                asm volatile("cp.async.wait_group 1;");
            } else {
                asm volatile("cp.async.wait_group 0;");
            }
            __syncthreads();                               // B

            const uint32_t skb = smb + (i & 1) * KBUF;
            float sacc[4][4];
            #pragma unroll
            for (int j = 0; j < 4; j++)
                #pragma unroll
                for (int e = 0; e < 4; e++) sacc[j][e] = 0.f;

            #pragma unroll
            for (int ksp = 0; ksp < 8; ksp++) {
                uint32_t kb[4][4];
                #pragma unroll
                for (int j = 0; j < 4; j++) {
                    uint32_t arow = (j * 8 + (lane & 7)) * KROWB + ksp * 64 + (lane >> 3) * 16;
                    LDMX4(kb[j][0], kb[j][1], kb[j][2], kb[j][3], skb + arow);
                }
                #pragma unroll
                for (int j = 0; j < 4; j++) {
                    uint32_t b0[2] = { kb[j][0], kb[j][1] };
                    uint32_t b1[2] = { kb[j][2], kb[j][3] };
                    MMAF16(sacc[j], qah[2 * ksp],     b0);
                    MMAF16(sacc[j], qah[2 * ksp + 1], b1);
                    MMAF16(sacc[j], qal[2 * ksp],     b0);
                    MMAF16(sacc[j], qal[2 * ksp + 1], b1);
                }
            }

            const int t0 = kmin + i * ACT;
            const uint32_t pbb = smb + POFFB + (i & 1) * PBUF;
            #pragma unroll
            for (int j = 0; j < 4; j++) {
                int tk = t0 + j * 8 + (lane & 3) * 2;
                float p[4];
                #pragma unroll
                for (int e = 0; e < 4; e++) {
                    float s = sacc[j][e];
                    int qp = (e < 2) ? qp0 : qp1;
                    int tt = tk + (e & 1);
                    float x2 = (s * (1.f / SOFTCAP)) * (s * (1.f / SOFTCAP));
                    float r = 1.f + x2 * (-0.333333333f + x2 * (0.133333333f + x2 * -0.053968254f));
                    float pe = __expf(fmaf(s, r, -PSHIFT));
                    p[e] = ((unsigned)(qp - tt) < WINDOW) ? pe : 0.f;
                }
                __half2 hp0 = __floats2half2_rn(p[0], p[1]);
                __half2 hp1 = __floats2half2_rn(p[2], p[3]);
                float2 f0 = __half22float2(hp0);
                float2 f1 = __half22float2(hp1);
                den0 += f0.x + f0.y;
                den1 += f1.x + f1.y;
                uint32_t a0 = pbb + (rw + (lane >> 2)) * PROWB + (j * 8 + (lane & 3) * 2) * 2;
                uint32_t a1 = a0 + 8 * PROWB;
                asm volatile("st.shared.b32 [%0], %1;" :: "r"(a0), "r"(*(uint32_t*)&hp0));
                asm volatile("st.shared.b32 [%0], %1;" :: "r"(a1), "r"(*(uint32_t*)&hp1));
            }
        }
        __syncthreads();                                   // C
        den0 += __shfl_xor_sync(0xffffffffu, den0, 1);
        den0 += __shfl_xor_sync(0xffffffffu, den0, 2);
        den1 += __shfl_xor_sync(0xffffffffu, den1, 1);
        den1 += __shfl_xor_sync(0xffffffffu, den1, 2);
        if ((lane & 3) == 0) {
            smf[DENF_IDX + rw + (lane >> 2)] = den0;
            smf[DENF_IDX + rw + 8 + (lane >> 2)] = den1;
        }
        __syncthreads();                                   // D
    } else {
        // ---------------- PV role: chunk i-1 (fp16 HMMA) ----------------
        const int rw = (wid - 4) * 16;
        float oacc[32][4];
        #pragma unroll
        for (int n = 0; n < 32; n++)
            #pragma unroll
            for (int e = 0; e < 4; e++) oacc[n][e] = 0.f;

        auto pv_compute = [&](int ci) {
            const uint32_t svb = smb + VOFFB + (ci % 3) * VBUF;
            const uint32_t pbb = smb + POFFB + (ci & 1) * PBUF;
            uint32_t pa[2][4];
            #pragma unroll
            for (int kk = 0; kk < 2; kk++)
                LDMX4(pa[kk][0], pa[kk][1], pa[kk][2], pa[kk][3],
                      pbb + (rw + (lane & 15)) * PROWB + kk * 32 + (lane >> 4) * 16);
            uint32_t vrow = ((lane >> 3) & 1) * 8 + (lane & 7);
            uint32_t vcol = (lane >> 4) * 8;
            #pragma unroll
            for (int np = 0; np < 16; np++) {
                #pragma unroll
                for (int kk = 0; kk < 2; kk++) {
                    uint32_t vb[4];
                    LDMX4T(vb[0], vb[1], vb[2], vb[3],
                           svb + (kk * 16 + vrow) * VROWB + (np * 16 + vcol) * 2);
                    uint32_t b0[2] = { vb[0], vb[1] };
                    uint32_t b1[2] = { vb[2], vb[3] };
                    MMAF16(oacc[2 * np],     pa[kk], b0);
                    MMAF16(oacc[2 * np + 1], pa[kk], b1);
                }
            }
        };

        for (int i = 0; i < nch; i++) {
            __syncthreads();                               // A
            if (i + 1 < nch) {
                load_chunk(i + 1);
                asm volatile("cp.async.wait_group 1;");
            } else {
                asm volatile("cp.async.wait_group 0;");
            }
            __syncthreads();                               // B
            if (i > 0) pv_compute(i - 1);
        }
        __syncthreads();                                   // C
        pv_compute(nch - 1);
        __syncthreads();                                   // D
        float inv0 = 1.f / smf[DENF_IDX + rw + (lane >> 2)];
        float inv1 = 1.f / smf[DENF_IDX + rw + 8 + (lane >> 2)];
        int grow0 = s0 + rw + (lane >> 2);
        __half* oh0 = outh + (size_t)grow0 * HID + h * HD;
        __half* oh1 = outh + (size_t)(grow0 + 8) * HID + h * HD;
        __half* ol0 = outl + (size_t)grow0 * HID + h * HD;
        __half* ol1 = outl + (size_t)(grow0 + 8) * HID + h * HD;
        #pragma unroll
        for (int n = 0; n < 32; n++) {
            int col = n * 8 + (lane & 3) * 2;
            float v00 = oacc[n][0] * inv0, v01 = oacc[n][1] * inv0;
            float v10 = oacc[n][2] * inv1, v11 = oacc[n][3] * inv1;
            __half h00 = __float2half_rn(v00), h01 = __float2half_rn(v01);
            __half h10 = __float2half_rn(v10), h11 = __float2half_rn(v11);
            *(__half2*)(oh0 + col) = __halves2half2(h00, h01);
            *(__half2*)(oh1 + col) = __halves2half2(h10, h11);
            *(__half2*)(ol0 + col) = __halves2half2(
                __float2half_rn(v00 - __half2float(h00)),
                __float2half_rn(v01 - __half2float(h01)));
            *(__half2*)(ol1 + col) = __halves2half2(
                __float2half_rn(v10 - __half2float(h10)),
                __float2half_rn(v11 - __half2float(h11)));
        }
    }
}

// ---------------- launch ----------------------------------------------------
extern "C" void kernel_launch(void* const* d_in, const int* in_sizes, int n_in,
                              void* d_out, int out_size)
{
    const float* x   = (const float*)d_in[0];
    const float* fc  = (const float*)d_in[1];
    const float* fs  = (const float*)d_in[2];
    const float* WAq = (const float*)d_in[3];
    const float* WAk = (const float*)d_in[4];
    const float* WAv = (const float*)d_in[5];
    const float* WBq = (const float*)d_in[6];
    const float* WBk = (const float*)d_in[7];
    const float* WBv = (const float*)d_in[8];
    const float* Wo  = (const float*)d_in[9];
    const float* qnw = (const float*)d_in[10];
    const float* knw = (const float*)d_in[11];
    const int*   idx = (const int*)d_in[16];
    float* out = (float*)d_out;

    float* gproj;
    __half *gqh, *gql, *gkf, *gv, *xhi, *xlo, *wcat, *wo, *ah, *al;
    cudaGetSymbolAddress((void**)&gproj, g_proj);
    cudaGetSymbolAddress((void**)&gqh, g_qhi);
    cudaGetSymbolAddress((void**)&gql, g_qlo);
    cudaGetSymbolAddress((void**)&gkf, g_kf);
    cudaGetSymbolAddress((void**)&gv,  g_v);
    cudaGetSymbolAddress((void**)&xhi, g_xhi);
    cudaGetSymbolAddress((void**)&xlo, g_xlo);
    cudaGetSymbolAddress((void**)&wcat, g_wcat);
    cudaGetSymbolAddress((void**)&wo, g_wo);
    cudaGetSymbolAddress((void**)&ah, g_attnhi);
    cudaGetSymbolAddress((void**)&al, g_attnlo);

    cudaFuncSetAttribute(mma_gemm, cudaFuncAttributeMaxDynamicSharedMemorySize, GEMM_SMEM);
    cudaFuncSetAttribute(attn_mma, cudaFuncAttributeMaxDynamicSharedMemorySize, ATTN_SMEM);

    cudaMemsetAsync(gkf, 0, (size_t)S_LEN * KVH * HD * sizeof(__half));
    cudaMemsetAsync(gv, 0, (size_t)S_LEN * KVH * HD * sizeof(__half));

    {
        int n4 = S_LEN * HID / 4;
        cvt_split_h<<<(n4 + 255) / 256, 256>>>((const float4*)x,
            (__half2*)xhi, (__half2*)xlo, n4);
    }
    cvt_wcat_h<<<(NPROJ * HID + 255) / 256, 256>>>(WBq, WBk, WBv, WAq, WAk, WAv, wcat);
    {
        int n4 = HID * HID / 4;
        cvt_h<<<(n4 + 255) / 256, 256>>>((const float4*)Wo, (__half2*)wo, n4);
    }

    mma_gemm<<<dim3(NPROJ / 128, 32), 256, GEMM_SMEM>>>(xhi, xlo, wcat,
                                                        gproj, S_LEN, NPROJ, HID);

    qkv_kernel<<<S_LEN, 256>>>(gproj, fc, fs, qnw, knw, idx,
                               gqh, gql, gkf, gv);

    attn_mma<<<dim3(S_LEN / AQ, NH), 256, ATTN_SMEM>>>(gqh, gql, gkf, gv, idx, ah, al);

    mma_gemm<<<dim3(16, 32), 256, GEMM_SMEM>>>(ah, al, wo, out, S_LEN, HID, HID);
}

// round 15
// speedup vs baseline: 7.3453x; 1.0205x over previous
#include <cuda_runtime.h>
#include <cuda_bf16.h>
#include <cuda_fp16.h>
#include <math.h>
#include <stdint.h>

#define S_LEN 4096
#define HID 2048
#define NH 8
#define KVH 4
#define HD 256
#define QR 6
#define KR 2
#define VR 2
#define WINDOW 1024
#define SOFTCAP 50.0f
#define SCALING 0.0625f
#define EPS 1e-6f
#define NPROJ 2688
#define PSHIFT 8.0f

// ---------------- scratch ----------------
__device__ float g_proj[S_LEN * NPROJ];
__device__ __half g_qhi[S_LEN * NH * HD];
__device__ __half g_qlo[S_LEN * NH * HD];
__device__ __half g_kf[S_LEN * KVH * HD];
__device__ __half g_v[S_LEN * KVH * HD];

__device__ __half g_xhi[S_LEN * HID];
__device__ __half g_xlo[S_LEN * HID];
__device__ __half g_wcat[NPROJ * HID];
__device__ __half g_wo[HID * HID];
__device__ __half g_attnhi[S_LEN * HID];
__device__ __half g_attnlo[S_LEN * HID];

// ---------------- helpers ----------------
__device__ __forceinline__ uint32_t smem_u32(const void* p) {
    uint32_t a;
    asm("{ .reg .u64 t; cvta.to.shared.u64 t, %1; cvt.u32.u64 %0, t; }" : "=r"(a) : "l"(p));
    return a;
}

#define LDMX4(r0, r1, r2, r3, addr)                                              \
    asm volatile("ldmatrix.sync.aligned.m8n8.x4.shared.b16 {%0,%1,%2,%3}, [%4];" \
                 : "=r"(r0), "=r"(r1), "=r"(r2), "=r"(r3) : "r"(addr))
#define LDMX4T(r0, r1, r2, r3, addr)                                             \
    asm volatile("ldmatrix.sync.aligned.m8n8.x4.trans.shared.b16 {%0,%1,%2,%3}, [%4];" \
                 : "=r"(r0), "=r"(r1), "=r"(r2), "=r"(r3) : "r"(addr))
#define MMAF16(d, a, b)                                                          \
    asm volatile("mma.sync.aligned.m16n8k16.row.col.f32.f16.f16.f32 "            \
                 "{%0,%1,%2,%3}, {%4,%5,%6,%7}, {%8,%9}, {%0,%1,%2,%3};"         \
                 : "+f"((d)[0]), "+f"((d)[1]), "+f"((d)[2]), "+f"((d)[3])        \
                 : "r"((a)[0]), "r"((a)[1]), "r"((a)[2]), "r"((a)[3]),           \
                   "r"((b)[0]), "r"((b)[1]))
#define CP_ASYNC16(dst, src)                                                     \
    asm volatile("cp.async.cg.shared.global [%0], [%1], 16;" :: "r"(dst), "l"(src))
#define CP_ASYNC16Z(dst, src, sz)                                                \
    asm volatile("cp.async.cg.shared.global [%0], [%1], 16, %2;"                 \
                 :: "r"(dst), "l"(src), "r"(sz))

// ---------------- fp16x2 GEMM via mma.sync: C = (Ah+Al) @ B^T ---------------
#define CK 64
#define ROW_B 144
#define MAT_B (128 * ROW_B)
#define BUF_B (3 * MAT_B)
#define GEMM_SMEM (2 * BUF_B)

__global__ __launch_bounds__(256, 2)
void mma_gemm(const __half* __restrict__ Ah, const __half* __restrict__ Al,
              const __half* __restrict__ B,
              float* __restrict__ C, int M, int N, int K)
{
    extern __shared__ char sm[];
    const uint32_t smb = smem_u32(sm);

    const int tid = threadIdx.x;
    const int wid = tid >> 5;
    const int lane = tid & 31;
    const int wm = wid & 3;
    const int wn = wid >> 2;
    const int bm = blockIdx.y;
    const int bn = blockIdx.x;

    const __half* baseAh = Ah + (size_t)(bm * 128) * K;
    const __half* baseAl = Al + (size_t)(bm * 128) * K;
    const __half* baseB  = B  + (size_t)(bn * 128) * K;

    float acc[2][8][4];
    #pragma unroll
    for (int mi = 0; mi < 2; mi++)
        #pragma unroll
        for (int ni = 0; ni < 8; ni++)
            #pragma unroll
            for (int j = 0; j < 4; j++) acc[mi][ni][j] = 0.f;

    auto load_chunk = [&](int kb, int b) {
        uint32_t bufb = smb + b * BUF_B;
        #pragma unroll
        for (int it = 0; it < 12; it++) {
            const __half* base = (it < 4) ? baseAh : (it < 8) ? baseAl : baseB;
            int idx = ((it & 3) << 8) + tid;
            int r = idx >> 3;
            int c = idx & 7;
            const void* src = base + (size_t)r * K + kb * CK + c * 8;
            uint32_t dst = bufb + (it >> 2) * MAT_B + r * ROW_B + c * 16;
            CP_ASYNC16(dst, src);
        }
        asm volatile("cp.async.commit_group;");
    };

    const int NC = K / CK;
    load_chunk(0, 0);

    for (int i = 0; i < NC; i++) {
        asm volatile("cp.async.wait_group 0;");
        __syncthreads();
        if (i + 1 < NC) load_chunk(i + 1, (i + 1) & 1);

        uint32_t sbase = smb + (i & 1) * BUF_B;
        uint32_t aoff = sbase + (wm * 32 + (lane & 15)) * ROW_B + (lane >> 4) * 16;
        uint32_t bbase = sbase + 2 * MAT_B;

        #pragma unroll
        for (int kk = 0; kk < 4; kk++) {
            uint32_t a_h[2][4], a_l[2][4];
            #pragma unroll
            for (int mi = 0; mi < 2; mi++) {
                LDMX4(a_h[mi][0], a_h[mi][1], a_h[mi][2], a_h[mi][3],
                      aoff + mi * 16 * ROW_B + kk * 32);
                LDMX4(a_l[mi][0], a_l[mi][1], a_l[mi][2], a_l[mi][3],
                      aoff + MAT_B + mi * 16 * ROW_B + kk * 32);
            }
            uint32_t bf[4][4];
            #pragma unroll
            for (int nip = 0; nip < 4; nip++) {
                LDMX4(bf[nip][0], bf[nip][1], bf[nip][2], bf[nip][3],
                      bbase + (wn * 64 + nip * 16 + (lane & 15)) * ROW_B
                            + (lane >> 4) * 16 + kk * 32);
            }
            #pragma unroll
            for (int nip = 0; nip < 4; nip++) {
                #pragma unroll
                for (int half = 0; half < 2; half++) {
                    int ni = nip * 2 + half;
                    uint32_t bb[2] = { bf[nip][half], bf[nip][half + 2] };
                    #pragma unroll
                    for (int mi = 0; mi < 2; mi++) {
                        MMAF16(acc[mi][ni], a_h[mi], bb);
                        MMAF16(acc[mi][ni], a_l[mi], bb);
                    }
                }
            }
        }
    }

    #pragma unroll
    for (int mi = 0; mi < 2; mi++) {
        int row0 = bm * 128 + wm * 32 + mi * 16 + (lane >> 2);
        #pragma unroll
        for (int ni = 0; ni < 8; ni++) {
            int col = bn * 128 + wn * 64 + ni * 8 + (lane & 3) * 2;
            *(float2*)(C + (size_t)row0 * N + col) =
                make_float2(acc[mi][ni][0], acc[mi][ni][1]);
            *(float2*)(C + (size_t)(row0 + 8) * N + col) =
                make_float2(acc[mi][ni][2], acc[mi][ni][3]);
        }
    }
}

// ---------------- conversions ----------------
__global__ __launch_bounds__(256) void cvt_split_h(
    const float4* __restrict__ x, __half2* __restrict__ hi,
    __half2* __restrict__ lo, int n4)
{
    int i = blockIdx.x * 256 + threadIdx.x;
    if (i >= n4) return;
    float4 v = x[i];
    __half h0 = __float2half_rn(v.x);
    __half h1 = __float2half_rn(v.y);
    __half h2 = __float2half_rn(v.z);
    __half h3 = __float2half_rn(v.w);
    hi[2 * i]     = __halves2half2(h0, h1);
    hi[2 * i + 1] = __halves2half2(h2, h3);
    lo[2 * i]     = __halves2half2(
        __float2half_rn(v.x - __half2float(h0)),
        __float2half_rn(v.y - __half2float(h1)));
    lo[2 * i + 1] = __halves2half2(
        __float2half_rn(v.z - __half2float(h2)),
        __float2half_rn(v.w - __half2float(h3)));
}

__global__ __launch_bounds__(256) void cvt_wcat_h(
    const float* __restrict__ wbq, const float* __restrict__ wbk,
    const float* __restrict__ wbv, const float* __restrict__ waq,
    const float* __restrict__ wak, const float* __restrict__ wav,
    __half* __restrict__ w)
{
    int i = blockIdx.x * 256 + threadIdx.x;
    if (i >= NPROJ * HID) return;
    int row = i / HID, col = i - row * HID;
    float val = 0.f;
    if (row < 1536)      val = wbq[row * HID + col];
    else if (row < 2048) val = wbk[(row - 1536) * HID + col];
    else if (row < 2560) val = wbv[(row - 2048) * HID + col];
    else if (row < 2608) val = waq[(row - 2560) * HID + col];
    else if (row < 2616) val = wak[(row - 2608) * HID + col];
    else if (row < 2624) val = wav[(row - 2616) * HID + col];
    w[i] = __float2half_rn(val);
}

__global__ __launch_bounds__(256) void cvt_h(
    const float4* __restrict__ x, __half2* __restrict__ w, int n4)
{
    int i = blockIdx.x * 256 + threadIdx.x;
    if (i >= n4) return;
    float4 v = x[i];
    w[2 * i]     = __halves2half2(__float2half_rn(v.x), __float2half_rn(v.y));
    w[2 * i + 1] = __halves2half2(__float2half_rn(v.z), __float2half_rn(v.w));
}

// ---------------- fused RoPE + tensor-product + RMSNorm --------------------
__global__ __launch_bounds__(256) void qkv_kernel(
    const float* __restrict__ proj,
    const float* __restrict__ fcos, const float* __restrict__ fsin,
    const float* __restrict__ qnw, const float* __restrict__ knw,
    const int* __restrict__ idx,
    __half* __restrict__ qhi, __half* __restrict__ qlo,
    __half* __restrict__ kf, __half* __restrict__ vo)
{
    int s = blockIdx.x;
    int tid = threadIdx.x;
    int d = tid;
    int warp = tid >> 5, lane = tid & 31;
    const float* row = proj + (size_t)s * NPROJ;

    __shared__ float sA[64];
    __shared__ float red[8][8];
    __shared__ float srstd[8];
    __shared__ float skrstd[4];

    if (tid < 64) sA[tid] = row[2560 + tid];
    __syncthreads();

    float c  = fcos[s * (HD / 2) + (d >> 1)];
    float sn = fsin[s * (HD / 2) + (d >> 1)];
    float seff = (d & 1) ? sn : -sn;

    float bq[QR];
    #pragma unroll
    for (int r = 0; r < QR; r++) {
        float x  = row[r * HD + d];
        float xn = row[r * HD + (d ^ 1)];
        bq[r] = x * c + xn * seff;
    }
    float qraw[NH];
    #pragma unroll
    for (int h = 0; h < NH; h++) {
        float a = 0.f;
        #pragma unroll
        for (int r = 0; r < QR; r++) a += sA[h * QR + r] * bq[r];
        qraw[h] = a * (1.f / QR);
    }
    #pragma unroll
    for (int h = 0; h < NH; h++) {
        float ss = qraw[h] * qraw[h];
        #pragma unroll
        for (int o = 16; o > 0; o >>= 1) ss += __shfl_xor_sync(0xffffffffu, ss, o);
        if (lane == 0) red[warp][h] = ss;
    }
    __syncthreads();
    if (tid < NH) {
        float t = 0.f;
        #pragma unroll
        for (int w = 0; w < 8; w++) t += red[w][tid];
        srstd[tid] = rsqrtf(t * (1.f / HD) + EPS);
    }
    __syncthreads();
    float qw = (1.f + qnw[d]) * SCALING;
    #pragma unroll
    for (int h = 0; h < NH; h++) {
        float qv = qraw[h] * srstd[h] * qw;
        __half hh = __float2half_rn(qv);
        size_t off = ((size_t)s * NH + h) * HD + d;
        qhi[off] = hh;
        qlo[off] = __float2half_rn(qv - __half2float(hh));
    }

    float bk[KR];
    #pragma unroll
    for (int r = 0; r < KR; r++) {
        float x  = row[1536 + r * HD + d];
        float xn = row[1536 + r * HD + (d ^ 1)];
        bk[r] = x * c + xn * seff;
    }
    float kraw[KVH];
    #pragma unroll
    for (int kh = 0; kh < KVH; kh++)
        kraw[kh] = (sA[48 + kh * KR + 0] * bk[0] + sA[48 + kh * KR + 1] * bk[1]) * 0.5f;

    __syncthreads();
    #pragma unroll
    for (int kh = 0; kh < KVH; kh++) {
        float ss = kraw[kh] * kraw[kh];
        #pragma unroll
        for (int o = 16; o > 0; o >>= 1) ss += __shfl_xor_sync(0xffffffffu, ss, o);
        if (lane == 0) red[warp][kh] = ss;
    }
    __syncthreads();
    if (tid < KVH) {
        float t = 0.f;
        #pragma unroll
        for (int w = 0; w < 8; w++) t += red[w][tid];
        skrstd[tid] = rsqrtf(t * (1.f / HD) + EPS);
    }
    __syncthreads();

    int tpos = idx[s];
    float kw = 1.f + knw[d];
    #pragma unroll
    for (int kh = 0; kh < KVH; kh++)
        kf[((size_t)tpos * KVH + kh) * HD + d] =
            __float2half_rn(kraw[kh] * skrstd[kh] * kw);

    float bv0 = row[2048 + 0 * HD + d];
    float bv1 = row[2048 + 1 * HD + d];
    #pragma unroll
    for (int kh = 0; kh < KVH; kh++)
        vo[((size_t)tpos * KVH + kh) * HD + d] = __float2half_rn(
            (sA[56 + kh * VR + 0] * bv0 + sA[56 + kh * VR + 1] * bv1) * 0.5f);
}

// ---------------- flash attention: fp16x2 QK + fp16 PV, 64-row chunks ------
// smem bytes: K(fp16) 2x33792 | V(fp16) 3x33792 | P(fp16) 2x9216 | den 256
#define AQ 64
#define CHK 64
#define KROWB 528
#define KBUF 33792
#define VOFFB 67584
#define VROWB 528
#define VBUF 33792
#define POFFB 168960
#define PROWB 144
#define PBUF 9216
#define DENF_IDX 46848
#define ATTN_SMEM 187648

__global__ __launch_bounds__(256, 1)
void attn_mma2(const __half* __restrict__ qh_, const __half* __restrict__ ql_,
               const __half* __restrict__ kf_, const __half* __restrict__ v,
               const int* __restrict__ idx,
               __half* __restrict__ outh, __half* __restrict__ outl)
{
    extern __shared__ float smf[];
    __shared__ int spos[AQ];
    __shared__ int srange[2];

    const int s0 = blockIdx.x * AQ;
    const int h = blockIdx.y;
    const int kvh = h >> 1;
    const int tid = threadIdx.x;
    const int wid = tid >> 5;
    const int lane = tid & 31;

    if (tid < AQ) spos[tid] = idx[s0 + tid];
    __syncthreads();
    if (tid == 0) {
        int mn = spos[0], mx = spos[0];
        for (int i = 1; i < AQ; i++) { mn = min(mn, spos[i]); mx = max(mx, spos[i]); }
        srange[0] = max(0, mn - (WINDOW - 1));
        srange[1] = mx;
    }
    __syncthreads();
    const int kmin = srange[0];
    const int nch = (srange[1] - kmin) / CHK + 1;

    const uint32_t smb = smem_u32(smf);
    const __half* kbase = kf_ + (size_t)kvh * HD;
    const __half* vbase = v + (size_t)kvh * HD;

    // load chunk ci: 64 rows of K and 64 rows of V, 512B per row
    auto load_chunk = [&](int ci) {
        const int tr0 = kmin + ci * CHK;
        const uint32_t dk = smb + (ci & 1) * KBUF;
        const uint32_t dv = smb + VOFFB + (ci % 3) * VBUF;
        #pragma unroll
        for (int step = 0; step < 8; step++) {
            const int slot = tid + step * 256;
            const int rr = slot >> 5;
            const int cc = slot & 31;
            const int tt = tr0 + rr;
            const int nbytes = (tt < S_LEN) ? 16 : 0;
            const size_t goff = (size_t)tt * (KVH * HD) + cc * 8;
            const uint32_t soff = rr * KROWB + cc * 16;
            CP_ASYNC16Z(dv + soff, vbase + goff, nbytes);
            CP_ASYNC16Z(dk + soff, kbase + goff, nbytes);
        }
        asm volatile("cp.async.commit_group;");
    };

    load_chunk(0);

    if (wid < 4) {
        // ---------------- score role: QK chunk i (fp16x2) ----------------
        const int rw = wid * 16;
        const int r0 = s0 + rw + (lane >> 2);
        const __half* q0h = qh_ + ((size_t)r0 * NH + h) * HD;
        const __half* q1h = qh_ + ((size_t)(r0 + 8) * NH + h) * HD;
        const __half* q0l = ql_ + ((size_t)r0 * NH + h) * HD;
        const __half* q1l = ql_ + ((size_t)(r0 + 8) * NH + h) * HD;
        uint32_t qah[16][4], qal[16][4];
        #pragma unroll
        for (int ks = 0; ks < 16; ks++) {
            int c = ks * 16 + 2 * (lane & 3);
            qah[ks][0] = *(const uint32_t*)(q0h + c);
            qah[ks][1] = *(const uint32_t*)(q1h + c);
            qah[ks][2] = *(const uint32_t*)(q0h + c + 8);
            qah[ks][3] = *(const uint32_t*)(q1h + c + 8);
            qal[ks][0] = *(const uint32_t*)(q0l + c);
            qal[ks][1] = *(const uint32_t*)(q1l + c);
            qal[ks][2] = *(const uint32_t*)(q0l + c + 8);
            qal[ks][3] = *(const uint32_t*)(q1l + c + 8);
        }
        const int qp0 = spos[rw + (lane >> 2)];
        const int qp1 = spos[rw + 8 + (lane >> 2)];
        float den0 = 0.f, den1 = 0.f;

        for (int i = 0; i < nch; i++) {
            __syncthreads();                               // A
            if (i + 1 < nch) {
                load_chunk(i + 1);
                asm volatile("cp.async.wait_group 1;");
            } else {
                asm volatile("cp.async.wait_group 0;");
            }
            __syncthreads();                               // B

            const uint32_t skb = smb + (i & 1) * KBUF;
            float sacc[8][4];
            #pragma unroll
            for (int j = 0; j < 8; j++)
                #pragma unroll
                for (int e = 0; e < 4; e++) sacc[j][e] = 0.f;

            #pragma unroll
            for (int ksp = 0; ksp < 8; ksp++) {
                #pragma unroll
                for (int jg = 0; jg < 2; jg++) {
                    uint32_t kb[4][4];
                    #pragma unroll
                    for (int jj = 0; jj < 4; jj++) {
                        const int j = jg * 4 + jj;
                        const uint32_t arow = (j * 8 + (lane & 7)) * KROWB
                                            + ksp * 64 + (lane >> 3) * 16;
                        LDMX4(kb[jj][0], kb[jj][1], kb[jj][2], kb[jj][3], skb + arow);
                    }
                    #pragma unroll
                    for (int jj = 0; jj < 4; jj++) {
                        const int j = jg * 4 + jj;
                        uint32_t b0[2] = { kb[jj][0], kb[jj][1] };
                        uint32_t b1[2] = { kb[jj][2], kb[jj][3] };
                        MMAF16(sacc[j], qah[2 * ksp],     b0);
                        MMAF16(sacc[j], qah[2 * ksp + 1], b1);
                        MMAF16(sacc[j], qal[2 * ksp],     b0);
                        MMAF16(sacc[j], qal[2 * ksp + 1], b1);
                    }
                }
            }

            const int t0 = kmin + i * CHK;
            const uint32_t pbb = smb + POFFB + (i & 1) * PBUF;
            #pragma unroll
            for (int j = 0; j < 8; j++) {
                const int tk = t0 + j * 8 + (lane & 3) * 2;
                float p[4];
                #pragma unroll
                for (int e = 0; e < 4; e++) {
                    const float s = sacc[j][e];
                    const int qp = (e < 2) ? qp0 : qp1;
                    const int tt = tk + (e & 1);
                    const float x2 = (s * (1.f / SOFTCAP)) * (s * (1.f / SOFTCAP));
                    const float r = 1.f + x2 * (-0.333333333f
                                  + x2 * (0.133333333f + x2 * -0.053968254f));
                    const float pe = __expf(fmaf(s, r, -PSHIFT));
                    p[e] = ((unsigned)(qp - tt) < WINDOW) ? pe : 0.f;
                }
                __half2 hp0 = __floats2half2_rn(p[0], p[1]);
                __half2 hp1 = __floats2half2_rn(p[2], p[3]);
                float2 f0 = __half22float2(hp0);
                float2 f1 = __half22float2(hp1);
                den0 += f0.x + f0.y;
                den1 += f1.x + f1.y;
                const uint32_t a0 = pbb + (rw + (lane >> 2)) * PROWB
                                  + (j * 8 + (lane & 3) * 2) * 2;
                const uint32_t a1 = a0 + 8 * PROWB;
                asm volatile("st.shared.b32 [%0], %1;" :: "r"(a0), "r"(*(uint32_t*)&hp0));
                asm volatile("st.shared.b32 [%0], %1;" :: "r"(a1), "r"(*(uint32_t*)&hp1));
            }
        }
        __syncthreads();                                   // C
        den0 += __shfl_xor_sync(0xffffffffu, den0, 1);
        den0 += __shfl_xor_sync(0xffffffffu, den0, 2);
        den1 += __shfl_xor_sync(0xffffffffu, den1, 1);
        den1 += __shfl_xor_sync(0xffffffffu, den1, 2);
        if ((lane & 3) == 0) {
            smf[DENF_IDX + rw + (lane >> 2)] = den0;
            smf[DENF_IDX + rw + 8 + (lane >> 2)] = den1;
        }
        __syncthreads();                                   // D
    } else {
        // ---------------- PV role: chunk i-1 (fp16 HMMA) ----------------
        const int rw = (wid - 4) * 16;
        float oacc[32][4];
        #pragma unroll
        for (int n = 0; n < 32; n++)
            #pragma unroll
            for (int e = 0; e < 4; e++) oacc[n][e] = 0.f;

        auto pv_compute = [&](int ci) {
            const uint32_t svb = smb + VOFFB + (ci % 3) * VBUF;
            const uint32_t pbb = smb + POFFB + (ci & 1) * PBUF;
            uint32_t pa[4][4];
            #pragma unroll
            for (int kk = 0; kk < 4; kk++)
                LDMX4(pa[kk][0], pa[kk][1], pa[kk][2], pa[kk][3],
                      pbb + (rw + (lane & 15)) * PROWB + kk * 32 + (lane >> 4) * 16);
            const uint32_t vrow = ((lane >> 3) & 1) * 8 + (lane & 7);
            const uint32_t vcol = (lane >> 4) * 8;
            #pragma unroll
            for (int np = 0; np < 16; np++) {
                #pragma unroll
                for (int kk = 0; kk < 4; kk++) {
                    uint32_t vb[4];
                    LDMX4T(vb[0], vb[1], vb[2], vb[3],
                           svb + (kk * 16 + vrow) * VROWB + (np * 16 + vcol) * 2);
                    uint32_t b0[2] = { vb[0], vb[1] };
                    uint32_t b1[2] = { vb[2], vb[3] };
                    MMAF16(oacc[2 * np],     pa[kk], b0);
                    MMAF16(oacc[2 * np + 1], pa[kk], b1);
                }
            }
        };

        for (int i = 0; i < nch; i++) {
            __syncthreads();                               // A
            if (i + 1 < nch) {
                load_chunk(i + 1);
                asm volatile("cp.async.wait_group 1;");
            } else {
                asm volatile("cp.async.wait_group 0;");
            }
            __syncthreads();                               // B
            if (i > 0) pv_compute(i - 1);
        }
        __syncthreads();                                   // C
        pv_compute(nch - 1);
        __syncthreads();                                   // D
        const float inv0 = 1.f / smf[DENF_IDX + rw + (lane >> 2)];
        const float inv1 = 1.f / smf[DENF_IDX + rw + 8 + (lane >> 2)];
        const int grow0 = s0 + rw + (lane >> 2);
        __half* oh0 = outh + (size_t)grow0 * HID + h * HD;
        __half* oh1 = outh + (size_t)(grow0 + 8) * HID + h * HD;
        __half* ol0 = outl + (size_t)grow0 * HID + h * HD;
        __half* ol1 = outl + (size_t)(grow0 + 8) * HID + h * HD;
        #pragma unroll
        for (int n = 0; n < 32; n++) {
            const int col = n * 8 + (lane & 3) * 2;
            const float v00 = oacc[n][0] * inv0, v01 = oacc[n][1] * inv0;
            const float v10 = oacc[n][2] * inv1, v11 = oacc[n][3] * inv1;
            const __half h00 = __float2half_rn(v00), h01 = __float2half_rn(v01);
            const __half h10 = __float2half_rn(v10), h11 = __float2half_rn(v11);
            *(__half2*)(oh0 + col) = __halves2half2(h00, h01);
            *(__half2*)(oh1 + col) = __halves2half2(h10, h11);
            *(__half2*)(ol0 + col) = __halves2half2(
                __float2half_rn(v00 - __half2float(h00)),
                __float2half_rn(v01 - __half2float(h01)));
            *(__half2*)(ol1 + col) = __halves2half2(
                __float2half_rn(v10 - __half2float(h10)),
                __float2half_rn(v11 - __half2float(h11)));
        }
    }
}

// ---------------- launch ----------------------------------------------------
extern "C" void kernel_launch(void* const* d_in, const int* in_sizes, int n_in,
                              void* d_out, int out_size)
{
    const float* x   = (const float*)d_in[0];
    const float* fc  = (const float*)d_in[1];
    const float* fs  = (const float*)d_in[2];
    const float* WAq = (const float*)d_in[3];
    const float* WAk = (const float*)d_in[4];
    const float* WAv = (const float*)d_in[5];
    const float* WBq = (const float*)d_in[6];
    const float* WBk = (const float*)d_in[7];
    const float* WBv = (const float*)d_in[8];
    const float* Wo  = (const float*)d_in[9];
    const float* qnw = (const float*)d_in[10];
    const float* knw = (const float*)d_in[11];
    const int*   idx = (const int*)d_in[16];
    float* out = (float*)d_out;

    float* gproj;
    __half *gqh, *gql, *gkf, *gv, *xhi, *xlo, *wcat, *wo, *ah, *al;
    cudaGetSymbolAddress((void**)&gproj, g_proj);
    cudaGetSymbolAddress((void**)&gqh, g_qhi);
    cudaGetSymbolAddress((void**)&gql, g_qlo);
    cudaGetSymbolAddress((void**)&gkf, g_kf);
    cudaGetSymbolAddress((void**)&gv,  g_v);
    cudaGetSymbolAddress((void**)&xhi, g_xhi);
    cudaGetSymbolAddress((void**)&xlo, g_xlo);
    cudaGetSymbolAddress((void**)&wcat, g_wcat);
    cudaGetSymbolAddress((void**)&wo, g_wo);
    cudaGetSymbolAddress((void**)&ah, g_attnhi);
    cudaGetSymbolAddress((void**)&al, g_attnlo);

    cudaFuncSetAttribute(mma_gemm, cudaFuncAttributeMaxDynamicSharedMemorySize, GEMM_SMEM);
    cudaFuncSetAttribute(attn_mma2, cudaFuncAttributeMaxDynamicSharedMemorySize, ATTN_SMEM);

    cudaMemsetAsync(gkf, 0, (size_t)S_LEN * KVH * HD * sizeof(__half));
    cudaMemsetAsync(gv, 0, (size_t)S_LEN * KVH * HD * sizeof(__half));

    {
        int n4 = S_LEN * HID / 4;
        cvt_split_h<<<(n4 + 255) / 256, 256>>>((const float4*)x,
            (__half2*)xhi, (__half2*)xlo, n4);
    }
    cvt_wcat_h<<<(NPROJ * HID + 255) / 256, 256>>>(WBq, WBk, WBv, WAq, WAk, WAv, wcat);
    {
        int n4 = HID * HID / 4;
        cvt_h<<<(n4 + 255) / 256, 256>>>((const float4*)Wo, (__half2*)wo, n4);
    }

    mma_gemm<<<dim3(NPROJ / 128, 32), 256, GEMM_SMEM>>>(xhi, xlo, wcat,
                                                        gproj, S_LEN, NPROJ, HID);

    qkv_kernel<<<S_LEN, 256>>>(gproj, fc, fs, qnw, knw, idx,
                               gqh, gql, gkf, gv);

    attn_mma2<<<dim3(S_LEN / AQ, NH), 256, ATTN_SMEM>>>(gqh, gql, gkf, gv, idx, ah, al);

    mma_gemm<<<dim3(16, 32), 256, GEMM_SMEM>>>(ah, al, wo, out, S_LEN, HID, HID);
}

// round 16
// speedup vs baseline: 7.3533x; 1.0011x over previous
#include <cuda_runtime.h>
#include <cuda_bf16.h>
#include <cuda_fp16.h>
#include <math.h>
#include <stdint.h>

#define S_LEN 4096
#define HID 2048
#define NH 8
#define KVH 4
#define HD 256
#define QR 6
#define KR 2
#define VR 2
#define WINDOW 1024
#define SOFTCAP 50.0f
#define SCALING 0.0625f
#define EPS 1e-6f
#define NPROJ 2688
#define PSHIFT 8.0f

// ---------------- scratch ----------------
__device__ float g_proj[S_LEN * NPROJ];
__device__ __half g_qhi[S_LEN * NH * HD];
__device__ __half g_qlo[S_LEN * NH * HD];
__device__ __half g_kf[S_LEN * KVH * HD];
__device__ __half g_v[S_LEN * KVH * HD];

__device__ __half g_xhi[S_LEN * HID];
__device__ __half g_xlo[S_LEN * HID];
__device__ __half g_wcat[NPROJ * HID];
__device__ __half g_wo[HID * HID];
__device__ __half g_attnhi[S_LEN * HID];
__device__ __half g_attnlo[S_LEN * HID];

// ---------------- helpers ----------------
__device__ __forceinline__ uint32_t smem_u32(const void* p) {
    uint32_t a;
    asm("{ .reg .u64 t; cvta.to.shared.u64 t, %1; cvt.u32.u64 %0, t; }" : "=r"(a) : "l"(p));
    return a;
}

#define LDMX4(r0, r1, r2, r3, addr)                                              \
    asm volatile("ldmatrix.sync.aligned.m8n8.x4.shared.b16 {%0,%1,%2,%3}, [%4];" \
                 : "=r"(r0), "=r"(r1), "=r"(r2), "=r"(r3) : "r"(addr))
#define LDMX4T(r0, r1, r2, r3, addr)                                             \
    asm volatile("ldmatrix.sync.aligned.m8n8.x4.trans.shared.b16 {%0,%1,%2,%3}, [%4];" \
                 : "=r"(r0), "=r"(r1), "=r"(r2), "=r"(r3) : "r"(addr))
#define MMAF16(d, a, b)                                                          \
    asm volatile("mma.sync.aligned.m16n8k16.row.col.f32.f16.f16.f32 "            \
                 "{%0,%1,%2,%3}, {%4,%5,%6,%7}, {%8,%9}, {%0,%1,%2,%3};"         \
                 : "+f"((d)[0]), "+f"((d)[1]), "+f"((d)[2]), "+f"((d)[3])        \
                 : "r"((a)[0]), "r"((a)[1]), "r"((a)[2]), "r"((a)[3]),           \
                   "r"((b)[0]), "r"((b)[1]))
#define CP_ASYNC16(dst, src)                                                     \
    asm volatile("cp.async.cg.shared.global [%0], [%1], 16;" :: "r"(dst), "l"(src))
#define CP_ASYNC16Z(dst, src, sz)                                                \
    asm volatile("cp.async.cg.shared.global [%0], [%1], 16, %2;"                 \
                 :: "r"(dst), "l"(src), "r"(sz))

// ---------------- fp16x2 GEMM via mma.sync: C = (Ah+Al) @ B^T ---------------
// mainloop interleaved: all hi-MMAs (independent accs) then all lo-MMAs.
#define CK 64
#define ROW_B 144
#define MAT_B (128 * ROW_B)
#define BUF_B (3 * MAT_B)
#define GEMM_SMEM (2 * BUF_B)

__global__ __launch_bounds__(256, 2)
void mma_gemm(const __half* __restrict__ Ah, const __half* __restrict__ Al,
              const __half* __restrict__ B,
              float* __restrict__ C, int M, int N, int K)
{
    extern __shared__ char sm[];
    const uint32_t smb = smem_u32(sm);

    const int tid = threadIdx.x;
    const int wid = tid >> 5;
    const int lane = tid & 31;
    const int wm = wid & 3;
    const int wn = wid >> 2;
    const int bm = blockIdx.y;
    const int bn = blockIdx.x;

    const __half* baseAh = Ah + (size_t)(bm * 128) * K;
    const __half* baseAl = Al + (size_t)(bm * 128) * K;
    const __half* baseB  = B  + (size_t)(bn * 128) * K;

    float acc[2][8][4];
    #pragma unroll
    for (int mi = 0; mi < 2; mi++)
        #pragma unroll
        for (int ni = 0; ni < 8; ni++)
            #pragma unroll
            for (int j = 0; j < 4; j++) acc[mi][ni][j] = 0.f;

    auto load_chunk = [&](int kb, int b) {
        uint32_t bufb = smb + b * BUF_B;
        #pragma unroll
        for (int it = 0; it < 12; it++) {
            const __half* base = (it < 4) ? baseAh : (it < 8) ? baseAl : baseB;
            int idx = ((it & 3) << 8) + tid;
            int r = idx >> 3;
            int c = idx & 7;
            const void* src = base + (size_t)r * K + kb * CK + c * 8;
            uint32_t dst = bufb + (it >> 2) * MAT_B + r * ROW_B + c * 16;
            CP_ASYNC16(dst, src);
        }
        asm volatile("cp.async.commit_group;");
    };

    const int NC = K / CK;
    load_chunk(0, 0);

    for (int i = 0; i < NC; i++) {
        asm volatile("cp.async.wait_group 0;");
        __syncthreads();
        if (i + 1 < NC) load_chunk(i + 1, (i + 1) & 1);

        uint32_t sbase = smb + (i & 1) * BUF_B;
        uint32_t aoff = sbase + (wm * 32 + (lane & 15)) * ROW_B + (lane >> 4) * 16;
        uint32_t bbase = sbase + 2 * MAT_B;

        #pragma unroll
        for (int kk = 0; kk < 4; kk++) {
            uint32_t a_h[2][4], a_l[2][4];
            #pragma unroll
            for (int mi = 0; mi < 2; mi++) {
                LDMX4(a_h[mi][0], a_h[mi][1], a_h[mi][2], a_h[mi][3],
                      aoff + mi * 16 * ROW_B + kk * 32);
                LDMX4(a_l[mi][0], a_l[mi][1], a_l[mi][2], a_l[mi][3],
                      aoff + MAT_B + mi * 16 * ROW_B + kk * 32);
            }
            uint32_t bf[4][4];
            #pragma unroll
            for (int nip = 0; nip < 4; nip++) {
                LDMX4(bf[nip][0], bf[nip][1], bf[nip][2], bf[nip][3],
                      bbase + (wn * 64 + nip * 16 + (lane & 15)) * ROW_B
                            + (lane >> 4) * 16 + kk * 32);
            }
            // pass 1: hi-part MMAs — 16 independent accumulators back-to-back
            #pragma unroll
            for (int nip = 0; nip < 4; nip++) {
                #pragma unroll
                for (int half = 0; half < 2; half++) {
                    int ni = nip * 2 + half;
                    uint32_t bb[2] = { bf[nip][half], bf[nip][half + 2] };
                    #pragma unroll
                    for (int mi = 0; mi < 2; mi++)
                        MMAF16(acc[mi][ni], a_h[mi], bb);
                }
            }
            // pass 2: lo-part MMAs — dependent on pass 1 but 16-wide window
            #pragma unroll
            for (int nip = 0; nip < 4; nip++) {
                #pragma unroll
                for (int half = 0; half < 2; half++) {
                    int ni = nip * 2 + half;
                    uint32_t bb[2] = { bf[nip][half], bf[nip][half + 2] };
                    #pragma unroll
                    for (int mi = 0; mi < 2; mi++)
                        MMAF16(acc[mi][ni], a_l[mi], bb);
                }
            }
        }
    }

    #pragma unroll
    for (int mi = 0; mi < 2; mi++) {
        int row0 = bm * 128 + wm * 32 + mi * 16 + (lane >> 2);
        #pragma unroll
        for (int ni = 0; ni < 8; ni++) {
            int col = bn * 128 + wn * 64 + ni * 8 + (lane & 3) * 2;
            *(float2*)(C + (size_t)row0 * N + col) =
                make_float2(acc[mi][ni][0], acc[mi][ni][1]);
            *(float2*)(C + (size_t)(row0 + 8) * N + col) =
                make_float2(acc[mi][ni][2], acc[mi][ni][3]);
        }
    }
}

// ---------------- conversions ----------------
__global__ __launch_bounds__(256) void cvt_split_h(
    const float4* __restrict__ x, __half2* __restrict__ hi,
    __half2* __restrict__ lo, int n4)
{
    int i = blockIdx.x * 256 + threadIdx.x;
    if (i >= n4) return;
    float4 v = x[i];
    __half h0 = __float2half_rn(v.x);
    __half h1 = __float2half_rn(v.y);
    __half h2 = __float2half_rn(v.z);
    __half h3 = __float2half_rn(v.w);
    hi[2 * i]     = __halves2half2(h0, h1);
    hi[2 * i + 1] = __halves2half2(h2, h3);
    lo[2 * i]     = __halves2half2(
        __float2half_rn(v.x - __half2float(h0)),
        __float2half_rn(v.y - __half2float(h1)));
    lo[2 * i + 1] = __halves2half2(
        __float2half_rn(v.z - __half2float(h2)),
        __float2half_rn(v.w - __half2float(h3)));
}

__global__ __launch_bounds__(256) void cvt_wcat_h(
    const float* __restrict__ wbq, const float* __restrict__ wbk,
    const float* __restrict__ wbv, const float* __restrict__ waq,
    const float* __restrict__ wak, const float* __restrict__ wav,
    __half* __restrict__ w)
{
    int i = blockIdx.x * 256 + threadIdx.x;
    if (i >= NPROJ * HID) return;
    int row = i / HID, col = i - row * HID;
    float val = 0.f;
    if (row < 1536)      val = wbq[row * HID + col];
    else if (row < 2048) val = wbk[(row - 1536) * HID + col];
    else if (row < 2560) val = wbv[(row - 2048) * HID + col];
    else if (row < 2608) val = waq[(row - 2560) * HID + col];
    else if (row < 2616) val = wak[(row - 2608) * HID + col];
    else if (row < 2624) val = wav[(row - 2616) * HID + col];
    w[i] = __float2half_rn(val);
}

__global__ __launch_bounds__(256) void cvt_h(
    const float4* __restrict__ x, __half2* __restrict__ w, int n4)
{
    int i = blockIdx.x * 256 + threadIdx.x;
    if (i >= n4) return;
    float4 v = x[i];
    w[2 * i]     = __halves2half2(__float2half_rn(v.x), __float2half_rn(v.y));
    w[2 * i + 1] = __halves2half2(__float2half_rn(v.z), __float2half_rn(v.w));
}

// ---------------- fused RoPE + tensor-product + RMSNorm --------------------
__global__ __launch_bounds__(256) void qkv_kernel(
    const float* __restrict__ proj,
    const float* __restrict__ fcos, const float* __restrict__ fsin,
    const float* __restrict__ qnw, const float* __restrict__ knw,
    const int* __restrict__ idx,
    __half* __restrict__ qhi, __half* __restrict__ qlo,
    __half* __restrict__ kf, __half* __restrict__ vo)
{
    int s = blockIdx.x;
    int tid = threadIdx.x;
    int d = tid;
    int warp = tid >> 5, lane = tid & 31;
    const float* row = proj + (size_t)s * NPROJ;

    __shared__ float sA[64];
    __shared__ float red[8][8];
    __shared__ float srstd[8];
    __shared__ float skrstd[4];

    if (tid < 64) sA[tid] = row[2560 + tid];
    __syncthreads();

    float c  = fcos[s * (HD / 2) + (d >> 1)];
    float sn = fsin[s * (HD / 2) + (d >> 1)];
    float seff = (d & 1) ? sn : -sn;

    float bq[QR];
    #pragma unroll
    for (int r = 0; r < QR; r++) {
        float x  = row[r * HD + d];
        float xn = row[r * HD + (d ^ 1)];
        bq[r] = x * c + xn * seff;
    }
    float qraw[NH];
    #pragma unroll
    for (int h = 0; h < NH; h++) {
        float a = 0.f;
        #pragma unroll
        for (int r = 0; r < QR; r++) a += sA[h * QR + r] * bq[r];
        qraw[h] = a * (1.f / QR);
    }
    #pragma unroll
    for (int h = 0; h < NH; h++) {
        float ss = qraw[h] * qraw[h];
        #pragma unroll
        for (int o = 16; o > 0; o >>= 1) ss += __shfl_xor_sync(0xffffffffu, ss, o);
        if (lane == 0) red[warp][h] = ss;
    }
    __syncthreads();
    if (tid < NH) {
        float t = 0.f;
        #pragma unroll
        for (int w = 0; w < 8; w++) t += red[w][tid];
        srstd[tid] = rsqrtf(t * (1.f / HD) + EPS);
    }
    __syncthreads();
    float qw = (1.f + qnw[d]) * SCALING;
    #pragma unroll
    for (int h = 0; h < NH; h++) {
        float qv = qraw[h] * srstd[h] * qw;
        __half hh = __float2half_rn(qv);
        size_t off = ((size_t)s * NH + h) * HD + d;
        qhi[off] = hh;
        qlo[off] = __float2half_rn(qv - __half2float(hh));
    }

    float bk[KR];
    #pragma unroll
    for (int r = 0; r < KR; r++) {
        float x  = row[1536 + r * HD + d];
        float xn = row[1536 + r * HD + (d ^ 1)];
        bk[r] = x * c + xn * seff;
    }
    float kraw[KVH];
    #pragma unroll
    for (int kh = 0; kh < KVH; kh++)
        kraw[kh] = (sA[48 + kh * KR + 0] * bk[0] + sA[48 + kh * KR + 1] * bk[1]) * 0.5f;

    __syncthreads();
    #pragma unroll
    for (int kh = 0; kh < KVH; kh++) {
        float ss = kraw[kh] * kraw[kh];
        #pragma unroll
        for (int o = 16; o > 0; o >>= 1) ss += __shfl_xor_sync(0xffffffffu, ss, o);
        if (lane == 0) red[warp][kh] = ss;
    }
    __syncthreads();
    if (tid < KVH) {
        float t = 0.f;
        #pragma unroll
        for (int w = 0; w < 8; w++) t += red[w][tid];
        skrstd[tid] = rsqrtf(t * (1.f / HD) + EPS);
    }
    __syncthreads();

    int tpos = idx[s];
    float kw = 1.f + knw[d];
    #pragma unroll
    for (int kh = 0; kh < KVH; kh++)
        kf[((size_t)tpos * KVH + kh) * HD + d] =
            __float2half_rn(kraw[kh] * skrstd[kh] * kw);

    float bv0 = row[2048 + 0 * HD + d];
    float bv1 = row[2048 + 1 * HD + d];
    #pragma unroll
    for (int kh = 0; kh < KVH; kh++)
        vo[((size_t)tpos * KVH + kh) * HD + d] = __float2half_rn(
            (sA[56 + kh * VR + 0] * bv0 + sA[56 + kh * VR + 1] * bv1) * 0.5f);
}

// ---------------- flash attention: fp16x2 QK + fp16 PV, 64-row chunks ------
// smem bytes: K(fp16) 2x33792 | V(fp16) 3x33792 | P(fp16) 2x9216 | den 256
#define AQ 64
#define CHK 64
#define KROWB 528
#define KBUF 33792
#define VOFFB 67584
#define VROWB 528
#define VBUF 33792
#define POFFB 168960
#define PROWB 144
#define PBUF 9216
#define DENF_IDX 46848
#define ATTN_SMEM 187648

__global__ __launch_bounds__(256, 1)
void attn_mma2(const __half* __restrict__ qh_, const __half* __restrict__ ql_,
               const __half* __restrict__ kf_, const __half* __restrict__ v,
               const int* __restrict__ idx,
               __half* __restrict__ outh, __half* __restrict__ outl)
{
    extern __shared__ float smf[];
    __shared__ int spos[AQ];
    __shared__ int srange[2];

    const int s0 = blockIdx.x * AQ;
    const int h = blockIdx.y;
    const int kvh = h >> 1;
    const int tid = threadIdx.x;
    const int wid = tid >> 5;
    const int lane = tid & 31;

    if (tid < AQ) spos[tid] = idx[s0 + tid];
    __syncthreads();
    if (tid == 0) {
        int mn = spos[0], mx = spos[0];
        for (int i = 1; i < AQ; i++) { mn = min(mn, spos[i]); mx = max(mx, spos[i]); }
        srange[0] = max(0, mn - (WINDOW - 1));
        srange[1] = mx;
    }
    __syncthreads();
    const int kmin = srange[0];
    const int nch = (srange[1] - kmin) / CHK + 1;

    const uint32_t smb = smem_u32(smf);
    const __half* kbase = kf_ + (size_t)kvh * HD;
    const __half* vbase = v + (size_t)kvh * HD;

    // load chunk ci: 64 rows of K and 64 rows of V, 512B per row
    auto load_chunk = [&](int ci) {
        const int tr0 = kmin + ci * CHK;
        const uint32_t dk = smb + (ci & 1) * KBUF;
        const uint32_t dv = smb + VOFFB + (ci % 3) * VBUF;
        #pragma unroll
        for (int step = 0; step < 8; step++) {
            const int slot = tid + step * 256;
            const int rr = slot >> 5;
            const int cc = slot & 31;
            const int tt = tr0 + rr;
            const int nbytes = (tt < S_LEN) ? 16 : 0;
            const size_t goff = (size_t)tt * (KVH * HD) + cc * 8;
            const uint32_t soff = rr * KROWB + cc * 16;
            CP_ASYNC16Z(dv + soff, vbase + goff, nbytes);
            CP_ASYNC16Z(dk + soff, kbase + goff, nbytes);
        }
        asm volatile("cp.async.commit_group;");
    };

    load_chunk(0);

    if (wid < 4) {
        // ---------------- score role: QK chunk i (fp16x2) ----------------
        const int rw = wid * 16;
        const int r0 = s0 + rw + (lane >> 2);
        const __half* q0h = qh_ + ((size_t)r0 * NH + h) * HD;
        const __half* q1h = qh_ + ((size_t)(r0 + 8) * NH + h) * HD;
        const __half* q0l = ql_ + ((size_t)r0 * NH + h) * HD;
        const __half* q1l = ql_ + ((size_t)(r0 + 8) * NH + h) * HD;
        uint32_t qah[16][4], qal[16][4];
        #pragma unroll
        for (int ks = 0; ks < 16; ks++) {
            int c = ks * 16 + 2 * (lane & 3);
            qah[ks][0] = *(const uint32_t*)(q0h + c);
            qah[ks][1] = *(const uint32_t*)(q1h + c);
            qah[ks][2] = *(const uint32_t*)(q0h + c + 8);
            qah[ks][3] = *(const uint32_t*)(q1h + c + 8);
            qal[ks][0] = *(const uint32_t*)(q0l + c);
            qal[ks][1] = *(const uint32_t*)(q1l + c);
            qal[ks][2] = *(const uint32_t*)(q0l + c + 8);
            qal[ks][3] = *(const uint32_t*)(q1l + c + 8);
        }
        const int qp0 = spos[rw + (lane >> 2)];
        const int qp1 = spos[rw + 8 + (lane >> 2)];
        float den0 = 0.f, den1 = 0.f;

        for (int i = 0; i < nch; i++) {
            __syncthreads();                               // A
            if (i + 1 < nch) {
                load_chunk(i + 1);
                asm volatile("cp.async.wait_group 1;");
            } else {
                asm volatile("cp.async.wait_group 0;");
            }
            __syncthreads();                               // B

            const uint32_t skb = smb + (i & 1) * KBUF;
            float sacc[8][4];
            #pragma unroll
            for (int j = 0; j < 8; j++)
                #pragma unroll
                for (int e = 0; e < 4; e++) sacc[j][e] = 0.f;

            #pragma unroll
            for (int ksp = 0; ksp < 8; ksp++) {
                #pragma unroll
                for (int jg = 0; jg < 2; jg++) {
                    uint32_t kb[4][4];
                    #pragma unroll
                    for (int jj = 0; jj < 4; jj++) {
                        const int j = jg * 4 + jj;
                        const uint32_t arow = (j * 8 + (lane & 7)) * KROWB
                                            + ksp * 64 + (lane >> 3) * 16;
                        LDMX4(kb[jj][0], kb[jj][1], kb[jj][2], kb[jj][3], skb + arow);
                    }
                    #pragma unroll
                    for (int jj = 0; jj < 4; jj++) {
                        const int j = jg * 4 + jj;
                        uint32_t b0[2] = { kb[jj][0], kb[jj][1] };
                        uint32_t b1[2] = { kb[jj][2], kb[jj][3] };
                        MMAF16(sacc[j], qah[2 * ksp],     b0);
                        MMAF16(sacc[j], qah[2 * ksp + 1], b1);
                        MMAF16(sacc[j], qal[2 * ksp],     b0);
                        MMAF16(sacc[j], qal[2 * ksp + 1], b1);
                    }
                }
            }

            const int t0 = kmin + i * CHK;
            const uint32_t pbb = smb + POFFB + (i & 1) * PBUF;
            #pragma unroll
            for (int j = 0; j < 8; j++) {
                const int tk = t0 + j * 8 + (lane & 3) * 2;
                float p[4];
                #pragma unroll
                for (int e = 0; e < 4; e++) {
                    const float s = sacc[j][e];
                    const int qp = (e < 2) ? qp0 : qp1;
                    const int tt = tk + (e & 1);
                    const float x2 = (s * (1.f / SOFTCAP)) * (s * (1.f / SOFTCAP));
                    const float r = 1.f + x2 * (-0.333333333f
                                  + x2 * (0.133333333f + x2 * -0.053968254f));
                    const float pe = __expf(fmaf(s, r, -PSHIFT));
                    p[e] = ((unsigned)(qp - tt) < WINDOW) ? pe : 0.f;
                }
                __half2 hp0 = __floats2half2_rn(p[0], p[1]);
                __half2 hp1 = __floats2half2_rn(p[2], p[3]);
                float2 f0 = __half22float2(hp0);
                float2 f1 = __half22float2(hp1);
                den0 += f0.x + f0.y;
                den1 += f1.x + f1.y;
                const uint32_t a0 = pbb + (rw + (lane >> 2)) * PROWB
                                  + (j * 8 + (lane & 3) * 2) * 2;
                const uint32_t a1 = a0 + 8 * PROWB;
                asm volatile("st.shared.b32 [%0], %1;" :: "r"(a0), "r"(*(uint32_t*)&hp0));
                asm volatile("st.shared.b32 [%0], %1;" :: "r"(a1), "r"(*(uint32_t*)&hp1));
            }
        }
        __syncthreads();                                   // C
        den0 += __shfl_xor_sync(0xffffffffu, den0, 1);
        den0 += __shfl_xor_sync(0xffffffffu, den0, 2);
        den1 += __shfl_xor_sync(0xffffffffu, den1, 1);
        den1 += __shfl_xor_sync(0xffffffffu, den1, 2);
        if ((lane & 3) == 0) {
            smf[DENF_IDX + rw + (lane >> 2)] = den0;
            smf[DENF_IDX + rw + 8 + (lane >> 2)] = den1;
        }
        __syncthreads();                                   // D
    } else {
        // ---------------- PV role: chunk i-1 (fp16 HMMA) ----------------
        const int rw = (wid - 4) * 16;
        float oacc[32][4];
        #pragma unroll
        for (int n = 0; n < 32; n++)
            #pragma unroll
            for (int e = 0; e < 4; e++) oacc[n][e] = 0.f;

        auto pv_compute = [&](int ci) {
            const uint32_t svb = smb + VOFFB + (ci % 3) * VBUF;
            const uint32_t pbb = smb + POFFB + (ci & 1) * PBUF;
            uint32_t pa[4][4];
            #pragma unroll
            for (int kk = 0; kk < 4; kk++)
                LDMX4(pa[kk][0], pa[kk][1], pa[kk][2], pa[kk][3],
                      pbb + (rw + (lane & 15)) * PROWB + kk * 32 + (lane >> 4) * 16);
            const uint32_t vrow = ((lane >> 3) & 1) * 8 + (lane & 7);
            const uint32_t vcol = (lane >> 4) * 8;
            #pragma unroll
            for (int np = 0; np < 16; np++) {
                #pragma unroll
                for (int kk = 0; kk < 4; kk++) {
                    uint32_t vb[4];
                    LDMX4T(vb[0], vb[1], vb[2], vb[3],
                           svb + (kk * 16 + vrow) * VROWB + (np * 16 + vcol) * 2);
                    uint32_t b0[2] = { vb[0], vb[1] };
                    uint32_t b1[2] = { vb[2], vb[3] };
                    MMAF16(oacc[2 * np],     pa[kk], b0);
                    MMAF16(oacc[2 * np + 1], pa[kk], b1);
                }
            }
        };

        for (int i = 0; i < nch; i++) {
            __syncthreads();                               // A
            if (i + 1 < nch) {
                load_chunk(i + 1);
                asm volatile("cp.async.wait_group 1;");
            } else {
                asm volatile("cp.async.wait_group 0;");
            }
            __syncthreads();                               // B
            if (i > 0) pv_compute(i - 1);
        }
        __syncthreads();                                   // C
        pv_compute(nch - 1);
        __syncthreads();                                   // D
        const float inv0 = 1.f / smf[DENF_IDX + rw + (lane >> 2)];
        const float inv1 = 1.f / smf[DENF_IDX + rw + 8 + (lane >> 2)];
        const int grow0 = s0 + rw + (lane >> 2);
        __half* oh0 = outh + (size_t)grow0 * HID + h * HD;
        __half* oh1 = outh + (size_t)(grow0 + 8) * HID + h * HD;
        __half* ol0 = outl + (size_t)grow0 * HID + h * HD;
        __half* ol1 = outl + (size_t)(grow0 + 8) * HID + h * HD;
        #pragma unroll
        for (int n = 0; n < 32; n++) {
            const int col = n * 8 + (lane & 3) * 2;
            const float v00 = oacc[n][0] * inv0, v01 = oacc[n][1] * inv0;
            const float v10 = oacc[n][2] * inv1, v11 = oacc[n][3] * inv1;
            const __half h00 = __float2half_rn(v00), h01 = __float2half_rn(v01);
            const __half h10 = __float2half_rn(v10), h11 = __float2half_rn(v11);
            *(__half2*)(oh0 + col) = __halves2half2(h00, h01);
            *(__half2*)(oh1 + col) = __halves2half2(h10, h11);
            *(__half2*)(ol0 + col) = __halves2half2(
                __float2half_rn(v00 - __half2float(h00)),
                __float2half_rn(v01 - __half2float(h01)));
            *(__half2*)(ol1 + col) = __halves2half2(
                __float2half_rn(v10 - __half2float(h10)),
                __float2half_rn(v11 - __half2float(h11)));
        }
    }
}

// ---------------- launch ----------------------------------------------------
extern "C" void kernel_launch(void* const* d_in, const int* in_sizes, int n_in,
                              void* d_out, int out_size)
{
    const float* x   = (const float*)d_in[0];
    const float* fc  = (const float*)d_in[1];
    const float* fs  = (const float*)d_in[2];
    const float* WAq = (const float*)d_in[3];
    const float* WAk = (const float*)d_in[4];
    const float* WAv = (const float*)d_in[5];
    const float* WBq = (const float*)d_in[6];
    const float* WBk = (const float*)d_in[7];
    const float* WBv = (const float*)d_in[8];
    const float* Wo  = (const float*)d_in[9];
    const float* qnw = (const float*)d_in[10];
    const float* knw = (const float*)d_in[11];
    const int*   idx = (const int*)d_in[16];
    float* out = (float*)d_out;

    float* gproj;
    __half *gqh, *gql, *gkf, *gv, *xhi, *xlo, *wcat, *wo, *ah, *al;
    cudaGetSymbolAddress((void**)&gproj, g_proj);
    cudaGetSymbolAddress((void**)&gqh, g_qhi);
    cudaGetSymbolAddress((void**)&gql, g_qlo);
    cudaGetSymbolAddress((void**)&gkf, g_kf);
    cudaGetSymbolAddress((void**)&gv,  g_v);
    cudaGetSymbolAddress((void**)&xhi, g_xhi);
    cudaGetSymbolAddress((void**)&xlo, g_xlo);
    cudaGetSymbolAddress((void**)&wcat, g_wcat);
    cudaGetSymbolAddress((void**)&wo, g_wo);
    cudaGetSymbolAddress((void**)&ah, g_attnhi);
    cudaGetSymbolAddress((void**)&al, g_attnlo);

    cudaFuncSetAttribute(mma_gemm, cudaFuncAttributeMaxDynamicSharedMemorySize, GEMM_SMEM);
    cudaFuncSetAttribute(attn_mma2, cudaFuncAttributeMaxDynamicSharedMemorySize, ATTN_SMEM);

    cudaMemsetAsync(gkf, 0, (size_t)S_LEN * KVH * HD * sizeof(__half));
    cudaMemsetAsync(gv, 0, (size_t)S_LEN * KVH * HD * sizeof(__half));

    {
        int n4 = S_LEN * HID / 4;
        cvt_split_h<<<(n4 + 255) / 256, 256>>>((const float4*)x,
            (__half2*)xhi, (__half2*)xlo, n4);
    }
    cvt_wcat_h<<<(NPROJ * HID + 255) / 256, 256>>>(WBq, WBk, WBv, WAq, WAk, WAv, wcat);
    {
        int n4 = HID * HID / 4;
        cvt_h<<<(n4 + 255) / 256, 256>>>((const float4*)Wo, (__half2*)wo, n4);
    }

    mma_gemm<<<dim3(NPROJ / 128, 32), 256, GEMM_SMEM>>>(xhi, xlo, wcat,
                                                        gproj, S_LEN, NPROJ, HID);

    qkv_kernel<<<S_LEN, 256>>>(gproj, fc, fs, qnw, knw, idx,
                               gqh, gql, gkf, gv);

    attn_mma2<<<dim3(S_LEN / AQ, NH), 256, ATTN_SMEM>>>(gqh, gql, gkf, gv, idx, ah, al);

    mma_gemm<<<dim3(16, 32), 256, GEMM_SMEM>>>(ah, al, wo, out, S_LEN, HID, HID);
}